// round 5
// baseline (speedup 1.0000x reference)
#include <cuda_runtime.h>

#define CDIV(a,b) (((a)+(b)-1)/(b))

// ---------------- problem constants (fixed by setup_inputs) ----------------
#define KDIM   256
#define NT1C   25000
#define NT2C   5000
#define N0C    100000
#define E1CAP  400000
#define E2CAP  100000
#define NEG_SLOPE 0.2f

// ---------------- static scratch (no allocations allowed) ----------------
__device__ float g_xs1[(size_t)N0C * 256];   // x @ W1_src         (102.4 MB)
__device__ float g_h  [(size_t)NT1C * 256];  // skip1 buf -> h     (25.6 MB)
__device__ float g_xs2[(size_t)NT1C * 64];   // h @ W2_src
__device__ float g_o  [(size_t)NT2C * 64];   // skip2 buf -> o
__device__ float g_as1[(size_t)N0C * 4];
__device__ float g_ad1[NT1C * 4];
__device__ float g_as2[NT1C];
__device__ float g_ad2[NT2C];
__device__ float g_vS1[4 * 256];
__device__ float g_vD1[4 * 256];
__device__ float g_vS2[256];
__device__ float g_vD2[256];
__device__ float g_comb1[256];
__device__ float g_comb2[64];
__device__ int g_cnt1[NT1C];
__device__ int g_off1[NT1C + 1];
__device__ int g_cur1[NT1C];
__device__ int g_eid1[E1CAP];
__device__ int g_cnt2[NT2C];
__device__ int g_off2[NT2C + 1];
__device__ int g_cur2[NT2C];
__device__ int g_eid2[E2CAP];

// ---------------- packed f32x2 helpers (FFMA2 — PTX-only, 2x fp32 rate) ------
__device__ __forceinline__ unsigned long long pk2(float x, float y) {
    unsigned long long r;
    asm("mov.b64 %0, {%1,%2};" : "=l"(r) : "f"(x), "f"(y));
    return r;
}
__device__ __forceinline__ unsigned long long dup2(float x) {
    unsigned long long r;
    asm("mov.b64 %0, {%1,%1};" : "=l"(r) : "f"(x));
    return r;
}
__device__ __forceinline__ void ffma2(unsigned long long& d,
                                      unsigned long long a, unsigned long long b) {
    asm("fma.rn.f32x2 %0, %1, %2, %0;" : "+l"(d) : "l"(a), "l"(b));
}
__device__ __forceinline__ void unpk2(unsigned long long v, float& lo, float& hi) {
    asm("mov.b64 {%0,%1}, %2;" : "=f"(lo), "=f"(hi) : "l"(v));
}

// ---------------- fold: attention projection vectors + combined biases ----
__global__ void fold_kernel(const float* __restrict__ W1s, const float* __restrict__ W1d,
                            const float* __restrict__ a1s, const float* __restrict__ a1d,
                            const float* __restrict__ b1,  const float* __restrict__ s1b,
                            const float* __restrict__ W2s, const float* __restrict__ W2d,
                            const float* __restrict__ a2s, const float* __restrict__ a2d,
                            const float* __restrict__ b2,  const float* __restrict__ s2b)
{
    int k = threadIdx.x;  // 0..255
    #pragma unroll
    for (int h = 0; h < 4; h++) {
        float ss = 0.f, sd = 0.f;
        for (int d = 0; d < 64; d++) {
            ss += W1s[k * 256 + h * 64 + d] * a1s[h * 64 + d];
            sd += W1d[k * 256 + h * 64 + d] * a1d[h * 64 + d];
        }
        g_vS1[h * 256 + k] = ss;
        g_vD1[h * 256 + k] = sd;
    }
    float s2 = 0.f, d2 = 0.f;
    for (int d = 0; d < 64; d++) {
        s2 += W2s[k * 64 + d] * a2s[d];
        d2 += W2d[k * 64 + d] * a2d[d];
    }
    g_vS2[k] = s2;
    g_vD2[k] = d2;
    g_comb1[k] = b1[k] + s1b[k];
    if (k < 64) g_comb2[k] = b2[k] + s2b[k];
}

// ---------------- CSR build ----------------
__global__ void zero_counts()
{
    int i = blockIdx.x * blockDim.x + threadIdx.x;
    if (i < NT1C) g_cnt1[i] = 0;
    if (i < NT2C) g_cnt2[i] = 0;
}

__global__ void count_kernel(const int* __restrict__ dst, int* __restrict__ cnt, int E)
{
    int e = blockIdx.x * blockDim.x + threadIdx.x;
    if (e < E) atomicAdd(&cnt[dst[e]], 1);
}

__global__ void scan_kernel(const int* __restrict__ cnt, int* __restrict__ off,
                            int* __restrict__ cur, int n)
{
    __shared__ int buf[1024];
    __shared__ int carry;
    int t = threadIdx.x;
    if (t == 0) { carry = 0; off[0] = 0; }
    __syncthreads();
    for (int base = 0; base < n; base += 1024) {
        int i = base + t;
        int v = (i < n) ? cnt[i] : 0;
        buf[t] = v;
        __syncthreads();
        #pragma unroll
        for (int d = 1; d < 1024; d <<= 1) {
            int x = (t >= d) ? buf[t - d] : 0;
            __syncthreads();
            buf[t] += x;
            __syncthreads();
        }
        if (i < n) {
            int incl = carry + buf[t];
            off[i + 1] = incl;
            cur[i] = incl - v;
        }
        __syncthreads();
        if (t == 0) carry += buf[1023];
        __syncthreads();
    }
}

__global__ void fill_kernel(const int* __restrict__ dst, int* __restrict__ cur,
                            int* __restrict__ eid, int E)
{
    int e = blockIdx.x * blockDim.x + threadIdx.x;
    if (e < E) {
        int p = atomicAdd(&cur[dst[e]], 1);
        eid[p] = e;
    }
}

// ---------------- SGEMM (FFMA2): C[M,N] = A[M,256] @ B[256,N] (+ bias) -------
// BM=128, BK=16, 256 threads. Microtile 8 rows x TN cols, rows packed in pairs
// into f32x2 accumulators. Double-buffered smem with register prefetch.
template <int BN, int TN>
__global__ __launch_bounds__(256) void sgemm_f2(
    const float* __restrict__ A, const float* __restrict__ B,
    const float* __restrict__ bias, float* __restrict__ C, int M, int N)
{
    constexpr int BM = 128;
    constexpr int BK = 16;
    constexpr int AL = BM + 4;                 // padded A-tile row (528B: 16B aligned)
    constexpr int BLOADS = (BK * BN) / 4 / 256;  // float4 loads of B per thread
    __shared__ float As[2][BK][AL];
    __shared__ float Bs[2][BK][BN];

    int tid = threadIdx.x;
    int tx = tid & 15;            // 16 thread-cols * TN
    int ty = tid >> 4;            // 16 thread-rows * 8
    int bm0 = blockIdx.y * BM;
    int bn0 = blockIdx.x * BN;

    unsigned long long acc[4][TN];
    #pragma unroll
    for (int i = 0; i < 4; i++)
        #pragma unroll
        for (int j = 0; j < TN; j++) acc[i][j] = 0ull;

    // global-load helpers (predicated on M for A)
    float4 ra[2], rb[BLOADS];
    auto ldgA = [&](int k0) {
        #pragma unroll
        for (int u = 0; u < 2; u++) {
            int q = tid + u * 256;        // 0..511 float4 of the 128x16 tile
            int r = q >> 2, c4 = q & 3;
            int row = bm0 + r;
            ra[u] = make_float4(0.f, 0.f, 0.f, 0.f);
            if (row < M) ra[u] = *(const float4*)(A + (size_t)row * KDIM + k0 + c4 * 4);
        }
    };
    auto ldgB = [&](int k0) {
        #pragma unroll
        for (int u = 0; u < BLOADS; u++) {
            int q = tid + u * 256;
            int r = q / (BN / 4), c4 = q % (BN / 4);
            rb[u] = *(const float4*)(B + (size_t)(k0 + r) * N + bn0 + c4 * 4);
        }
    };
    auto sts = [&](int buf) {
        #pragma unroll
        for (int u = 0; u < 2; u++) {
            int q = tid + u * 256;
            int r = q >> 2, c4 = q & 3;
            As[buf][c4 * 4 + 0][r] = ra[u].x;
            As[buf][c4 * 4 + 1][r] = ra[u].y;
            As[buf][c4 * 4 + 2][r] = ra[u].z;
            As[buf][c4 * 4 + 3][r] = ra[u].w;
        }
        #pragma unroll
        for (int u = 0; u < BLOADS; u++) {
            int q = tid + u * 256;
            int r = q / (BN / 4), c4 = q % (BN / 4);
            *(float4*)&Bs[buf][r][c4 * 4] = rb[u];
        }
    };

    ldgA(0); ldgB(0);
    sts(0);
    __syncthreads();

    constexpr int NT = KDIM / BK;   // 16
    int buf = 0;
    for (int t = 0; t < NT; t++) {
        if (t + 1 < NT) { ldgA((t + 1) * BK); ldgB((t + 1) * BK); }
        #pragma unroll
        for (int k = 0; k < BK; k++) {
            float4 a0 = *(const float4*)&As[buf][k][ty * 8];
            float4 a1 = *(const float4*)&As[buf][k][ty * 8 + 4];
            unsigned long long ap[4];
            ap[0] = pk2(a0.x, a0.y);
            ap[1] = pk2(a0.z, a0.w);
            ap[2] = pk2(a1.x, a1.y);
            ap[3] = pk2(a1.z, a1.w);
            float bv[TN];
            #pragma unroll
            for (int j4 = 0; j4 < TN / 4; j4++)
                *(float4*)&bv[j4 * 4] = *(const float4*)&Bs[buf][k][tx * TN + j4 * 4];
            unsigned long long bd[TN];
            #pragma unroll
            for (int j = 0; j < TN; j++) bd[j] = dup2(bv[j]);
            #pragma unroll
            for (int i = 0; i < 4; i++)
                #pragma unroll
                for (int j = 0; j < TN; j++)
                    ffma2(acc[i][j], ap[i], bd[j]);
        }
        if (t + 1 < NT) {
            sts(buf ^ 1);
            __syncthreads();
            buf ^= 1;
        }
    }

    float bv[TN];
    #pragma unroll
    for (int j = 0; j < TN; j++) bv[j] = 0.f;
    if (bias) {
        #pragma unroll
        for (int j4 = 0; j4 < TN / 4; j4++)
            *(float4*)&bv[j4 * 4] = *(const float4*)(bias + bn0 + tx * TN + j4 * 4);
    }
    #pragma unroll
    for (int i = 0; i < 4; i++) {
        float lo[TN], hi[TN];
        #pragma unroll
        for (int j = 0; j < TN; j++) {
            unpk2(acc[i][j], lo[j], hi[j]);
            lo[j] += bv[j];
            hi[j] += bv[j];
        }
        int r0 = bm0 + ty * 8 + i * 2;
        if (r0 < M) {
            #pragma unroll
            for (int j4 = 0; j4 < TN / 4; j4++)
                *(float4*)(C + (size_t)r0 * N + bn0 + tx * TN + j4 * 4) = *(float4*)&lo[j4 * 4];
        }
        if (r0 + 1 < M) {
            #pragma unroll
            for (int j4 = 0; j4 < TN / 4; j4++)
                *(float4*)(C + (size_t)(r0 + 1) * N + bn0 + tx * TN + j4 * 4) = *(float4*)&hi[j4 * 4];
        }
    }
}

// ---------------- skinny row-dot: out[M,H] = X[M,256] @ V^T (V is [H,256]) ----
template <int H>
__global__ void rowdot_kernel(const float* __restrict__ X, const float* __restrict__ V,
                              float* __restrict__ out, int M)
{
    int warp = (blockIdx.x * blockDim.x + threadIdx.x) >> 5;
    int lane = threadIdx.x & 31;
    if (warp >= M) return;
    const float* xr = X + (size_t)warp * 256 + lane * 8;
    float4 x0 = *(const float4*)xr;
    float4 x1 = *(const float4*)(xr + 4);
    float r[H];
    #pragma unroll
    for (int h = 0; h < H; h++) {
        const float* vr = V + h * 256 + lane * 8;
        float4 v0 = *(const float4*)vr;
        float4 v1 = *(const float4*)(vr + 4);
        float s = x0.x * v0.x + x0.y * v0.y + x0.z * v0.z + x0.w * v0.w +
                  x1.x * v1.x + x1.y * v1.y + x1.z * v1.z + x1.w * v1.w;
        #pragma unroll
        for (int o = 16; o; o >>= 1) s += __shfl_xor_sync(0xffffffffu, s, o);
        r[h] = s;
    }
    #pragma unroll
    for (int h = 0; h < H; h++)
        if (lane == h) out[(size_t)warp * H + h] = r[h];
}

// ---------------- layer 1 aggregation: warp per target, online softmax -------
__global__ __launch_bounds__(256) void gat_agg1(const int* __restrict__ src)
{
    int warp = (blockIdx.x * blockDim.x + threadIdx.x) >> 5;
    int lane = threadIdx.x & 31;
    if (warp >= NT1C) return;
    int myh = lane >> 3;                       // head for this lane's 8 features
    float ad = g_ad1[warp * 4 + myh];
    int beg = g_off1[warp], end = g_off1[warp + 1];
    float m = -1e30f, s = 0.f;
    float acc[8];
    #pragma unroll
    for (int j = 0; j < 8; j++) acc[j] = 0.f;

    for (int i = beg; i < end; i++) {
        int sn = src[g_eid1[i]];
        float ev = g_as1[(size_t)sn * 4 + myh] + ad;
        ev = ev > 0.f ? ev : NEG_SLOPE * ev;
        float nm = fmaxf(m, ev);
        float corr = __expf(m - nm);
        float w = __expf(ev - nm);
        s = s * corr + w;
        const float4* r = (const float4*)(g_xs1 + (size_t)sn * 256 + lane * 8);
        float4 r0 = r[0], r1 = r[1];
        acc[0] = acc[0] * corr + w * r0.x;
        acc[1] = acc[1] * corr + w * r0.y;
        acc[2] = acc[2] * corr + w * r0.z;
        acc[3] = acc[3] * corr + w * r0.w;
        acc[4] = acc[4] * corr + w * r1.x;
        acc[5] = acc[5] * corr + w * r1.y;
        acc[6] = acc[6] * corr + w * r1.z;
        acc[7] = acc[7] * corr + w * r1.w;
        m = nm;
    }
    float inv = 1.f / (s + 1e-16f);
    float* hp = g_h + (size_t)warp * 256 + lane * 8;
    float4 h0 = ((float4*)hp)[0], h1 = ((float4*)hp)[1];   // skip + bias
    float v[8];
    v[0] = acc[0] * inv + h0.x;  v[1] = acc[1] * inv + h0.y;
    v[2] = acc[2] * inv + h0.z;  v[3] = acc[3] * inv + h0.w;
    v[4] = acc[4] * inv + h1.x;  v[5] = acc[5] * inv + h1.y;
    v[6] = acc[6] * inv + h1.z;  v[7] = acc[7] * inv + h1.w;
    #pragma unroll
    for (int j = 0; j < 8; j++) v[j] = v[j] > 0.f ? v[j] : (__expf(v[j]) - 1.f);  // ELU
    float4 o0 = make_float4(v[0], v[1], v[2], v[3]);
    float4 o1 = make_float4(v[4], v[5], v[6], v[7]);
    ((float4*)hp)[0] = o0;
    ((float4*)hp)[1] = o1;
}

// ---------------- layer 2 aggregation (heads=1, hid=64) ----------------------
__global__ __launch_bounds__(256) void gat_agg2(const int* __restrict__ src)
{
    int warp = (blockIdx.x * blockDim.x + threadIdx.x) >> 5;
    int lane = threadIdx.x & 31;
    if (warp >= NT2C) return;
    float ad = g_ad2[warp];
    int beg = g_off2[warp], end = g_off2[warp + 1];
    float m = -1e30f, s = 0.f, a0 = 0.f, a1 = 0.f;
    for (int i = beg; i < end; i++) {
        int sn = src[g_eid2[i]];
        float ev = g_as2[sn] + ad;
        ev = ev > 0.f ? ev : NEG_SLOPE * ev;
        float nm = fmaxf(m, ev);
        float corr = __expf(m - nm);
        float w = __expf(ev - nm);
        s = s * corr + w;
        float2 r = *(const float2*)(g_xs2 + (size_t)sn * 64 + lane * 2);
        a0 = a0 * corr + w * r.x;
        a1 = a1 * corr + w * r.y;
        m = nm;
    }
    float inv = 1.f / (s + 1e-16f);
    float2* op = (float2*)(g_o + (size_t)warp * 64 + lane * 2);
    float2 o = *op;                  // skip2 + bias2
    o.x += a0 * inv;
    o.y += a1 * inv;
    *op = o;
}

// ---------------- log_softmax over 64 classes, warp per row -------------------
__global__ void logsoftmax_kernel(float* __restrict__ out)
{
    int warp = (blockIdx.x * blockDim.x + threadIdx.x) >> 5;
    int lane = threadIdx.x & 31;
    if (warp >= NT2C) return;
    float2 v = *(const float2*)(g_o + (size_t)warp * 64 + lane * 2);
    float mx = fmaxf(v.x, v.y);
    #pragma unroll
    for (int o = 16; o; o >>= 1) mx = fmaxf(mx, __shfl_xor_sync(0xffffffffu, mx, o));
    float se = __expf(v.x - mx) + __expf(v.y - mx);
    #pragma unroll
    for (int o = 16; o; o >>= 1) se += __shfl_xor_sync(0xffffffffu, se, o);
    float l = mx + logf(se);
    float2 r;
    r.x = v.x - l;
    r.y = v.y - l;
    *(float2*)(out + (size_t)warp * 64 + lane * 2) = r;
}

// ---------------- host launcher ----------------------------------------------
extern "C" void kernel_launch(void* const* d_in, const int* in_sizes, int n_in,
                              void* d_out, int out_size)
{
    const float* x    = (const float*)d_in[0];
    const int*   src1 = (const int*)d_in[1];
    const int*   dst1 = (const int*)d_in[2];
    const int*   src2 = (const int*)d_in[3];
    const int*   dst2 = (const int*)d_in[4];
    const float* W1s  = (const float*)d_in[7];
    const float* W1d  = (const float*)d_in[8];
    const float* a1s  = (const float*)d_in[9];
    const float* a1d  = (const float*)d_in[10];
    const float* b1   = (const float*)d_in[11];
    const float* sk1W = (const float*)d_in[12];
    const float* sk1b = (const float*)d_in[13];
    const float* W2s  = (const float*)d_in[14];
    const float* W2d  = (const float*)d_in[15];
    const float* a2s  = (const float*)d_in[16];
    const float* a2d  = (const float*)d_in[17];
    const float* b2   = (const float*)d_in[18];
    const float* sk2W = (const float*)d_in[19];
    const float* sk2b = (const float*)d_in[20];

    int N0 = in_sizes[0] / KDIM;
    int E1 = in_sizes[1];
    int E2 = in_sizes[3];

    float *xs1, *hbuf, *xs2, *obuf, *as1, *ad1, *as2, *ad2;
    float *vS1, *vD1, *vS2, *vD2, *comb1, *comb2;
    int *cnt1, *off1, *cur1, *eid1, *cnt2, *off2, *cur2, *eid2;
    cudaGetSymbolAddress((void**)&xs1,  g_xs1);
    cudaGetSymbolAddress((void**)&hbuf, g_h);
    cudaGetSymbolAddress((void**)&xs2,  g_xs2);
    cudaGetSymbolAddress((void**)&obuf, g_o);
    cudaGetSymbolAddress((void**)&as1,  g_as1);
    cudaGetSymbolAddress((void**)&ad1,  g_ad1);
    cudaGetSymbolAddress((void**)&as2,  g_as2);
    cudaGetSymbolAddress((void**)&ad2,  g_ad2);
    cudaGetSymbolAddress((void**)&vS1,  g_vS1);
    cudaGetSymbolAddress((void**)&vD1,  g_vD1);
    cudaGetSymbolAddress((void**)&vS2,  g_vS2);
    cudaGetSymbolAddress((void**)&vD2,  g_vD2);
    cudaGetSymbolAddress((void**)&comb1, g_comb1);
    cudaGetSymbolAddress((void**)&comb2, g_comb2);
    cudaGetSymbolAddress((void**)&cnt1, g_cnt1);
    cudaGetSymbolAddress((void**)&off1, g_off1);
    cudaGetSymbolAddress((void**)&cur1, g_cur1);
    cudaGetSymbolAddress((void**)&eid1, g_eid1);
    cudaGetSymbolAddress((void**)&cnt2, g_cnt2);
    cudaGetSymbolAddress((void**)&off2, g_off2);
    cudaGetSymbolAddress((void**)&cur2, g_cur2);
    cudaGetSymbolAddress((void**)&eid2, g_eid2);

    // launch order arranged so the big xs1 GEMM is launch #5 (ncu -s 5 -c 1)
    fold_kernel<<<1, 256>>>(W1s, W1d, a1s, a1d, b1, sk1b,
                            W2s, W2d, a2s, a2d, b2, sk2b);          // 0
    zero_counts<<<CDIV(NT1C, 256), 256>>>();                        // 1
    count_kernel<<<CDIV(E1, 256), 256>>>(dst1, cnt1, E1);           // 2
    count_kernel<<<CDIV(E2, 256), 256>>>(dst2, cnt2, E2);           // 3
    scan_kernel<<<1, 1024>>>(cnt1, off1, cur1, NT1C);               // 4

    // --- big GEMM: xs1 = x @ W1_src  (launch #5, profiled) ---
    sgemm_f2<128, 8><<<dim3(2, CDIV(N0, 128)), 256>>>(x, W1s, nullptr, xs1, N0, 256);  // 5

    scan_kernel<<<1, 1024>>>(cnt2, off2, cur2, NT2C);               // 6
    fill_kernel<<<CDIV(E1, 256), 256>>>(dst1, cur1, eid1, E1);      // 7
    fill_kernel<<<CDIV(E2, 256), 256>>>(dst2, cur2, eid2, E2);      // 8

    // --- layer 1 ---
    rowdot_kernel<4><<<CDIV(N0 * 32, 256), 256>>>(x, vS1, as1, N0);
    rowdot_kernel<4><<<CDIV(NT1C * 32, 256), 256>>>(x, vD1, ad1, NT1C);
    sgemm_f2<128, 8><<<dim3(2, CDIV(NT1C, 128)), 256>>>(x, sk1W, comb1, hbuf, NT1C, 256);
    gat_agg1<<<CDIV(NT1C * 32, 256), 256>>>(src1);

    // --- layer 2 ---
    sgemm_f2<64, 4><<<dim3(1, CDIV(NT1C, 128)), 256>>>(hbuf, W2s, nullptr, xs2, NT1C, 64);
    rowdot_kernel<1><<<CDIV(NT1C * 32, 256), 256>>>(hbuf, vS2, as2, NT1C);
    rowdot_kernel<1><<<CDIV(NT2C * 32, 256), 256>>>(hbuf, vD2, ad2, NT2C);
    sgemm_f2<64, 4><<<dim3(1, CDIV(NT2C, 128)), 256>>>(hbuf, sk2W, comb2, obuf, NT2C, 64);
    gat_agg2<<<CDIV(NT2C * 32, 256), 256>>>(src2);

    // --- output ---
    logsoftmax_kernel<<<CDIV(NT2C * 32, 256), 256>>>((float*)d_out);
}

// round 10
// speedup vs baseline: 1.3833x; 1.3833x over previous
#include <cuda_runtime.h>
#include <cuda_bf16.h>
#include <cstdint>

#define CDIV(a,b) (((a)+(b)-1)/(b))

// ---------------- problem constants ----------------
#define KDIM   256
#define NT1C   25000
#define NT2C   5000
#define N0C    100000
#define E1CAP  400000
#define E2CAP  100000
#define NEG_SLOPE 0.2f

// ---------------- static scratch ----------------
__device__ float g_xs1[(size_t)N0C * 256];
__device__ float g_h  [(size_t)NT1C * 256];
__device__ float g_xs2[(size_t)NT1C * 64];
__device__ float g_o  [(size_t)NT2C * 64];
__device__ float g_as1[(size_t)N0C * 4];
__device__ float g_ad1[NT1C * 4];
__device__ float g_as2[NT1C];
__device__ float g_ad2[NT2C];
__device__ float g_vS1[4 * 256];
__device__ float g_vD1[4 * 256];
__device__ float g_vS2[256];
__device__ float g_vD2[256];
__device__ float g_comb1[256];
__device__ float g_comb2[64];
// bf16 hi/lo split planes (A operands)
__device__ unsigned short g_xhi[(size_t)N0C * 256];
__device__ unsigned short g_xlo[(size_t)N0C * 256];
__device__ unsigned short g_hhi[(size_t)NT1C * 256];
__device__ unsigned short g_hlo[(size_t)NT1C * 256];
// transposed + split B matrices: [N][K] bf16
__device__ unsigned short g_B1hi[256 * 256],  g_B1lo[256 * 256];
__device__ unsigned short g_Bs1hi[256 * 256], g_Bs1lo[256 * 256];
__device__ unsigned short g_B2hi[64 * 256],   g_B2lo[64 * 256];
__device__ unsigned short g_Bs2hi[64 * 256],  g_Bs2lo[64 * 256];
__device__ int g_cnt1[NT1C];
__device__ int g_off1[NT1C + 1];
__device__ int g_cur1[NT1C];
__device__ int g_eid1[E1CAP];
__device__ int g_cnt2[NT2C];
__device__ int g_off2[NT2C + 1];
__device__ int g_cur2[NT2C];
__device__ int g_eid2[E2CAP];

// ---------------- helpers ----------------
__device__ __forceinline__ uint32_t pack_bf2(float a, float b) {
    unsigned short ua = __bfloat16_as_ushort(__float2bfloat16_rn(a));
    unsigned short ub = __bfloat16_as_ushort(__float2bfloat16_rn(b));
    return (uint32_t)ua | ((uint32_t)ub << 16);
}
__device__ __forceinline__ void split1(float v, unsigned short& h, unsigned short& l) {
    __nv_bfloat16 hb = __float2bfloat16_rn(v);
    float hf = __bfloat162float(hb);
    h = __bfloat16_as_ushort(hb);
    l = __bfloat16_as_ushort(__float2bfloat16_rn(v - hf));
}
__device__ __forceinline__ void mma_bf16(float& c0, float& c1, float& c2, float& c3,
                                         uint32_t a0, uint32_t a1, uint32_t a2, uint32_t a3,
                                         uint32_t b0, uint32_t b1) {
    asm volatile(
        "mma.sync.aligned.m16n8k16.row.col.f32.bf16.bf16.f32 "
        "{%0,%1,%2,%3}, {%4,%5,%6,%7}, {%8,%9}, {%0,%1,%2,%3};"
        : "+f"(c0), "+f"(c1), "+f"(c2), "+f"(c3)
        : "r"(a0), "r"(a1), "r"(a2), "r"(a3), "r"(b0), "r"(b1));
}

// ---------------- bf16 split pass: fp32 -> hi/lo planes ----------------
__global__ void split_kernel(const float* __restrict__ in,
                             unsigned short* __restrict__ hi,
                             unsigned short* __restrict__ lo, int n4)
{
    int i = blockIdx.x * blockDim.x + threadIdx.x;
    if (i >= n4) return;
    float4 v = ((const float4*)in)[i];
    unsigned short h[4], l[4];
    split1(v.x, h[0], l[0]);
    split1(v.y, h[1], l[1]);
    split1(v.z, h[2], l[2]);
    split1(v.w, h[3], l[3]);
    uint2 ph, pl;
    ph.x = (uint32_t)h[0] | ((uint32_t)h[1] << 16);
    ph.y = (uint32_t)h[2] | ((uint32_t)h[3] << 16);
    pl.x = (uint32_t)l[0] | ((uint32_t)l[1] << 16);
    pl.y = (uint32_t)l[2] | ((uint32_t)l[3] << 16);
    *(uint2*)(hi + (size_t)i * 4) = ph;
    *(uint2*)(lo + (size_t)i * 4) = pl;
}

// ---------------- prep: transpose + split B matrices ----------------
__global__ void prep_B(const float* __restrict__ W1s, const float* __restrict__ sk1W,
                       const float* __restrict__ W2s, const float* __restrict__ sk2W)
{
    int k = blockIdx.x;    // 0..255
    int n = threadIdx.x;   // 0..255
    unsigned short h, l;
    split1(W1s[k * 256 + n], h, l);
    g_B1hi[n * 256 + k] = h;  g_B1lo[n * 256 + k] = l;
    split1(sk1W[k * 256 + n], h, l);
    g_Bs1hi[n * 256 + k] = h; g_Bs1lo[n * 256 + k] = l;
    if (n < 64) {
        split1(W2s[k * 64 + n], h, l);
        g_B2hi[n * 256 + k] = h;  g_B2lo[n * 256 + k] = l;
        split1(sk2W[k * 64 + n], h, l);
        g_Bs2hi[n * 256 + k] = h; g_Bs2lo[n * 256 + k] = l;
    }
}

// ---------------- MMA GEMM: C[M,NDIM] = A[M,256] @ B^T (+bias) ---------------
// A given as bf16 hi/lo planes [M][256]; B as [NDIM][256] bf16 hi/lo.
// 3-product split: hi*hi + hi*lo + lo*hi. CTA tile 128x64, 8 warps (4x2).
template <int NDIM>
__global__ __launch_bounds__(256) void gemm_mma(
    const unsigned short* __restrict__ Ahi, const unsigned short* __restrict__ Alo,
    const unsigned short* __restrict__ Bhi, const unsigned short* __restrict__ Blo,
    const float* __restrict__ bias, float* __restrict__ C, int M)
{
    constexpr int P = 40;   // bf16 padding: conflict-free LDS.32 frag loads
    __shared__ __align__(16) unsigned short As[2][128 * P];
    __shared__ __align__(16) unsigned short Bs[2][64 * P];

    int tid = threadIdx.x, lane = tid & 31, wid = tid >> 5;
    int wm = wid >> 1, wn = wid & 1;
    int g = lane >> 2, t = lane & 3;
    int bm0 = blockIdx.x * 128, bn0 = blockIdx.y * 64;

    float acc[2][4][4];
    #pragma unroll
    for (int i = 0; i < 2; i++)
        #pragma unroll
        for (int j = 0; j < 4; j++)
            #pragma unroll
            for (int q = 0; q < 4; q++) acc[i][j][q] = 0.f;

    for (int kt = 0; kt < 8; kt++) {
        int k0 = kt * 32;
        // prefetch global -> regs (uint4 = 8 bf16)
        uint4 ra[2][2], rb[2];
        const unsigned short* Ap[2] = { Ahi, Alo };
        const unsigned short* Bp[2] = { Bhi, Blo };
        #pragma unroll
        for (int pl = 0; pl < 2; pl++) {
            #pragma unroll
            for (int u = 0; u < 2; u++) {
                int q = tid + u * 256;        // 0..511
                int r = q >> 2, c = q & 3;    // 128 rows x 4 chunks
                int row = bm0 + r;
                ra[pl][u] = make_uint4(0, 0, 0, 0);
                if (row < M)
                    ra[pl][u] = *(const uint4*)(Ap[pl] + (size_t)row * KDIM + k0 + c * 8);
            }
            {
                int r = tid >> 2, c = tid & 3;  // 64 rows x 4 chunks
                rb[pl] = *(const uint4*)(Bp[pl] + (size_t)(bn0 + r) * KDIM + k0 + c * 8);
            }
        }
        __syncthreads();
        #pragma unroll
        for (int pl = 0; pl < 2; pl++) {
            #pragma unroll
            for (int u = 0; u < 2; u++) {
                int q = tid + u * 256;
                int r = q >> 2, c = q & 3;
                *(uint4*)&As[pl][r * P + c * 8] = ra[pl][u];
            }
            {
                int r = tid >> 2, c = tid & 3;
                *(uint4*)&Bs[pl][r * P + c * 8] = rb[pl];
            }
        }
        __syncthreads();

        #pragma unroll
        for (int kk = 0; kk < 32; kk += 16) {
            uint32_t ah[2][4], al[2][4];
            #pragma unroll
            for (int mt = 0; mt < 2; mt++) {
                int mr = (wm * 32 + mt * 16 + g) * P + kk + t * 2;
                ah[mt][0] = *(const uint32_t*)&As[0][mr];
                ah[mt][1] = *(const uint32_t*)&As[0][mr + 8 * P];
                ah[mt][2] = *(const uint32_t*)&As[0][mr + 8];
                ah[mt][3] = *(const uint32_t*)&As[0][mr + 8 * P + 8];
                al[mt][0] = *(const uint32_t*)&As[1][mr];
                al[mt][1] = *(const uint32_t*)&As[1][mr + 8 * P];
                al[mt][2] = *(const uint32_t*)&As[1][mr + 8];
                al[mt][3] = *(const uint32_t*)&As[1][mr + 8 * P + 8];
            }
            uint32_t bh[4][2], bl[4][2];
            #pragma unroll
            for (int nt = 0; nt < 4; nt++) {
                int nr = (wn * 32 + nt * 8 + g) * P + kk + t * 2;
                bh[nt][0] = *(const uint32_t*)&Bs[0][nr];
                bh[nt][1] = *(const uint32_t*)&Bs[0][nr + 8];
                bl[nt][0] = *(const uint32_t*)&Bs[1][nr];
                bl[nt][1] = *(const uint32_t*)&Bs[1][nr + 8];
            }
            #pragma unroll
            for (int mt = 0; mt < 2; mt++)
                #pragma unroll
                for (int nt = 0; nt < 4; nt++) {
                    float* c = acc[mt][nt];
                    mma_bf16(c[0], c[1], c[2], c[3],
                             ah[mt][0], ah[mt][1], ah[mt][2], ah[mt][3],
                             bh[nt][0], bh[nt][1]);
                    mma_bf16(c[0], c[1], c[2], c[3],
                             ah[mt][0], ah[mt][1], ah[mt][2], ah[mt][3],
                             bl[nt][0], bl[nt][1]);
                    mma_bf16(c[0], c[1], c[2], c[3],
                             al[mt][0], al[mt][1], al[mt][2], al[mt][3],
                             bh[nt][0], bh[nt][1]);
                }
        }
        __syncthreads();
    }

    // epilogue
    #pragma unroll
    for (int nt = 0; nt < 4; nt++) {
        int cn = bn0 + wn * 32 + nt * 8 + t * 2;
        float2 bv = make_float2(0.f, 0.f);
        if (bias) bv = *(const float2*)(bias + cn);
        #pragma unroll
        for (int mt = 0; mt < 2; mt++) {
            int row0 = bm0 + wm * 32 + mt * 16 + g;
            float* c = acc[mt][nt];
            if (row0 < M) {
                float2 o = make_float2(c[0] + bv.x, c[1] + bv.y);
                *(float2*)(C + (size_t)row0 * NDIM + cn) = o;
            }
            if (row0 + 8 < M) {
                float2 o = make_float2(c[2] + bv.x, c[3] + bv.y);
                *(float2*)(C + (size_t)(row0 + 8) * NDIM + cn) = o;
            }
        }
    }
}

// ---------------- fold: attention projection vectors + combined biases -------
__global__ void fold_kernel(const float* __restrict__ W1s, const float* __restrict__ W1d,
                            const float* __restrict__ a1s, const float* __restrict__ a1d,
                            const float* __restrict__ b1,  const float* __restrict__ s1b,
                            const float* __restrict__ W2s, const float* __restrict__ W2d,
                            const float* __restrict__ a2s, const float* __restrict__ a2d,
                            const float* __restrict__ b2,  const float* __restrict__ s2b)
{
    int k = threadIdx.x;
    #pragma unroll
    for (int h = 0; h < 4; h++) {
        float ss = 0.f, sd = 0.f;
        for (int d = 0; d < 64; d++) {
            ss += W1s[k * 256 + h * 64 + d] * a1s[h * 64 + d];
            sd += W1d[k * 256 + h * 64 + d] * a1d[h * 64 + d];
        }
        g_vS1[h * 256 + k] = ss;
        g_vD1[h * 256 + k] = sd;
    }
    float s2 = 0.f, d2 = 0.f;
    for (int d = 0; d < 64; d++) {
        s2 += W2s[k * 64 + d] * a2s[d];
        d2 += W2d[k * 64 + d] * a2d[d];
    }
    g_vS2[k] = s2;
    g_vD2[k] = d2;
    g_comb1[k] = b1[k] + s1b[k];
    if (k < 64) g_comb2[k] = b2[k] + s2b[k];
}

// ---------------- CSR build ----------------
__global__ void zero_counts()
{
    int i = blockIdx.x * blockDim.x + threadIdx.x;
    if (i < NT1C) g_cnt1[i] = 0;
    if (i < NT2C) g_cnt2[i] = 0;
}

__global__ void count_kernel(const int* __restrict__ dst, int* __restrict__ cnt, int E)
{
    int e = blockIdx.x * blockDim.x + threadIdx.x;
    if (e < E) atomicAdd(&cnt[dst[e]], 1);
}

__global__ void scan_kernel(const int* __restrict__ cnt, int* __restrict__ off,
                            int* __restrict__ cur, int n)
{
    __shared__ int buf[1024];
    __shared__ int carry;
    int t = threadIdx.x;
    if (t == 0) { carry = 0; off[0] = 0; }
    __syncthreads();
    for (int base = 0; base < n; base += 1024) {
        int i = base + t;
        int v = (i < n) ? cnt[i] : 0;
        buf[t] = v;
        __syncthreads();
        #pragma unroll
        for (int d = 1; d < 1024; d <<= 1) {
            int x = (t >= d) ? buf[t - d] : 0;
            __syncthreads();
            buf[t] += x;
            __syncthreads();
        }
        if (i < n) {
            int incl = carry + buf[t];
            off[i + 1] = incl;
            cur[i] = incl - v;
        }
        __syncthreads();
        if (t == 0) carry += buf[1023];
        __syncthreads();
    }
}

__global__ void fill_kernel(const int* __restrict__ dst, int* __restrict__ cur,
                            int* __restrict__ eid, int E)
{
    int e = blockIdx.x * blockDim.x + threadIdx.x;
    if (e < E) {
        int p = atomicAdd(&cur[dst[e]], 1);
        eid[p] = e;
    }
}

// ---------------- skinny row-dot ----------------
template <int H>
__global__ void rowdot_kernel(const float* __restrict__ X, const float* __restrict__ V,
                              float* __restrict__ out, int M)
{
    int warp = (blockIdx.x * blockDim.x + threadIdx.x) >> 5;
    int lane = threadIdx.x & 31;
    if (warp >= M) return;
    const float* xr = X + (size_t)warp * 256 + lane * 8;
    float4 x0 = *(const float4*)xr;
    float4 x1 = *(const float4*)(xr + 4);
    float r[H];
    #pragma unroll
    for (int h = 0; h < H; h++) {
        const float* vr = V + h * 256 + lane * 8;
        float4 v0 = *(const float4*)vr;
        float4 v1 = *(const float4*)(vr + 4);
        float s = x0.x * v0.x + x0.y * v0.y + x0.z * v0.z + x0.w * v0.w +
                  x1.x * v1.x + x1.y * v1.y + x1.z * v1.z + x1.w * v1.w;
        #pragma unroll
        for (int o = 16; o; o >>= 1) s += __shfl_xor_sync(0xffffffffu, s, o);
        r[h] = s;
    }
    #pragma unroll
    for (int h = 0; h < H; h++)
        if (lane == h) out[(size_t)warp * H + h] = r[h];
}

// ---------------- layer 1 aggregation ----------------
__global__ __launch_bounds__(256) void gat_agg1(const int* __restrict__ src)
{
    int warp = (blockIdx.x * blockDim.x + threadIdx.x) >> 5;
    int lane = threadIdx.x & 31;
    if (warp >= NT1C) return;
    int myh = lane >> 3;
    float ad = g_ad1[warp * 4 + myh];
    int beg = g_off1[warp], end = g_off1[warp + 1];
    float m = -1e30f, s = 0.f;
    float acc[8];
    #pragma unroll
    for (int j = 0; j < 8; j++) acc[j] = 0.f;

    for (int i = beg; i < end; i++) {
        int sn = src[g_eid1[i]];
        float ev = g_as1[(size_t)sn * 4 + myh] + ad;
        ev = ev > 0.f ? ev : NEG_SLOPE * ev;
        float nm = fmaxf(m, ev);
        float corr = __expf(m - nm);
        float w = __expf(ev - nm);
        s = s * corr + w;
        const float4* r = (const float4*)(g_xs1 + (size_t)sn * 256 + lane * 8);
        float4 r0 = r[0], r1 = r[1];
        acc[0] = acc[0] * corr + w * r0.x;
        acc[1] = acc[1] * corr + w * r0.y;
        acc[2] = acc[2] * corr + w * r0.z;
        acc[3] = acc[3] * corr + w * r0.w;
        acc[4] = acc[4] * corr + w * r1.x;
        acc[5] = acc[5] * corr + w * r1.y;
        acc[6] = acc[6] * corr + w * r1.z;
        acc[7] = acc[7] * corr + w * r1.w;
        m = nm;
    }
    float inv = 1.f / (s + 1e-16f);
    float* hp = g_h + (size_t)warp * 256 + lane * 8;
    float4 h0 = ((float4*)hp)[0], h1 = ((float4*)hp)[1];
    float v[8];
    v[0] = acc[0] * inv + h0.x;  v[1] = acc[1] * inv + h0.y;
    v[2] = acc[2] * inv + h0.z;  v[3] = acc[3] * inv + h0.w;
    v[4] = acc[4] * inv + h1.x;  v[5] = acc[5] * inv + h1.y;
    v[6] = acc[6] * inv + h1.z;  v[7] = acc[7] * inv + h1.w;
    #pragma unroll
    for (int j = 0; j < 8; j++) v[j] = v[j] > 0.f ? v[j] : (__expf(v[j]) - 1.f);
    ((float4*)hp)[0] = make_float4(v[0], v[1], v[2], v[3]);
    ((float4*)hp)[1] = make_float4(v[4], v[5], v[6], v[7]);
}

// ---------------- layer 2 aggregation ----------------
__global__ __launch_bounds__(256) void gat_agg2(const int* __restrict__ src)
{
    int warp = (blockIdx.x * blockDim.x + threadIdx.x) >> 5;
    int lane = threadIdx.x & 31;
    if (warp >= NT2C) return;
    float ad = g_ad2[warp];
    int beg = g_off2[warp], end = g_off2[warp + 1];
    float m = -1e30f, s = 0.f, a0 = 0.f, a1 = 0.f;
    for (int i = beg; i < end; i++) {
        int sn = src[g_eid2[i]];
        float ev = g_as2[sn] + ad;
        ev = ev > 0.f ? ev : NEG_SLOPE * ev;
        float nm = fmaxf(m, ev);
        float corr = __expf(m - nm);
        float w = __expf(ev - nm);
        s = s * corr + w;
        float2 r = *(const float2*)(g_xs2 + (size_t)sn * 64 + lane * 2);
        a0 = a0 * corr + w * r.x;
        a1 = a1 * corr + w * r.y;
        m = nm;
    }
    float inv = 1.f / (s + 1e-16f);
    float2* op = (float2*)(g_o + (size_t)warp * 64 + lane * 2);
    float2 o = *op;
    o.x += a0 * inv;
    o.y += a1 * inv;
    *op = o;
}

// ---------------- log_softmax ----------------
__global__ void logsoftmax_kernel(float* __restrict__ out)
{
    int warp = (blockIdx.x * blockDim.x + threadIdx.x) >> 5;
    int lane = threadIdx.x & 31;
    if (warp >= NT2C) return;
    float2 v = *(const float2*)(g_o + (size_t)warp * 64 + lane * 2);
    float mx = fmaxf(v.x, v.y);
    #pragma unroll
    for (int o = 16; o; o >>= 1) mx = fmaxf(mx, __shfl_xor_sync(0xffffffffu, mx, o));
    float se = __expf(v.x - mx) + __expf(v.y - mx);
    #pragma unroll
    for (int o = 16; o; o >>= 1) se += __shfl_xor_sync(0xffffffffu, se, o);
    float l = mx + logf(se);
    float2 r;
    r.x = v.x - l;
    r.y = v.y - l;
    *(float2*)(out + (size_t)warp * 64 + lane * 2) = r;
}

// ---------------- host launcher ----------------
extern "C" void kernel_launch(void* const* d_in, const int* in_sizes, int n_in,
                              void* d_out, int out_size)
{
    const float* x    = (const float*)d_in[0];
    const int*   src1 = (const int*)d_in[1];
    const int*   dst1 = (const int*)d_in[2];
    const int*   src2 = (const int*)d_in[3];
    const int*   dst2 = (const int*)d_in[4];
    const float* W1s  = (const float*)d_in[7];
    const float* W1d  = (const float*)d_in[8];
    const float* a1s  = (const float*)d_in[9];
    const float* a1d  = (const float*)d_in[10];
    const float* b1   = (const float*)d_in[11];
    const float* sk1W = (const float*)d_in[12];
    const float* sk1b = (const float*)d_in[13];
    const float* W2s  = (const float*)d_in[14];
    const float* W2d  = (const float*)d_in[15];
    const float* a2s  = (const float*)d_in[16];
    const float* a2d  = (const float*)d_in[17];
    const float* b2   = (const float*)d_in[18];
    const float* sk2W = (const float*)d_in[19];
    const float* sk2b = (const float*)d_in[20];

    int N0 = in_sizes[0] / KDIM;
    int E1 = in_sizes[1];
    int E2 = in_sizes[3];

    float *xs1, *hbuf, *xs2, *obuf, *as1, *ad1, *as2, *ad2;
    float *vS1, *vD1, *vS2, *vD2, *comb1, *comb2;
    unsigned short *xhi, *xlo, *hhi, *hlo;
    unsigned short *B1hi, *B1lo, *Bs1hi, *Bs1lo, *B2hi, *B2lo, *Bs2hi, *Bs2lo;
    int *cnt1, *off1, *cur1, *eid1, *cnt2, *off2, *cur2, *eid2;
    cudaGetSymbolAddress((void**)&xs1,  g_xs1);
    cudaGetSymbolAddress((void**)&hbuf, g_h);
    cudaGetSymbolAddress((void**)&xs2,  g_xs2);
    cudaGetSymbolAddress((void**)&obuf, g_o);
    cudaGetSymbolAddress((void**)&as1,  g_as1);
    cudaGetSymbolAddress((void**)&ad1,  g_ad1);
    cudaGetSymbolAddress((void**)&as2,  g_as2);
    cudaGetSymbolAddress((void**)&ad2,  g_ad2);
    cudaGetSymbolAddress((void**)&vS1,  g_vS1);
    cudaGetSymbolAddress((void**)&vD1,  g_vD1);
    cudaGetSymbolAddress((void**)&vS2,  g_vS2);
    cudaGetSymbolAddress((void**)&vD2,  g_vD2);
    cudaGetSymbolAddress((void**)&comb1, g_comb1);
    cudaGetSymbolAddress((void**)&comb2, g_comb2);
    cudaGetSymbolAddress((void**)&xhi,  g_xhi);
    cudaGetSymbolAddress((void**)&xlo,  g_xlo);
    cudaGetSymbolAddress((void**)&hhi,  g_hhi);
    cudaGetSymbolAddress((void**)&hlo,  g_hlo);
    cudaGetSymbolAddress((void**)&B1hi,  g_B1hi);
    cudaGetSymbolAddress((void**)&B1lo,  g_B1lo);
    cudaGetSymbolAddress((void**)&Bs1hi, g_Bs1hi);
    cudaGetSymbolAddress((void**)&Bs1lo, g_Bs1lo);
    cudaGetSymbolAddress((void**)&B2hi,  g_B2hi);
    cudaGetSymbolAddress((void**)&B2lo,  g_B2lo);
    cudaGetSymbolAddress((void**)&Bs2hi, g_Bs2hi);
    cudaGetSymbolAddress((void**)&Bs2lo, g_Bs2lo);
    cudaGetSymbolAddress((void**)&cnt1, g_cnt1);
    cudaGetSymbolAddress((void**)&off1, g_off1);
    cudaGetSymbolAddress((void**)&cur1, g_cur1);
    cudaGetSymbolAddress((void**)&eid1, g_eid1);
    cudaGetSymbolAddress((void**)&cnt2, g_cnt2);
    cudaGetSymbolAddress((void**)&off2, g_off2);
    cudaGetSymbolAddress((void**)&cur2, g_cur2);
    cudaGetSymbolAddress((void**)&eid2, g_eid2);

    // ordering: big xs1 GEMM is launch #5 for ncu (-s 5 -c 1)
    fold_kernel<<<1, 256>>>(W1s, W1d, a1s, a1d, b1, sk1b,
                            W2s, W2d, a2s, a2d, b2, sk2b);              // 0
    prep_B<<<256, 256>>>(W1s, sk1W, W2s, sk2W);                         // 1
    split_kernel<<<CDIV(N0 * 64, 256), 256>>>(x, xhi, xlo, N0 * 64);    // 2
    zero_counts<<<CDIV(NT1C, 256), 256>>>();                            // 3
    count_kernel<<<CDIV(E1, 256), 256>>>(dst1, cnt1, E1);               // 4

    gemm_mma<256><<<dim3(CDIV(N0, 128), 4), 256>>>(xhi, xlo, B1hi, B1lo,
                                                   nullptr, xs1, N0);   // 5 (profiled)

    count_kernel<<<CDIV(E2, 256), 256>>>(dst2, cnt2, E2);               // 6
    scan_kernel<<<1, 1024>>>(cnt1, off1, cur1, NT1C);                   // 7
    scan_kernel<<<1, 1024>>>(cnt2, off2, cur2, NT2C);                   // 8
    fill_kernel<<<CDIV(E1, 256), 256>>>(dst1, cur1, eid1, E1);          // 9
    fill_kernel<<<CDIV(E2, 256), 256>>>(dst2, cur2, eid2, E2);          // 10

    // --- layer 1 ---
    rowdot_kernel<4><<<CDIV(N0 * 32, 256), 256>>>(x, vS1, as1, N0);
    rowdot_kernel<4><<<CDIV(NT1C * 32, 256), 256>>>(x, vD1, ad1, NT1C);
    gemm_mma<256><<<dim3(CDIV(NT1C, 128), 4), 256>>>(xhi, xlo, Bs1hi, Bs1lo,
                                                     comb1, hbuf, NT1C);
    gat_agg1<<<CDIV(NT1C * 32, 256), 256>>>(src1);

    // --- layer 2 ---
    split_kernel<<<CDIV(NT1C * 64, 256), 256>>>(hbuf, hhi, hlo, NT1C * 64);
    gemm_mma<64><<<dim3(CDIV(NT1C, 128), 1), 256>>>(hhi, hlo, B2hi, B2lo,
                                                    nullptr, xs2, NT1C);
    rowdot_kernel<1><<<CDIV(NT1C * 32, 256), 256>>>(hbuf, vS2, as2, NT1C);
    rowdot_kernel<1><<<CDIV(NT2C * 32, 256), 256>>>(hbuf, vD2, ad2, NT2C);
    gemm_mma<64><<<dim3(CDIV(NT2C, 128), 1), 256>>>(hhi, hlo, Bs2hi, Bs2lo,
                                                    comb2, obuf, NT2C);
    gat_agg2<<<CDIV(NT2C * 32, 256), 256>>>(src2);

    // --- output ---
    logsoftmax_kernel<<<CDIV(NT2C * 32, 256), 256>>>((float*)d_out);
}

// round 11
// speedup vs baseline: 1.5598x; 1.1276x over previous
#include <cuda_runtime.h>
#include <cuda_bf16.h>
#include <cstdint>

#define CDIV(a,b) (((a)+(b)-1)/(b))

// ---------------- problem constants ----------------
#define KDIM   256
#define NT1C   25000
#define NT2C   5000
#define N0C    100000
#define E1CAP  400000
#define E2CAP  100000
#define NEG_SLOPE 0.2f

// ---------------- static scratch ----------------
__device__ float g_xs1[(size_t)N0C * 256];
__device__ float g_h  [(size_t)NT1C * 256];
__device__ float g_xs2[(size_t)NT1C * 64];
__device__ float g_o  [(size_t)NT2C * 64];
__device__ float g_as1[(size_t)N0C * 4];
__device__ float g_ad1[NT1C * 4];
__device__ float g_as2[NT1C];
__device__ float g_ad2[NT2C];
__device__ float g_vS1[4 * 256];
__device__ float g_vD1[4 * 256];
__device__ float g_vS2[256];
__device__ float g_vD2[256];
__device__ float g_comb1[256];
__device__ float g_comb2[64];
__device__ unsigned short g_xhi[(size_t)N0C * 256];
__device__ unsigned short g_xlo[(size_t)N0C * 256];
__device__ unsigned short g_hhi[(size_t)NT1C * 256];
__device__ unsigned short g_hlo[(size_t)NT1C * 256];
__device__ unsigned short g_B1hi[256 * 256],  g_B1lo[256 * 256];
__device__ unsigned short g_Bs1hi[256 * 256], g_Bs1lo[256 * 256];
__device__ unsigned short g_B2hi[64 * 256],   g_B2lo[64 * 256];
__device__ unsigned short g_Bs2hi[64 * 256],  g_Bs2lo[64 * 256];
__device__ int g_cnt1[NT1C];
__device__ int g_off1[NT1C + 1];
__device__ int g_cur1[NT1C];
__device__ int g_eid1[E1CAP];
__device__ int g_cnt2[NT2C];
__device__ int g_off2[NT2C + 1];
__device__ int g_cur2[NT2C];
__device__ int g_eid2[E2CAP];

// ---------------- helpers ----------------
__device__ __forceinline__ uint32_t smem_u32(const void* p) {
    uint32_t a;
    asm("{ .reg .u64 t; cvta.to.shared.u64 t, %1; cvt.u32.u64 %0, t; }" : "=r"(a) : "l"(p));
    return a;
}
__device__ __forceinline__ void split1(float v, unsigned short& h, unsigned short& l) {
    __nv_bfloat16 hb = __float2bfloat16_rn(v);
    float hf = __bfloat162float(hb);
    h = __bfloat16_as_ushort(hb);
    l = __bfloat16_as_ushort(__float2bfloat16_rn(v - hf));
}
__device__ __forceinline__ void mma_bf16(float& c0, float& c1, float& c2, float& c3,
                                         uint32_t a0, uint32_t a1, uint32_t a2, uint32_t a3,
                                         uint32_t b0, uint32_t b1) {
    asm volatile(
        "mma.sync.aligned.m16n8k16.row.col.f32.bf16.bf16.f32 "
        "{%0,%1,%2,%3}, {%4,%5,%6,%7}, {%8,%9}, {%0,%1,%2,%3};"
        : "+f"(c0), "+f"(c1), "+f"(c2), "+f"(c3)
        : "r"(a0), "r"(a1), "r"(a2), "r"(a3), "r"(b0), "r"(b1));
}
#define LDSM4(r, a) \
    asm volatile("ldmatrix.sync.aligned.m8n8.x4.shared.b16 {%0,%1,%2,%3}, [%4];" \
        : "=r"((r)[0]), "=r"((r)[1]), "=r"((r)[2]), "=r"((r)[3]) : "r"(a))

// ---------------- fused split + attention dots (warp per row) ----------------
// Streams X once: writes bf16 hi/lo planes, computes a_src (H dots, all M rows)
// and a_dst (H dots, first Mdst rows).
template <int H>
__global__ void split_dot(const float* __restrict__ X,
                          unsigned short* __restrict__ hi, unsigned short* __restrict__ lo,
                          const float* __restrict__ Vs, const float* __restrict__ Vd,
                          float* __restrict__ as_, float* __restrict__ ad_,
                          int M, int Mdst)
{
    int warp = (blockIdx.x * blockDim.x + threadIdx.x) >> 5;
    int lane = threadIdx.x & 31;
    if (warp >= M) return;
    const float* xr = X + (size_t)warp * 256 + lane * 8;
    float4 x0 = *(const float4*)xr;
    float4 x1 = *(const float4*)(xr + 4);
    float xv[8] = { x0.x, x0.y, x0.z, x0.w, x1.x, x1.y, x1.z, x1.w };

    unsigned short h8[8], l8[8];
    #pragma unroll
    for (int j = 0; j < 8; j++) split1(xv[j], h8[j], l8[j]);
    uint4 ph, pl;
    ph.x = (uint32_t)h8[0] | ((uint32_t)h8[1] << 16);
    ph.y = (uint32_t)h8[2] | ((uint32_t)h8[3] << 16);
    ph.z = (uint32_t)h8[4] | ((uint32_t)h8[5] << 16);
    ph.w = (uint32_t)h8[6] | ((uint32_t)h8[7] << 16);
    pl.x = (uint32_t)l8[0] | ((uint32_t)l8[1] << 16);
    pl.y = (uint32_t)l8[2] | ((uint32_t)l8[3] << 16);
    pl.z = (uint32_t)l8[4] | ((uint32_t)l8[5] << 16);
    pl.w = (uint32_t)l8[6] | ((uint32_t)l8[7] << 16);
    *(uint4*)(hi + (size_t)warp * 256 + lane * 8) = ph;
    *(uint4*)(lo + (size_t)warp * 256 + lane * 8) = pl;

    #pragma unroll
    for (int hh = 0; hh < H; hh++) {
        const float* vr = Vs + hh * 256 + lane * 8;
        float4 v0 = *(const float4*)vr;
        float4 v1 = *(const float4*)(vr + 4);
        float s = xv[0]*v0.x + xv[1]*v0.y + xv[2]*v0.z + xv[3]*v0.w +
                  xv[4]*v1.x + xv[5]*v1.y + xv[6]*v1.z + xv[7]*v1.w;
        #pragma unroll
        for (int o = 16; o; o >>= 1) s += __shfl_xor_sync(0xffffffffu, s, o);
        if (lane == hh) as_[(size_t)warp * H + hh] = s;
    }
    if (warp < Mdst) {
        #pragma unroll
        for (int hh = 0; hh < H; hh++) {
            const float* vr = Vd + hh * 256 + lane * 8;
            float4 v0 = *(const float4*)vr;
            float4 v1 = *(const float4*)(vr + 4);
            float s = xv[0]*v0.x + xv[1]*v0.y + xv[2]*v0.z + xv[3]*v0.w +
                      xv[4]*v1.x + xv[5]*v1.y + xv[6]*v1.z + xv[7]*v1.w;
            #pragma unroll
            for (int o = 16; o; o >>= 1) s += __shfl_xor_sync(0xffffffffu, s, o);
            if (lane == hh) ad_[(size_t)warp * H + hh] = s;
        }
    }
}

// ---------------- prep: transpose + split B matrices ----------------
__global__ void prep_B(const float* __restrict__ W1s, const float* __restrict__ sk1W,
                       const float* __restrict__ W2s, const float* __restrict__ sk2W)
{
    int k = blockIdx.x;    // 0..255
    int n = threadIdx.x;   // 0..255
    unsigned short h, l;
    split1(W1s[k * 256 + n], h, l);
    g_B1hi[n * 256 + k] = h;  g_B1lo[n * 256 + k] = l;
    split1(sk1W[k * 256 + n], h, l);
    g_Bs1hi[n * 256 + k] = h; g_Bs1lo[n * 256 + k] = l;
    if (n < 64) {
        split1(W2s[k * 64 + n], h, l);
        g_B2hi[n * 256 + k] = h;  g_B2lo[n * 256 + k] = l;
        split1(sk2W[k * 64 + n], h, l);
        g_Bs2hi[n * 256 + k] = h; g_Bs2lo[n * 256 + k] = l;
    }
}

// ---------------- MMA GEMM v2: C[M,NDIM] = A[M,256] @ B^T (+bias) ------------
// BM=128, BN template (128 or 64). cp.async double-buffer, ldmatrix frags,
// 3-product bf16 split (hi*hi + hi*lo + lo*hi). 256 threads, warps 4x2.
template <int BN>
__global__ __launch_bounds__(256) void gemm_mma2(
    const unsigned short* __restrict__ Ahi, const unsigned short* __restrict__ Alo,
    const unsigned short* __restrict__ Bhi, const unsigned short* __restrict__ Blo,
    const float* __restrict__ bias, float* __restrict__ C, int M, int NDIM)
{
    constexpr int P = 40;                       // padded row (bf16): conflict-free
    constexpr uint32_t APL = 128 * P * 2;       // A plane bytes (10240)
    constexpr uint32_t BPL = (uint32_t)BN * P * 2;
    constexpr uint32_t AREG = 4 * APL;          // 2 bufs x 2 planes
    constexpr int NT_N = BN / 16;               // per-warp N frags
    constexpr int NPAIR = BN / 32;              // ldmatrix pairs
    constexpr int BU = BN / 64;                 // B cp.async chunks/thread/plane

    extern __shared__ char smem[];
    uint32_t sb = smem_u32(smem);
    uint32_t sbB = sb + AREG;

    int tid = threadIdx.x, lane = tid & 31, wid = tid >> 5;
    int wm = wid >> 1, wn = wid & 1;
    int g = lane >> 2, t = lane & 3;
    int bm0 = blockIdx.x * 128, bn0 = blockIdx.y * BN;

    // ldmatrix per-lane base offsets
    int q8 = lane & 7, mm = lane >> 3;
    uint32_t aoff = (uint32_t)((wm * 32 + (mm & 1) * 8 + q8) * P * 2 + ((mm & 2) * 4) * 2);
    uint32_t boff = (uint32_t)((wn * (BN / 2) + ((mm >> 1) & 1) * 8 + q8) * P * 2 + ((mm & 1) * 8) * 2);

    float acc[2][NT_N][4];
    #pragma unroll
    for (int i = 0; i < 2; i++)
        #pragma unroll
        for (int j = 0; j < NT_N; j++)
            #pragma unroll
            for (int q = 0; q < 4; q++) acc[i][j][q] = 0.f;

    auto ld_stage = [&](int kt, int buf) {
        int k0 = kt * 32;
        #pragma unroll
        for (int pl = 0; pl < 2; pl++) {
            const unsigned short* Ap = pl ? Alo : Ahi;
            #pragma unroll
            for (int u = 0; u < 2; u++) {
                int c = tid + u * 256;         // 0..511
                int r = c >> 2, c4 = c & 3;
                int row = bm0 + r;
                const void* gp = Ap + (size_t)row * KDIM + k0 + c4 * 8;
                uint32_t dst = sb + (buf * 2 + pl) * APL + (uint32_t)(r * P * 2 + c4 * 16);
                int sz = (row < M) ? 16 : 0;
                asm volatile("cp.async.cg.shared.global [%0], [%1], 16, %2;"
                             :: "r"(dst), "l"(gp), "r"(sz));
            }
            const unsigned short* Bp = pl ? Blo : Bhi;
            #pragma unroll
            for (int u = 0; u < BU; u++) {
                int c = tid + u * 256;
                int r = c >> 2, c4 = c & 3;
                const void* gp = Bp + (size_t)(bn0 + r) * KDIM + k0 + c4 * 8;
                uint32_t dst = sbB + (buf * 2 + pl) * BPL + (uint32_t)(r * P * 2 + c4 * 16);
                asm volatile("cp.async.cg.shared.global [%0], [%1], 16;"
                             :: "r"(dst), "l"(gp));
            }
        }
        asm volatile("cp.async.commit_group;");
    };

    auto compute = [&](int buf) {
        #pragma unroll
        for (int kk = 0; kk < 32; kk += 16) {
            uint32_t ah[2][4], al[2][4];
            #pragma unroll
            for (int mt = 0; mt < 2; mt++) {
                uint32_t ad = sb + (buf * 2) * APL + aoff + (uint32_t)(mt * 16 * P * 2 + kk * 2);
                LDSM4(ah[mt], ad);
                LDSM4(al[mt], ad + APL);
            }
            uint32_t bh[NT_N][2], bl[NT_N][2];
            #pragma unroll
            for (int pr = 0; pr < NPAIR; pr++) {
                uint32_t bd = sbB + (buf * 2) * BPL + boff + (uint32_t)(pr * 16 * P * 2 + kk * 2);
                uint32_t r4[4];
                LDSM4(r4, bd);
                bh[2 * pr][0] = r4[0]; bh[2 * pr][1] = r4[1];
                bh[2 * pr + 1][0] = r4[2]; bh[2 * pr + 1][1] = r4[3];
                LDSM4(r4, bd + BPL);
                bl[2 * pr][0] = r4[0]; bl[2 * pr][1] = r4[1];
                bl[2 * pr + 1][0] = r4[2]; bl[2 * pr + 1][1] = r4[3];
            }
            #pragma unroll
            for (int mt = 0; mt < 2; mt++)
                #pragma unroll
                for (int nt = 0; nt < NT_N; nt++) {
                    float* c = acc[mt][nt];
                    mma_bf16(c[0], c[1], c[2], c[3],
                             ah[mt][0], ah[mt][1], ah[mt][2], ah[mt][3],
                             bh[nt][0], bh[nt][1]);
                    mma_bf16(c[0], c[1], c[2], c[3],
                             ah[mt][0], ah[mt][1], ah[mt][2], ah[mt][3],
                             bl[nt][0], bl[nt][1]);
                    mma_bf16(c[0], c[1], c[2], c[3],
                             al[mt][0], al[mt][1], al[mt][2], al[mt][3],
                             bh[nt][0], bh[nt][1]);
                }
        }
    };

    ld_stage(0, 0);
    asm volatile("cp.async.wait_group 0;");
    __syncthreads();
    int buf = 0;
    for (int kt = 0; kt < 8; kt++) {
        if (kt < 7) ld_stage(kt + 1, buf ^ 1);
        compute(buf);
        if (kt < 7) asm volatile("cp.async.wait_group 0;");
        __syncthreads();
        buf ^= 1;
    }

    // epilogue
    #pragma unroll
    for (int nt = 0; nt < NT_N; nt++) {
        int cn = bn0 + wn * (BN / 2) + nt * 8 + t * 2;
        float2 bv = make_float2(0.f, 0.f);
        if (bias) bv = *(const float2*)(bias + cn);
        #pragma unroll
        for (int mt = 0; mt < 2; mt++) {
            int row0 = bm0 + wm * 32 + mt * 16 + g;
            float* c = acc[mt][nt];
            if (row0 < M) {
                float2 o = make_float2(c[0] + bv.x, c[1] + bv.y);
                *(float2*)(C + (size_t)row0 * NDIM + cn) = o;
            }
            if (row0 + 8 < M) {
                float2 o = make_float2(c[2] + bv.x, c[3] + bv.y);
                *(float2*)(C + (size_t)(row0 + 8) * NDIM + cn) = o;
            }
        }
    }
}

// ---------------- fold: attention projection vectors + combined biases -------
__global__ void fold_kernel(const float* __restrict__ W1s, const float* __restrict__ W1d,
                            const float* __restrict__ a1s, const float* __restrict__ a1d,
                            const float* __restrict__ b1,  const float* __restrict__ s1b,
                            const float* __restrict__ W2s, const float* __restrict__ W2d,
                            const float* __restrict__ a2s, const float* __restrict__ a2d,
                            const float* __restrict__ b2,  const float* __restrict__ s2b)
{
    int k = threadIdx.x;
    #pragma unroll
    for (int h = 0; h < 4; h++) {
        float ss = 0.f, sd = 0.f;
        for (int d = 0; d < 64; d++) {
            ss += W1s[k * 256 + h * 64 + d] * a1s[h * 64 + d];
            sd += W1d[k * 256 + h * 64 + d] * a1d[h * 64 + d];
        }
        g_vS1[h * 256 + k] = ss;
        g_vD1[h * 256 + k] = sd;
    }
    float s2 = 0.f, d2 = 0.f;
    for (int d = 0; d < 64; d++) {
        s2 += W2s[k * 64 + d] * a2s[d];
        d2 += W2d[k * 64 + d] * a2d[d];
    }
    g_vS2[k] = s2;
    g_vD2[k] = d2;
    g_comb1[k] = b1[k] + s1b[k];
    if (k < 64) g_comb2[k] = b2[k] + s2b[k];
}

// ---------------- CSR build ----------------
__global__ void zero_counts()
{
    int i = blockIdx.x * blockDim.x + threadIdx.x;
    if (i < NT1C) g_cnt1[i] = 0;
    if (i < NT2C) g_cnt2[i] = 0;
}

__global__ void count_kernel(const int* __restrict__ dst, int* __restrict__ cnt, int E)
{
    int e = blockIdx.x * blockDim.x + threadIdx.x;
    if (e < E) atomicAdd(&cnt[dst[e]], 1);
}

__global__ void scan_kernel(const int* __restrict__ cnt, int* __restrict__ off,
                            int* __restrict__ cur, int n)
{
    __shared__ int buf[1024];
    __shared__ int carry;
    int t = threadIdx.x;
    if (t == 0) { carry = 0; off[0] = 0; }
    __syncthreads();
    for (int base = 0; base < n; base += 1024) {
        int i = base + t;
        int v = (i < n) ? cnt[i] : 0;
        buf[t] = v;
        __syncthreads();
        #pragma unroll
        for (int d = 1; d < 1024; d <<= 1) {
            int x = (t >= d) ? buf[t - d] : 0;
            __syncthreads();
            buf[t] += x;
            __syncthreads();
        }
        if (i < n) {
            int incl = carry + buf[t];
            off[i + 1] = incl;
            cur[i] = incl - v;
        }
        __syncthreads();
        if (t == 0) carry += buf[1023];
        __syncthreads();
    }
}

__global__ void fill_kernel(const int* __restrict__ dst, int* __restrict__ cur,
                            int* __restrict__ eid, int E)
{
    int e = blockIdx.x * blockDim.x + threadIdx.x;
    if (e < E) {
        int p = atomicAdd(&cur[dst[e]], 1);
        eid[p] = e;
    }
}

// ---------------- layer 1 aggregation ----------------
__global__ __launch_bounds__(256) void gat_agg1(const int* __restrict__ src)
{
    int warp = (blockIdx.x * blockDim.x + threadIdx.x) >> 5;
    int lane = threadIdx.x & 31;
    if (warp >= NT1C) return;
    int myh = lane >> 3;
    float ad = g_ad1[warp * 4 + myh];
    int beg = g_off1[warp], end = g_off1[warp + 1];
    float m = -1e30f, s = 0.f;
    float acc[8];
    #pragma unroll
    for (int j = 0; j < 8; j++) acc[j] = 0.f;

    for (int i = beg; i < end; i++) {
        int sn = src[g_eid1[i]];
        float ev = g_as1[(size_t)sn * 4 + myh] + ad;
        ev = ev > 0.f ? ev : NEG_SLOPE * ev;
        float nm = fmaxf(m, ev);
        float corr = __expf(m - nm);
        float w = __expf(ev - nm);
        s = s * corr + w;
        const float4* r = (const float4*)(g_xs1 + (size_t)sn * 256 + lane * 8);
        float4 r0 = r[0], r1 = r[1];
        acc[0] = acc[0] * corr + w * r0.x;
        acc[1] = acc[1] * corr + w * r0.y;
        acc[2] = acc[2] * corr + w * r0.z;
        acc[3] = acc[3] * corr + w * r0.w;
        acc[4] = acc[4] * corr + w * r1.x;
        acc[5] = acc[5] * corr + w * r1.y;
        acc[6] = acc[6] * corr + w * r1.z;
        acc[7] = acc[7] * corr + w * r1.w;
        m = nm;
    }
    float inv = 1.f / (s + 1e-16f);
    float* hp = g_h + (size_t)warp * 256 + lane * 8;
    float4 h0 = ((float4*)hp)[0], h1 = ((float4*)hp)[1];
    float v[8];
    v[0] = acc[0] * inv + h0.x;  v[1] = acc[1] * inv + h0.y;
    v[2] = acc[2] * inv + h0.z;  v[3] = acc[3] * inv + h0.w;
    v[4] = acc[4] * inv + h1.x;  v[5] = acc[5] * inv + h1.y;
    v[6] = acc[6] * inv + h1.z;  v[7] = acc[7] * inv + h1.w;
    #pragma unroll
    for (int j = 0; j < 8; j++) v[j] = v[j] > 0.f ? v[j] : (__expf(v[j]) - 1.f);
    ((float4*)hp)[0] = make_float4(v[0], v[1], v[2], v[3]);
    ((float4*)hp)[1] = make_float4(v[4], v[5], v[6], v[7]);
}

// ---------------- layer 2 aggregation ----------------
__global__ __launch_bounds__(256) void gat_agg2(const int* __restrict__ src)
{
    int warp = (blockIdx.x * blockDim.x + threadIdx.x) >> 5;
    int lane = threadIdx.x & 31;
    if (warp >= NT2C) return;
    float ad = g_ad2[warp];
    int beg = g_off2[warp], end = g_off2[warp + 1];
    float m = -1e30f, s = 0.f, a0 = 0.f, a1 = 0.f;
    for (int i = beg; i < end; i++) {
        int sn = src[g_eid2[i]];
        float ev = g_as2[sn] + ad;
        ev = ev > 0.f ? ev : NEG_SLOPE * ev;
        float nm = fmaxf(m, ev);
        float corr = __expf(m - nm);
        float w = __expf(ev - nm);
        s = s * corr + w;
        float2 r = *(const float2*)(g_xs2 + (size_t)sn * 64 + lane * 2);
        a0 = a0 * corr + w * r.x;
        a1 = a1 * corr + w * r.y;
        m = nm;
    }
    float inv = 1.f / (s + 1e-16f);
    float2* op = (float2*)(g_o + (size_t)warp * 64 + lane * 2);
    float2 o = *op;
    o.x += a0 * inv;
    o.y += a1 * inv;
    *op = o;
}

// ---------------- log_softmax ----------------
__global__ void logsoftmax_kernel(float* __restrict__ out)
{
    int warp = (blockIdx.x * blockDim.x + threadIdx.x) >> 5;
    int lane = threadIdx.x & 31;
    if (warp >= NT2C) return;
    float2 v = *(const float2*)(g_o + (size_t)warp * 64 + lane * 2);
    float mx = fmaxf(v.x, v.y);
    #pragma unroll
    for (int o = 16; o; o >>= 1) mx = fmaxf(mx, __shfl_xor_sync(0xffffffffu, mx, o));
    float se = __expf(v.x - mx) + __expf(v.y - mx);
    #pragma unroll
    for (int o = 16; o; o >>= 1) se += __shfl_xor_sync(0xffffffffu, se, o);
    float l = mx + logf(se);
    float2 r;
    r.x = v.x - l;
    r.y = v.y - l;
    *(float2*)(out + (size_t)warp * 64 + lane * 2) = r;
}

// ---------------- host launcher ----------------
extern "C" void kernel_launch(void* const* d_in, const int* in_sizes, int n_in,
                              void* d_out, int out_size)
{
    const float* x    = (const float*)d_in[0];
    const int*   src1 = (const int*)d_in[1];
    const int*   dst1 = (const int*)d_in[2];
    const int*   src2 = (const int*)d_in[3];
    const int*   dst2 = (const int*)d_in[4];
    const float* W1s  = (const float*)d_in[7];
    const float* W1d  = (const float*)d_in[8];
    const float* a1s  = (const float*)d_in[9];
    const float* a1d  = (const float*)d_in[10];
    const float* b1   = (const float*)d_in[11];
    const float* sk1W = (const float*)d_in[12];
    const float* sk1b = (const float*)d_in[13];
    const float* W2s  = (const float*)d_in[14];
    const float* W2d  = (const float*)d_in[15];
    const float* a2s  = (const float*)d_in[16];
    const float* a2d  = (const float*)d_in[17];
    const float* b2   = (const float*)d_in[18];
    const float* sk2W = (const float*)d_in[19];
    const float* sk2b = (const float*)d_in[20];

    int N0 = in_sizes[0] / KDIM;
    int E1 = in_sizes[1];
    int E2 = in_sizes[3];

    float *xs1, *hbuf, *xs2, *obuf, *as1, *ad1, *as2, *ad2;
    float *vS1, *vD1, *vS2, *vD2, *comb1, *comb2;
    unsigned short *xhi, *xlo, *hhi, *hlo;
    unsigned short *B1hi, *B1lo, *Bs1hi, *Bs1lo, *B2hi, *B2lo, *Bs2hi, *Bs2lo;
    int *cnt1, *off1, *cur1, *eid1, *cnt2, *off2, *cur2, *eid2;
    cudaGetSymbolAddress((void**)&xs1,  g_xs1);
    cudaGetSymbolAddress((void**)&hbuf, g_h);
    cudaGetSymbolAddress((void**)&xs2,  g_xs2);
    cudaGetSymbolAddress((void**)&obuf, g_o);
    cudaGetSymbolAddress((void**)&as1,  g_as1);
    cudaGetSymbolAddress((void**)&ad1,  g_ad1);
    cudaGetSymbolAddress((void**)&as2,  g_as2);
    cudaGetSymbolAddress((void**)&ad2,  g_ad2);
    cudaGetSymbolAddress((void**)&vS1,  g_vS1);
    cudaGetSymbolAddress((void**)&vD1,  g_vD1);
    cudaGetSymbolAddress((void**)&vS2,  g_vS2);
    cudaGetSymbolAddress((void**)&vD2,  g_vD2);
    cudaGetSymbolAddress((void**)&comb1, g_comb1);
    cudaGetSymbolAddress((void**)&comb2, g_comb2);
    cudaGetSymbolAddress((void**)&xhi,  g_xhi);
    cudaGetSymbolAddress((void**)&xlo,  g_xlo);
    cudaGetSymbolAddress((void**)&hhi,  g_hhi);
    cudaGetSymbolAddress((void**)&hlo,  g_hlo);
    cudaGetSymbolAddress((void**)&B1hi,  g_B1hi);
    cudaGetSymbolAddress((void**)&B1lo,  g_B1lo);
    cudaGetSymbolAddress((void**)&Bs1hi, g_Bs1hi);
    cudaGetSymbolAddress((void**)&Bs1lo, g_Bs1lo);
    cudaGetSymbolAddress((void**)&B2hi,  g_B2hi);
    cudaGetSymbolAddress((void**)&B2lo,  g_B2lo);
    cudaGetSymbolAddress((void**)&Bs2hi, g_Bs2hi);
    cudaGetSymbolAddress((void**)&Bs2lo, g_Bs2lo);
    cudaGetSymbolAddress((void**)&cnt1, g_cnt1);
    cudaGetSymbolAddress((void**)&off1, g_off1);
    cudaGetSymbolAddress((void**)&cur1, g_cur1);
    cudaGetSymbolAddress((void**)&eid1, g_eid1);
    cudaGetSymbolAddress((void**)&cnt2, g_cnt2);
    cudaGetSymbolAddress((void**)&off2, g_off2);
    cudaGetSymbolAddress((void**)&cur2, g_cur2);
    cudaGetSymbolAddress((void**)&eid2, g_eid2);

    const int SMEM_BN128 = 4 * 10240 + 4 * 128 * 40 * 2;  // 81920
    const int SMEM_BN64  = 4 * 10240 + 4 * 64 * 40 * 2;   // 61440
    cudaFuncSetAttribute(gemm_mma2<128>, cudaFuncAttributeMaxDynamicSharedMemorySize, SMEM_BN128);
    cudaFuncSetAttribute(gemm_mma2<64>,  cudaFuncAttributeMaxDynamicSharedMemorySize, SMEM_BN64);

    // launch order: big GEMM at index 3 (ncu capture slot)
    fold_kernel<<<1, 256>>>(W1s, W1d, a1s, a1d, b1, sk1b,
                            W2s, W2d, a2s, a2d, b2, sk2b);                       // 0
    prep_B<<<256, 256>>>(W1s, sk1W, W2s, sk2W);                                  // 1
    split_dot<4><<<CDIV(N0 * 32, 256), 256>>>(x, xhi, xlo, vS1, vD1,
                                              as1, ad1, N0, NT1C);               // 2
    gemm_mma2<128><<<dim3(CDIV(N0, 128), 2), 256, SMEM_BN128>>>(
        xhi, xlo, B1hi, B1lo, nullptr, xs1, N0, 256);                            // 3 (profiled)

    zero_counts<<<CDIV(NT1C, 256), 256>>>();                                     // 4
    count_kernel<<<CDIV(E1, 256), 256>>>(dst1, cnt1, E1);                        // 5
    count_kernel<<<CDIV(E2, 256), 256>>>(dst2, cnt2, E2);                        // 6
    scan_kernel<<<1, 1024>>>(cnt1, off1, cur1, NT1C);                            // 7
    scan_kernel<<<1, 1024>>>(cnt2, off2, cur2, NT2C);                            // 8
    fill_kernel<<<CDIV(E1, 256), 256>>>(dst1, cur1, eid1, E1);                   // 9
    fill_kernel<<<CDIV(E2, 256), 256>>>(dst2, cur2, eid2, E2);                   // 10

    // --- layer 1 ---
    gemm_mma2<128><<<dim3(CDIV(NT1C, 128), 2), 256, SMEM_BN128>>>(
        xhi, xlo, Bs1hi, Bs1lo, comb1, hbuf, NT1C, 256);                         // 11
    gat_agg1<<<CDIV(NT1C * 32, 256), 256>>>(src1);                               // 12

    // --- layer 2 ---
    split_dot<1><<<CDIV(NT1C * 32, 256), 256>>>(hbuf, hhi, hlo, vS2, vD2,
                                                as2, ad2, NT1C, NT2C);           // 13
    gemm_mma2<64><<<dim3(CDIV(NT1C, 128), 1), 256, SMEM_BN64>>>(
        hhi, hlo, B2hi, B2lo, nullptr, xs2, NT1C, 64);                           // 14
    gemm_mma2<64><<<dim3(CDIV(NT2C, 128), 1), 256, SMEM_BN64>>>(
        hhi, hlo, Bs2hi, Bs2lo, comb2, obuf, NT2C, 64);                          // 15
    gat_agg2<<<CDIV(NT2C * 32, 256), 256>>>(src2);                               // 16

    // --- output ---
    logsoftmax_kernel<<<CDIV(NT2C * 32, 256), 256>>>((float*)d_out);             // 17
}

// round 12
// speedup vs baseline: 1.7384x; 1.1145x over previous
#include <cuda_runtime.h>
#include <cuda_bf16.h>
#include <cstdint>

#define CDIV(a,b) (((a)+(b)-1)/(b))

// ---------------- problem constants ----------------
#define KDIM   256
#define NT1C   25000
#define NT2C   5000
#define N0C    100000
#define E1CAP  400000
#define E2CAP  100000
#define NEG_SLOPE 0.2f

// ---------------- static scratch ----------------
__device__ float g_xs1[(size_t)N0C * 256];
__device__ float g_h  [(size_t)NT1C * 256];
__device__ float g_xs2[(size_t)NT1C * 64];
__device__ float g_o  [(size_t)NT2C * 64];
__device__ float g_as1[(size_t)N0C * 4];
__device__ float g_ad1[NT1C * 4];
__device__ float g_as2[NT1C];
__device__ float g_ad2[NT2C];
__device__ float g_vS1[4 * 256];
__device__ float g_vD1[4 * 256];
__device__ float g_vS2[256];
__device__ float g_vD2[256];
__device__ float g_comb1[256];
__device__ float g_comb2[64];
__device__ unsigned short g_xhi[(size_t)N0C * 256];
__device__ unsigned short g_xlo[(size_t)N0C * 256];
__device__ unsigned short g_hhi[(size_t)NT1C * 256];
__device__ unsigned short g_hlo[(size_t)NT1C * 256];
__device__ unsigned short g_B1hi[256 * 256],  g_B1lo[256 * 256];
__device__ unsigned short g_Bs1hi[256 * 256], g_Bs1lo[256 * 256];
__device__ unsigned short g_B2hi[64 * 256],   g_B2lo[64 * 256];
__device__ unsigned short g_Bs2hi[64 * 256],  g_Bs2lo[64 * 256];
__device__ int g_cnt1[NT1C];
__device__ int g_off1[NT1C + 1];
__device__ int g_cur1[NT1C];
__device__ int g_srcid1[E1CAP];   // CSR payload: source NODE id (not edge id)
__device__ int g_cnt2[NT2C];
__device__ int g_off2[NT2C + 1];
__device__ int g_cur2[NT2C];
__device__ int g_srcid2[E2CAP];

// ---------------- helpers ----------------
__device__ __forceinline__ uint32_t smem_u32(const void* p) {
    uint32_t a;
    asm("{ .reg .u64 t; cvta.to.shared.u64 t, %1; cvt.u32.u64 %0, t; }" : "=r"(a) : "l"(p));
    return a;
}
__device__ __forceinline__ void split1(float v, unsigned short& h, unsigned short& l) {
    __nv_bfloat16 hb = __float2bfloat16_rn(v);
    float hf = __bfloat162float(hb);
    h = __bfloat16_as_ushort(hb);
    l = __bfloat16_as_ushort(__float2bfloat16_rn(v - hf));
}
__device__ __forceinline__ void mma_bf16(float& c0, float& c1, float& c2, float& c3,
                                         uint32_t a0, uint32_t a1, uint32_t a2, uint32_t a3,
                                         uint32_t b0, uint32_t b1) {
    asm volatile(
        "mma.sync.aligned.m16n8k16.row.col.f32.bf16.bf16.f32 "
        "{%0,%1,%2,%3}, {%4,%5,%6,%7}, {%8,%9}, {%0,%1,%2,%3};"
        : "+f"(c0), "+f"(c1), "+f"(c2), "+f"(c3)
        : "r"(a0), "r"(a1), "r"(a2), "r"(a3), "r"(b0), "r"(b1));
}
#define LDSM4(r, a) \
    asm volatile("ldmatrix.sync.aligned.m8n8.x4.shared.b16 {%0,%1,%2,%3}, [%4];" \
        : "=r"((r)[0]), "=r"((r)[1]), "=r"((r)[2]), "=r"((r)[3]) : "r"(a))

// ---------------- fused split + attention dots (warp per row) ----------------
template <int H>
__global__ void split_dot(const float* __restrict__ X,
                          unsigned short* __restrict__ hi, unsigned short* __restrict__ lo,
                          const float* __restrict__ Vs, const float* __restrict__ Vd,
                          float* __restrict__ as_, float* __restrict__ ad_,
                          int M, int Mdst)
{
    int warp = (blockIdx.x * blockDim.x + threadIdx.x) >> 5;
    int lane = threadIdx.x & 31;
    if (warp >= M) return;
    const float* xr = X + (size_t)warp * 256 + lane * 8;
    float4 x0 = *(const float4*)xr;
    float4 x1 = *(const float4*)(xr + 4);
    float xv[8] = { x0.x, x0.y, x0.z, x0.w, x1.x, x1.y, x1.z, x1.w };

    unsigned short h8[8], l8[8];
    #pragma unroll
    for (int j = 0; j < 8; j++) split1(xv[j], h8[j], l8[j]);
    uint4 ph, pl;
    ph.x = (uint32_t)h8[0] | ((uint32_t)h8[1] << 16);
    ph.y = (uint32_t)h8[2] | ((uint32_t)h8[3] << 16);
    ph.z = (uint32_t)h8[4] | ((uint32_t)h8[5] << 16);
    ph.w = (uint32_t)h8[6] | ((uint32_t)h8[7] << 16);
    pl.x = (uint32_t)l8[0] | ((uint32_t)l8[1] << 16);
    pl.y = (uint32_t)l8[2] | ((uint32_t)l8[3] << 16);
    pl.z = (uint32_t)l8[4] | ((uint32_t)l8[5] << 16);
    pl.w = (uint32_t)l8[6] | ((uint32_t)l8[7] << 16);
    *(uint4*)(hi + (size_t)warp * 256 + lane * 8) = ph;
    *(uint4*)(lo + (size_t)warp * 256 + lane * 8) = pl;

    #pragma unroll
    for (int hh = 0; hh < H; hh++) {
        const float* vr = Vs + hh * 256 + lane * 8;
        float4 v0 = *(const float4*)vr;
        float4 v1 = *(const float4*)(vr + 4);
        float s = xv[0]*v0.x + xv[1]*v0.y + xv[2]*v0.z + xv[3]*v0.w +
                  xv[4]*v1.x + xv[5]*v1.y + xv[6]*v1.z + xv[7]*v1.w;
        #pragma unroll
        for (int o = 16; o; o >>= 1) s += __shfl_xor_sync(0xffffffffu, s, o);
        if (lane == hh) as_[(size_t)warp * H + hh] = s;
    }
    if (warp < Mdst) {
        #pragma unroll
        for (int hh = 0; hh < H; hh++) {
            const float* vr = Vd + hh * 256 + lane * 8;
            float4 v0 = *(const float4*)vr;
            float4 v1 = *(const float4*)(vr + 4);
            float s = xv[0]*v0.x + xv[1]*v0.y + xv[2]*v0.z + xv[3]*v0.w +
                      xv[4]*v1.x + xv[5]*v1.y + xv[6]*v1.z + xv[7]*v1.w;
            #pragma unroll
            for (int o = 16; o; o >>= 1) s += __shfl_xor_sync(0xffffffffu, s, o);
            if (lane == hh) ad_[(size_t)warp * H + hh] = s;
        }
    }
}

// ---------------- prep: transpose + split B matrices ----------------
__global__ void prep_B(const float* __restrict__ W1s, const float* __restrict__ sk1W,
                       const float* __restrict__ W2s, const float* __restrict__ sk2W)
{
    int k = blockIdx.x;    // 0..255
    int n = threadIdx.x;   // 0..255
    unsigned short h, l;
    split1(W1s[k * 256 + n], h, l);
    g_B1hi[n * 256 + k] = h;  g_B1lo[n * 256 + k] = l;
    split1(sk1W[k * 256 + n], h, l);
    g_Bs1hi[n * 256 + k] = h; g_Bs1lo[n * 256 + k] = l;
    if (n < 64) {
        split1(W2s[k * 64 + n], h, l);
        g_B2hi[n * 256 + k] = h;  g_B2lo[n * 256 + k] = l;
        split1(sk2W[k * 64 + n], h, l);
        g_Bs2hi[n * 256 + k] = h; g_Bs2lo[n * 256 + k] = l;
    }
}

// ---------------- MMA GEMM v2: C[M,NDIM] = A[M,256] @ B^T (+bias) ------------
// BM=128, BN template. cp.async double-buffer, ldmatrix frags, 3-product bf16
// split. 256 threads, warps 4x2. minBlocks=2 forces regs<=128 -> 2 CTAs/SM.
template <int BN>
__global__ __launch_bounds__(256, 2) void gemm_mma2(
    const unsigned short* __restrict__ Ahi, const unsigned short* __restrict__ Alo,
    const unsigned short* __restrict__ Bhi, const unsigned short* __restrict__ Blo,
    const float* __restrict__ bias, float* __restrict__ C, int M, int NDIM)
{
    constexpr int P = 40;
    constexpr uint32_t APL = 128 * P * 2;
    constexpr uint32_t BPL = (uint32_t)BN * P * 2;
    constexpr uint32_t AREG = 4 * APL;
    constexpr int NT_N = BN / 16;
    constexpr int NPAIR = BN / 32;
    constexpr int BU = BN / 64;

    extern __shared__ char smem[];
    uint32_t sb = smem_u32(smem);
    uint32_t sbB = sb + AREG;

    int tid = threadIdx.x, lane = tid & 31, wid = tid >> 5;
    int wm = wid >> 1, wn = wid & 1;
    int g = lane >> 2, t = lane & 3;
    int bm0 = blockIdx.x * 128, bn0 = blockIdx.y * BN;

    int q8 = lane & 7, mm = lane >> 3;
    uint32_t aoff = (uint32_t)((wm * 32 + (mm & 1) * 8 + q8) * P * 2 + ((mm & 2) * 4) * 2);
    uint32_t boff = (uint32_t)((wn * (BN / 2) + ((mm >> 1) & 1) * 8 + q8) * P * 2 + ((mm & 1) * 8) * 2);

    float acc[2][NT_N][4];
    #pragma unroll
    for (int i = 0; i < 2; i++)
        #pragma unroll
        for (int j = 0; j < NT_N; j++)
            #pragma unroll
            for (int q = 0; q < 4; q++) acc[i][j][q] = 0.f;

    auto ld_stage = [&](int kt, int buf) {
        int k0 = kt * 32;
        #pragma unroll
        for (int pl = 0; pl < 2; pl++) {
            const unsigned short* Ap = pl ? Alo : Ahi;
            #pragma unroll
            for (int u = 0; u < 2; u++) {
                int c = tid + u * 256;
                int r = c >> 2, c4 = c & 3;
                int row = bm0 + r;
                const void* gp = Ap + (size_t)row * KDIM + k0 + c4 * 8;
                uint32_t dst = sb + (buf * 2 + pl) * APL + (uint32_t)(r * P * 2 + c4 * 16);
                int sz = (row < M) ? 16 : 0;
                asm volatile("cp.async.cg.shared.global [%0], [%1], 16, %2;"
                             :: "r"(dst), "l"(gp), "r"(sz));
            }
            const unsigned short* Bp = pl ? Blo : Bhi;
            #pragma unroll
            for (int u = 0; u < BU; u++) {
                int c = tid + u * 256;
                int r = c >> 2, c4 = c & 3;
                const void* gp = Bp + (size_t)(bn0 + r) * KDIM + k0 + c4 * 8;
                uint32_t dst = sbB + (buf * 2 + pl) * BPL + (uint32_t)(r * P * 2 + c4 * 16);
                asm volatile("cp.async.cg.shared.global [%0], [%1], 16;"
                             :: "r"(dst), "l"(gp));
            }
        }
        asm volatile("cp.async.commit_group;");
    };

    auto compute = [&](int buf) {
        #pragma unroll
        for (int kk = 0; kk < 32; kk += 16) {
            uint32_t ah[2][4], al[2][4];
            #pragma unroll
            for (int mt = 0; mt < 2; mt++) {
                uint32_t ad = sb + (buf * 2) * APL + aoff + (uint32_t)(mt * 16 * P * 2 + kk * 2);
                LDSM4(ah[mt], ad);
                LDSM4(al[mt], ad + APL);
            }
            uint32_t bh[NT_N][2], bl[NT_N][2];
            #pragma unroll
            for (int pr = 0; pr < NPAIR; pr++) {
                uint32_t bd = sbB + (buf * 2) * BPL + boff + (uint32_t)(pr * 16 * P * 2 + kk * 2);
                uint32_t r4[4];
                LDSM4(r4, bd);
                bh[2 * pr][0] = r4[0]; bh[2 * pr][1] = r4[1];
                bh[2 * pr + 1][0] = r4[2]; bh[2 * pr + 1][1] = r4[3];
                LDSM4(r4, bd + BPL);
                bl[2 * pr][0] = r4[0]; bl[2 * pr][1] = r4[1];
                bl[2 * pr + 1][0] = r4[2]; bl[2 * pr + 1][1] = r4[3];
            }
            #pragma unroll
            for (int mt = 0; mt < 2; mt++)
                #pragma unroll
                for (int nt = 0; nt < NT_N; nt++) {
                    float* c = acc[mt][nt];
                    mma_bf16(c[0], c[1], c[2], c[3],
                             ah[mt][0], ah[mt][1], ah[mt][2], ah[mt][3],
                             bh[nt][0], bh[nt][1]);
                    mma_bf16(c[0], c[1], c[2], c[3],
                             ah[mt][0], ah[mt][1], ah[mt][2], ah[mt][3],
                             bl[nt][0], bl[nt][1]);
                    mma_bf16(c[0], c[1], c[2], c[3],
                             al[mt][0], al[mt][1], al[mt][2], al[mt][3],
                             bh[nt][0], bh[nt][1]);
                }
        }
    };

    ld_stage(0, 0);
    asm volatile("cp.async.wait_group 0;");
    __syncthreads();
    int buf = 0;
    for (int kt = 0; kt < 8; kt++) {
        if (kt < 7) ld_stage(kt + 1, buf ^ 1);
        compute(buf);
        if (kt < 7) asm volatile("cp.async.wait_group 0;");
        __syncthreads();
        buf ^= 1;
    }

    #pragma unroll
    for (int nt = 0; nt < NT_N; nt++) {
        int cn = bn0 + wn * (BN / 2) + nt * 8 + t * 2;
        float2 bv = make_float2(0.f, 0.f);
        if (bias) bv = *(const float2*)(bias + cn);
        #pragma unroll
        for (int mt = 0; mt < 2; mt++) {
            int row0 = bm0 + wm * 32 + mt * 16 + g;
            float* c = acc[mt][nt];
            if (row0 < M) {
                float2 o = make_float2(c[0] + bv.x, c[1] + bv.y);
                *(float2*)(C + (size_t)row0 * NDIM + cn) = o;
            }
            if (row0 + 8 < M) {
                float2 o = make_float2(c[2] + bv.x, c[3] + bv.y);
                *(float2*)(C + (size_t)(row0 + 8) * NDIM + cn) = o;
            }
        }
    }
}

// ---------------- fold ----------------
__global__ void fold_kernel(const float* __restrict__ W1s, const float* __restrict__ W1d,
                            const float* __restrict__ a1s, const float* __restrict__ a1d,
                            const float* __restrict__ b1,  const float* __restrict__ s1b,
                            const float* __restrict__ W2s, const float* __restrict__ W2d,
                            const float* __restrict__ a2s, const float* __restrict__ a2d,
                            const float* __restrict__ b2,  const float* __restrict__ s2b)
{
    int k = threadIdx.x;
    #pragma unroll
    for (int h = 0; h < 4; h++) {
        float ss = 0.f, sd = 0.f;
        for (int d = 0; d < 64; d++) {
            ss += W1s[k * 256 + h * 64 + d] * a1s[h * 64 + d];
            sd += W1d[k * 256 + h * 64 + d] * a1d[h * 64 + d];
        }
        g_vS1[h * 256 + k] = ss;
        g_vD1[h * 256 + k] = sd;
    }
    float s2 = 0.f, d2 = 0.f;
    for (int d = 0; d < 64; d++) {
        s2 += W2s[k * 64 + d] * a2s[d];
        d2 += W2d[k * 64 + d] * a2d[d];
    }
    g_vS2[k] = s2;
    g_vD2[k] = d2;
    g_comb1[k] = b1[k] + s1b[k];
    if (k < 64) g_comb2[k] = b2[k] + s2b[k];
}

// ---------------- CSR build ----------------
__global__ void zero_counts()
{
    int i = blockIdx.x * blockDim.x + threadIdx.x;
    if (i < NT1C) g_cnt1[i] = 0;
    if (i < NT2C) g_cnt2[i] = 0;
}

__global__ void count_kernel(const int* __restrict__ dst, int* __restrict__ cnt, int E)
{
    int e = blockIdx.x * blockDim.x + threadIdx.x;
    if (e < E) atomicAdd(&cnt[dst[e]], 1);
}

__global__ void scan_kernel(const int* __restrict__ cnt, int* __restrict__ off,
                            int* __restrict__ cur, int n)
{
    __shared__ int buf[1024];
    __shared__ int carry;
    int t = threadIdx.x;
    if (t == 0) { carry = 0; off[0] = 0; }
    __syncthreads();
    for (int base = 0; base < n; base += 1024) {
        int i = base + t;
        int v = (i < n) ? cnt[i] : 0;
        buf[t] = v;
        __syncthreads();
        #pragma unroll
        for (int d = 1; d < 1024; d <<= 1) {
            int x = (t >= d) ? buf[t - d] : 0;
            __syncthreads();
            buf[t] += x;
            __syncthreads();
        }
        if (i < n) {
            int incl = carry + buf[t];
            off[i + 1] = incl;
            cur[i] = incl - v;
        }
        __syncthreads();
        if (t == 0) carry += buf[1023];
        __syncthreads();
    }
}

// stores SOURCE NODE id per CSR slot (saves one gather in aggregation)
__global__ void fill_kernel(const int* __restrict__ dst, const int* __restrict__ src,
                            int* __restrict__ cur, int* __restrict__ srcid, int E)
{
    int e = blockIdx.x * blockDim.x + threadIdx.x;
    if (e < E) {
        int p = atomicAdd(&cur[dst[e]], 1);
        srcid[p] = src[e];
    }
}

// ---------------- layer 1 aggregation ----------------
__global__ __launch_bounds__(256) void gat_agg1()
{
    int warp = (blockIdx.x * blockDim.x + threadIdx.x) >> 5;
    int lane = threadIdx.x & 31;
    if (warp >= NT1C) return;
    int myh = lane >> 3;
    float ad = g_ad1[warp * 4 + myh];
    int beg = g_off1[warp], end = g_off1[warp + 1];
    float m = -1e30f, s = 0.f;
    float acc[8];
    #pragma unroll
    for (int j = 0; j < 8; j++) acc[j] = 0.f;

    for (int i = beg; i < end; i++) {
        int sn = g_srcid1[i];
        float ev = g_as1[(size_t)sn * 4 + myh] + ad;
        ev = ev > 0.f ? ev : NEG_SLOPE * ev;
        float nm = fmaxf(m, ev);
        float corr = __expf(m - nm);
        float w = __expf(ev - nm);
        s = s * corr + w;
        const float4* r = (const float4*)(g_xs1 + (size_t)sn * 256 + lane * 8);
        float4 r0 = r[0], r1 = r[1];
        acc[0] = acc[0] * corr + w * r0.x;
        acc[1] = acc[1] * corr + w * r0.y;
        acc[2] = acc[2] * corr + w * r0.z;
        acc[3] = acc[3] * corr + w * r0.w;
        acc[4] = acc[4] * corr + w * r1.x;
        acc[5] = acc[5] * corr + w * r1.y;
        acc[6] = acc[6] * corr + w * r1.z;
        acc[7] = acc[7] * corr + w * r1.w;
        m = nm;
    }
    float inv = 1.f / (s + 1e-16f);
    float* hp = g_h + (size_t)warp * 256 + lane * 8;
    float4 h0 = ((float4*)hp)[0], h1 = ((float4*)hp)[1];
    float v[8];
    v[0] = acc[0] * inv + h0.x;  v[1] = acc[1] * inv + h0.y;
    v[2] = acc[2] * inv + h0.z;  v[3] = acc[3] * inv + h0.w;
    v[4] = acc[4] * inv + h1.x;  v[5] = acc[5] * inv + h1.y;
    v[6] = acc[6] * inv + h1.z;  v[7] = acc[7] * inv + h1.w;
    #pragma unroll
    for (int j = 0; j < 8; j++) v[j] = v[j] > 0.f ? v[j] : (__expf(v[j]) - 1.f);
    ((float4*)hp)[0] = make_float4(v[0], v[1], v[2], v[3]);
    ((float4*)hp)[1] = make_float4(v[4], v[5], v[6], v[7]);
}

// ---------------- layer 2 aggregation ----------------
__global__ __launch_bounds__(256) void gat_agg2()
{
    int warp = (blockIdx.x * blockDim.x + threadIdx.x) >> 5;
    int lane = threadIdx.x & 31;
    if (warp >= NT2C) return;
    float ad = g_ad2[warp];
    int beg = g_off2[warp], end = g_off2[warp + 1];
    float m = -1e30f, s = 0.f, a0 = 0.f, a1 = 0.f;
    for (int i = beg; i < end; i++) {
        int sn = g_srcid2[i];
        float ev = g_as2[sn] + ad;
        ev = ev > 0.f ? ev : NEG_SLOPE * ev;
        float nm = fmaxf(m, ev);
        float corr = __expf(m - nm);
        float w = __expf(ev - nm);
        s = s * corr + w;
        float2 r = *(const float2*)(g_xs2 + (size_t)sn * 64 + lane * 2);
        a0 = a0 * corr + w * r.x;
        a1 = a1 * corr + w * r.y;
        m = nm;
    }
    float inv = 1.f / (s + 1e-16f);
    float2* op = (float2*)(g_o + (size_t)warp * 64 + lane * 2);
    float2 o = *op;
    o.x += a0 * inv;
    o.y += a1 * inv;
    *op = o;
}

// ---------------- log_softmax ----------------
__global__ void logsoftmax_kernel(float* __restrict__ out)
{
    int warp = (blockIdx.x * blockDim.x + threadIdx.x) >> 5;
    int lane = threadIdx.x & 31;
    if (warp >= NT2C) return;
    float2 v = *(const float2*)(g_o + (size_t)warp * 64 + lane * 2);
    float mx = fmaxf(v.x, v.y);
    #pragma unroll
    for (int o = 16; o; o >>= 1) mx = fmaxf(mx, __shfl_xor_sync(0xffffffffu, mx, o));
    float se = __expf(v.x - mx) + __expf(v.y - mx);
    #pragma unroll
    for (int o = 16; o; o >>= 1) se += __shfl_xor_sync(0xffffffffu, se, o);
    float l = mx + logf(se);
    float2 r;
    r.x = v.x - l;
    r.y = v.y - l;
    *(float2*)(out + (size_t)warp * 64 + lane * 2) = r;
}

// ---------------- host launcher ----------------
extern "C" void kernel_launch(void* const* d_in, const int* in_sizes, int n_in,
                              void* d_out, int out_size)
{
    const float* x    = (const float*)d_in[0];
    const int*   src1 = (const int*)d_in[1];
    const int*   dst1 = (const int*)d_in[2];
    const int*   src2 = (const int*)d_in[3];
    const int*   dst2 = (const int*)d_in[4];
    const float* W1s  = (const float*)d_in[7];
    const float* W1d  = (const float*)d_in[8];
    const float* a1s  = (const float*)d_in[9];
    const float* a1d  = (const float*)d_in[10];
    const float* b1   = (const float*)d_in[11];
    const float* sk1W = (const float*)d_in[12];
    const float* sk1b = (const float*)d_in[13];
    const float* W2s  = (const float*)d_in[14];
    const float* W2d  = (const float*)d_in[15];
    const float* a2s  = (const float*)d_in[16];
    const float* a2d  = (const float*)d_in[17];
    const float* b2   = (const float*)d_in[18];
    const float* sk2W = (const float*)d_in[19];
    const float* sk2b = (const float*)d_in[20];

    int N0 = in_sizes[0] / KDIM;
    int E1 = in_sizes[1];
    int E2 = in_sizes[3];

    float *xs1, *hbuf, *xs2, *obuf, *as1, *ad1, *as2, *ad2;
    float *vS1, *vD1, *vS2, *vD2, *comb1, *comb2;
    unsigned short *xhi, *xlo, *hhi, *hlo;
    unsigned short *B1hi, *B1lo, *Bs1hi, *Bs1lo, *B2hi, *B2lo, *Bs2hi, *Bs2lo;
    int *cnt1, *off1, *cur1, *sid1, *cnt2, *off2, *cur2, *sid2;
    cudaGetSymbolAddress((void**)&xs1,  g_xs1);
    cudaGetSymbolAddress((void**)&hbuf, g_h);
    cudaGetSymbolAddress((void**)&xs2,  g_xs2);
    cudaGetSymbolAddress((void**)&obuf, g_o);
    cudaGetSymbolAddress((void**)&as1,  g_as1);
    cudaGetSymbolAddress((void**)&ad1,  g_ad1);
    cudaGetSymbolAddress((void**)&as2,  g_as2);
    cudaGetSymbolAddress((void**)&ad2,  g_ad2);
    cudaGetSymbolAddress((void**)&vS1,  g_vS1);
    cudaGetSymbolAddress((void**)&vD1,  g_vD1);
    cudaGetSymbolAddress((void**)&vS2,  g_vS2);
    cudaGetSymbolAddress((void**)&vD2,  g_vD2);
    cudaGetSymbolAddress((void**)&comb1, g_comb1);
    cudaGetSymbolAddress((void**)&comb2, g_comb2);
    cudaGetSymbolAddress((void**)&xhi,  g_xhi);
    cudaGetSymbolAddress((void**)&xlo,  g_xlo);
    cudaGetSymbolAddress((void**)&hhi,  g_hhi);
    cudaGetSymbolAddress((void**)&hlo,  g_hlo);
    cudaGetSymbolAddress((void**)&B1hi,  g_B1hi);
    cudaGetSymbolAddress((void**)&B1lo,  g_B1lo);
    cudaGetSymbolAddress((void**)&Bs1hi, g_Bs1hi);
    cudaGetSymbolAddress((void**)&Bs1lo, g_Bs1lo);
    cudaGetSymbolAddress((void**)&B2hi,  g_B2hi);
    cudaGetSymbolAddress((void**)&B2lo,  g_B2lo);
    cudaGetSymbolAddress((void**)&Bs2hi, g_Bs2hi);
    cudaGetSymbolAddress((void**)&Bs2lo, g_Bs2lo);
    cudaGetSymbolAddress((void**)&cnt1, g_cnt1);
    cudaGetSymbolAddress((void**)&off1, g_off1);
    cudaGetSymbolAddress((void**)&cur1, g_cur1);
    cudaGetSymbolAddress((void**)&sid1, g_srcid1);
    cudaGetSymbolAddress((void**)&cnt2, g_cnt2);
    cudaGetSymbolAddress((void**)&off2, g_off2);
    cudaGetSymbolAddress((void**)&cur2, g_cur2);
    cudaGetSymbolAddress((void**)&sid2, g_srcid2);

    const int SMEM_BN128 = 4 * 10240 + 4 * 128 * 40 * 2;  // 81920
    const int SMEM_BN64  = 4 * 10240 + 4 * 64 * 40 * 2;   // 61440
    cudaFuncSetAttribute(gemm_mma2<128>, cudaFuncAttributeMaxDynamicSharedMemorySize, SMEM_BN128);
    cudaFuncSetAttribute(gemm_mma2<64>,  cudaFuncAttributeMaxDynamicSharedMemorySize, SMEM_BN64);

    // launch order: big GEMM at index 3 (ncu capture slot)
    fold_kernel<<<1, 256>>>(W1s, W1d, a1s, a1d, b1, sk1b,
                            W2s, W2d, a2s, a2d, b2, sk2b);                       // 0
    prep_B<<<256, 256>>>(W1s, sk1W, W2s, sk2W);                                  // 1
    split_dot<4><<<CDIV(N0 * 32, 256), 256>>>(x, xhi, xlo, vS1, vD1,
                                              as1, ad1, N0, NT1C);               // 2
    gemm_mma2<128><<<dim3(CDIV(N0, 128), 2), 256, SMEM_BN128>>>(
        xhi, xlo, B1hi, B1lo, nullptr, xs1, N0, 256);                            // 3 (profiled)

    zero_counts<<<CDIV(NT1C, 256), 256>>>();                                     // 4
    count_kernel<<<CDIV(E1, 256), 256>>>(dst1, cnt1, E1);                        // 5
    count_kernel<<<CDIV(E2, 256), 256>>>(dst2, cnt2, E2);                        // 6
    scan_kernel<<<1, 1024>>>(cnt1, off1, cur1, NT1C);                            // 7
    scan_kernel<<<1, 1024>>>(cnt2, off2, cur2, NT2C);                            // 8
    fill_kernel<<<CDIV(E1, 256), 256>>>(dst1, src1, cur1, sid1, E1);             // 9
    fill_kernel<<<CDIV(E2, 256), 256>>>(dst2, src2, cur2, sid2, E2);             // 10

    // --- layer 1 ---
    gemm_mma2<128><<<dim3(CDIV(NT1C, 128), 2), 256, SMEM_BN128>>>(
        xhi, xlo, Bs1hi, Bs1lo, comb1, hbuf, NT1C, 256);                         // 11
    gat_agg1<<<CDIV(NT1C * 32, 256), 256>>>();                                   // 12

    // --- layer 2 ---
    split_dot<1><<<CDIV(NT1C * 32, 256), 256>>>(hbuf, hhi, hlo, vS2, vD2,
                                                as2, ad2, NT1C, NT2C);           // 13
    gemm_mma2<64><<<dim3(CDIV(NT1C, 128), 1), 256, SMEM_BN64>>>(
        hhi, hlo, B2hi, B2lo, nullptr, xs2, NT1C, 64);                           // 14
    gemm_mma2<64><<<dim3(CDIV(NT2C, 128), 1), 256, SMEM_BN64>>>(
        hhi, hlo, Bs2hi, Bs2lo, comb2, obuf, NT2C, 64);                          // 15
    gat_agg2<<<CDIV(NT2C * 32, 256), 256>>>();                                   // 16

    // --- output ---
    logsoftmax_kernel<<<CDIV(NT2C * 32, 256), 256>>>((float*)d_out);             // 17
}

// round 13
// speedup vs baseline: 1.8494x; 1.0639x over previous
#include <cuda_runtime.h>
#include <cuda_bf16.h>
#include <cstdint>

#define CDIV(a,b) (((a)+(b)-1)/(b))

// ---------------- problem constants ----------------
#define KDIM   256
#define NT1C   25000
#define NT2C   5000
#define N0C    100000
#define E1CAP  400000
#define E2CAP  100000
#define NEG_SLOPE 0.2f

// ---------------- static scratch ----------------
__device__ float g_xs1[(size_t)N0C * 256];
__device__ float g_h  [(size_t)NT1C * 256];
__device__ float g_xs2[(size_t)NT1C * 64];
__device__ float g_o  [(size_t)NT2C * 64];
__device__ float g_as1[(size_t)N0C * 4];
__device__ float g_ad1[NT1C * 4];
__device__ float g_as2[NT1C];
__device__ float g_ad2[NT2C];
__device__ float g_vS1[4 * 256];
__device__ float g_vD1[4 * 256];
__device__ float g_vS2[256];
__device__ float g_vD2[256];
__device__ float g_comb1[256];
__device__ float g_comb2[64];
__device__ unsigned short g_xhi[(size_t)N0C * 256];
__device__ unsigned short g_xlo[(size_t)N0C * 256];
__device__ unsigned short g_hhi[(size_t)NT1C * 256];
__device__ unsigned short g_hlo[(size_t)NT1C * 256];
__device__ unsigned short g_B1hi[256 * 256],  g_B1lo[256 * 256];
__device__ unsigned short g_Bs1hi[256 * 256], g_Bs1lo[256 * 256];
__device__ unsigned short g_B2hi[64 * 256],   g_B2lo[64 * 256];
__device__ unsigned short g_Bs2hi[64 * 256],  g_Bs2lo[64 * 256];
__device__ int g_cnt1[NT1C];
__device__ int g_off1[NT1C + 1];
__device__ int g_cur1[NT1C];
__device__ int g_srcid1[E1CAP];
__device__ int g_cnt2[NT2C];
__device__ int g_off2[NT2C + 1];
__device__ int g_cur2[NT2C];
__device__ int g_srcid2[E2CAP];

// ---------------- helpers ----------------
__device__ __forceinline__ uint32_t smem_u32(const void* p) {
    uint32_t a;
    asm("{ .reg .u64 t; cvta.to.shared.u64 t, %1; cvt.u32.u64 %0, t; }" : "=r"(a) : "l"(p));
    return a;
}
__device__ __forceinline__ void split1(float v, unsigned short& h, unsigned short& l) {
    __nv_bfloat16 hb = __float2bfloat16_rn(v);
    float hf = __bfloat162float(hb);
    h = __bfloat16_as_ushort(hb);
    l = __bfloat16_as_ushort(__float2bfloat16_rn(v - hf));
}
__device__ __forceinline__ void mma_bf16(float& c0, float& c1, float& c2, float& c3,
                                         uint32_t a0, uint32_t a1, uint32_t a2, uint32_t a3,
                                         uint32_t b0, uint32_t b1) {
    asm volatile(
        "mma.sync.aligned.m16n8k16.row.col.f32.bf16.bf16.f32 "
        "{%0,%1,%2,%3}, {%4,%5,%6,%7}, {%8,%9}, {%0,%1,%2,%3};"
        : "+f"(c0), "+f"(c1), "+f"(c2), "+f"(c3)
        : "r"(a0), "r"(a1), "r"(a2), "r"(a3), "r"(b0), "r"(b1));
}
#define LDSM4(r, a) \
    asm volatile("ldmatrix.sync.aligned.m8n8.x4.shared.b16 {%0,%1,%2,%3}, [%4];" \
        : "=r"((r)[0]), "=r"((r)[1]), "=r"((r)[2]), "=r"((r)[3]) : "r"(a))

// ---------------- fused split + attention dots (warp per row) ----------------
template <int H>
__global__ void split_dot(const float* __restrict__ X,
                          unsigned short* __restrict__ hi, unsigned short* __restrict__ lo,
                          const float* __restrict__ Vs, const float* __restrict__ Vd,
                          float* __restrict__ as_, float* __restrict__ ad_,
                          int M, int Mdst)
{
    int warp = (blockIdx.x * blockDim.x + threadIdx.x) >> 5;
    int lane = threadIdx.x & 31;
    if (warp >= M) return;
    const float* xr = X + (size_t)warp * 256 + lane * 8;
    float4 x0 = *(const float4*)xr;
    float4 x1 = *(const float4*)(xr + 4);
    float xv[8] = { x0.x, x0.y, x0.z, x0.w, x1.x, x1.y, x1.z, x1.w };

    unsigned short h8[8], l8[8];
    #pragma unroll
    for (int j = 0; j < 8; j++) split1(xv[j], h8[j], l8[j]);
    uint4 ph, pl;
    ph.x = (uint32_t)h8[0] | ((uint32_t)h8[1] << 16);
    ph.y = (uint32_t)h8[2] | ((uint32_t)h8[3] << 16);
    ph.z = (uint32_t)h8[4] | ((uint32_t)h8[5] << 16);
    ph.w = (uint32_t)h8[6] | ((uint32_t)h8[7] << 16);
    pl.x = (uint32_t)l8[0] | ((uint32_t)l8[1] << 16);
    pl.y = (uint32_t)l8[2] | ((uint32_t)l8[3] << 16);
    pl.z = (uint32_t)l8[4] | ((uint32_t)l8[5] << 16);
    pl.w = (uint32_t)l8[6] | ((uint32_t)l8[7] << 16);
    *(uint4*)(hi + (size_t)warp * 256 + lane * 8) = ph;
    *(uint4*)(lo + (size_t)warp * 256 + lane * 8) = pl;

    #pragma unroll
    for (int hh = 0; hh < H; hh++) {
        const float* vr = Vs + hh * 256 + lane * 8;
        float4 v0 = *(const float4*)vr;
        float4 v1 = *(const float4*)(vr + 4);
        float s = xv[0]*v0.x + xv[1]*v0.y + xv[2]*v0.z + xv[3]*v0.w +
                  xv[4]*v1.x + xv[5]*v1.y + xv[6]*v1.z + xv[7]*v1.w;
        #pragma unroll
        for (int o = 16; o; o >>= 1) s += __shfl_xor_sync(0xffffffffu, s, o);
        if (lane == hh) as_[(size_t)warp * H + hh] = s;
    }
    if (warp < Mdst) {
        #pragma unroll
        for (int hh = 0; hh < H; hh++) {
            const float* vr = Vd + hh * 256 + lane * 8;
            float4 v0 = *(const float4*)vr;
            float4 v1 = *(const float4*)(vr + 4);
            float s = xv[0]*v0.x + xv[1]*v0.y + xv[2]*v0.z + xv[3]*v0.w +
                      xv[4]*v1.x + xv[5]*v1.y + xv[6]*v1.z + xv[7]*v1.w;
            #pragma unroll
            for (int o = 16; o; o >>= 1) s += __shfl_xor_sync(0xffffffffu, s, o);
            if (lane == hh) ad_[(size_t)warp * H + hh] = s;
        }
    }
}

// ---------------- prep: transpose + split B matrices ----------------
__global__ void prep_B(const float* __restrict__ W1s, const float* __restrict__ sk1W,
                       const float* __restrict__ W2s, const float* __restrict__ sk2W)
{
    int k = blockIdx.x;    // 0..255
    int n = threadIdx.x;   // 0..255
    unsigned short h, l;
    split1(W1s[k * 256 + n], h, l);
    g_B1hi[n * 256 + k] = h;  g_B1lo[n * 256 + k] = l;
    split1(sk1W[k * 256 + n], h, l);
    g_Bs1hi[n * 256 + k] = h; g_Bs1lo[n * 256 + k] = l;
    if (n < 64) {
        split1(W2s[k * 64 + n], h, l);
        g_B2hi[n * 256 + k] = h;  g_B2lo[n * 256 + k] = l;
        split1(sk2W[k * 64 + n], h, l);
        g_Bs2hi[n * 256 + k] = h; g_Bs2lo[n * 256 + k] = l;
    }
}

// ---------------- MMA GEMM: C[M,NDIM] = A[M,256] @ B^T (+bias) ---------------
// grid = (N-chunks, M-tiles): x-major order puts both N-halves of the same A
// tile adjacent in launch order -> 2nd read of A hits L2 (halves A DRAM).
template <int BN>
__global__ __launch_bounds__(256, 2) void gemm_mma2(
    const unsigned short* __restrict__ Ahi, const unsigned short* __restrict__ Alo,
    const unsigned short* __restrict__ Bhi, const unsigned short* __restrict__ Blo,
    const float* __restrict__ bias, float* __restrict__ C, int M, int NDIM)
{
    constexpr int P = 40;
    constexpr uint32_t APL = 128 * P * 2;
    constexpr uint32_t BPL = (uint32_t)BN * P * 2;
    constexpr uint32_t AREG = 4 * APL;
    constexpr int NT_N = BN / 16;
    constexpr int NPAIR = BN / 32;
    constexpr int BU = BN / 64;

    extern __shared__ char smem[];
    uint32_t sb = smem_u32(smem);
    uint32_t sbB = sb + AREG;

    int tid = threadIdx.x, lane = tid & 31, wid = tid >> 5;
    int wm = wid >> 1, wn = wid & 1;
    int g = lane >> 2, t = lane & 3;
    int bm0 = blockIdx.y * 128, bn0 = blockIdx.x * BN;

    int q8 = lane & 7, mm = lane >> 3;
    uint32_t aoff = (uint32_t)((wm * 32 + (mm & 1) * 8 + q8) * P * 2 + ((mm & 2) * 4) * 2);
    uint32_t boff = (uint32_t)((wn * (BN / 2) + ((mm >> 1) & 1) * 8 + q8) * P * 2 + ((mm & 1) * 8) * 2);

    float acc[2][NT_N][4];
    #pragma unroll
    for (int i = 0; i < 2; i++)
        #pragma unroll
        for (int j = 0; j < NT_N; j++)
            #pragma unroll
            for (int q = 0; q < 4; q++) acc[i][j][q] = 0.f;

    auto ld_stage = [&](int kt, int buf) {
        int k0 = kt * 32;
        #pragma unroll
        for (int pl = 0; pl < 2; pl++) {
            const unsigned short* Ap = pl ? Alo : Ahi;
            #pragma unroll
            for (int u = 0; u < 2; u++) {
                int c = tid + u * 256;
                int r = c >> 2, c4 = c & 3;
                int row = bm0 + r;
                const void* gp = Ap + (size_t)row * KDIM + k0 + c4 * 8;
                uint32_t dst = sb + (buf * 2 + pl) * APL + (uint32_t)(r * P * 2 + c4 * 16);
                int sz = (row < M) ? 16 : 0;
                asm volatile("cp.async.cg.shared.global [%0], [%1], 16, %2;"
                             :: "r"(dst), "l"(gp), "r"(sz));
            }
            const unsigned short* Bp = pl ? Blo : Bhi;
            #pragma unroll
            for (int u = 0; u < BU; u++) {
                int c = tid + u * 256;
                int r = c >> 2, c4 = c & 3;
                const void* gp = Bp + (size_t)(bn0 + r) * KDIM + k0 + c4 * 8;
                uint32_t dst = sbB + (buf * 2 + pl) * BPL + (uint32_t)(r * P * 2 + c4 * 16);
                asm volatile("cp.async.cg.shared.global [%0], [%1], 16;"
                             :: "r"(dst), "l"(gp));
            }
        }
        asm volatile("cp.async.commit_group;");
    };

    auto compute = [&](int buf) {
        #pragma unroll
        for (int kk = 0; kk < 32; kk += 16) {
            uint32_t ah[2][4], al[2][4];
            #pragma unroll
            for (int mt = 0; mt < 2; mt++) {
                uint32_t ad = sb + (buf * 2) * APL + aoff + (uint32_t)(mt * 16 * P * 2 + kk * 2);
                LDSM4(ah[mt], ad);
                LDSM4(al[mt], ad + APL);
            }
            uint32_t bh[NT_N][2], bl[NT_N][2];
            #pragma unroll
            for (int pr = 0; pr < NPAIR; pr++) {
                uint32_t bd = sbB + (buf * 2) * BPL + boff + (uint32_t)(pr * 16 * P * 2 + kk * 2);
                uint32_t r4[4];
                LDSM4(r4, bd);
                bh[2 * pr][0] = r4[0]; bh[2 * pr][1] = r4[1];
                bh[2 * pr + 1][0] = r4[2]; bh[2 * pr + 1][1] = r4[3];
                LDSM4(r4, bd + BPL);
                bl[2 * pr][0] = r4[0]; bl[2 * pr][1] = r4[1];
                bl[2 * pr + 1][0] = r4[2]; bl[2 * pr + 1][1] = r4[3];
            }
            #pragma unroll
            for (int mt = 0; mt < 2; mt++)
                #pragma unroll
                for (int nt = 0; nt < NT_N; nt++) {
                    float* c = acc[mt][nt];
                    mma_bf16(c[0], c[1], c[2], c[3],
                             ah[mt][0], ah[mt][1], ah[mt][2], ah[mt][3],
                             bh[nt][0], bh[nt][1]);
                    mma_bf16(c[0], c[1], c[2], c[3],
                             ah[mt][0], ah[mt][1], ah[mt][2], ah[mt][3],
                             bl[nt][0], bl[nt][1]);
                    mma_bf16(c[0], c[1], c[2], c[3],
                             al[mt][0], al[mt][1], al[mt][2], al[mt][3],
                             bh[nt][0], bh[nt][1]);
                }
        }
    };

    ld_stage(0, 0);
    asm volatile("cp.async.wait_group 0;");
    __syncthreads();
    int buf = 0;
    for (int kt = 0; kt < 8; kt++) {
        if (kt < 7) ld_stage(kt + 1, buf ^ 1);
        compute(buf);
        if (kt < 7) asm volatile("cp.async.wait_group 0;");
        __syncthreads();
        buf ^= 1;
    }

    #pragma unroll
    for (int nt = 0; nt < NT_N; nt++) {
        int cn = bn0 + wn * (BN / 2) + nt * 8 + t * 2;
        float2 bv = make_float2(0.f, 0.f);
        if (bias) bv = *(const float2*)(bias + cn);
        #pragma unroll
        for (int mt = 0; mt < 2; mt++) {
            int row0 = bm0 + wm * 32 + mt * 16 + g;
            float* c = acc[mt][nt];
            if (row0 < M) {
                float2 o = make_float2(c[0] + bv.x, c[1] + bv.y);
                *(float2*)(C + (size_t)row0 * NDIM + cn) = o;
            }
            if (row0 + 8 < M) {
                float2 o = make_float2(c[2] + bv.x, c[3] + bv.y);
                *(float2*)(C + (size_t)(row0 + 8) * NDIM + cn) = o;
            }
        }
    }
}

// ---------------- fold ----------------
__global__ void fold_kernel(const float* __restrict__ W1s, const float* __restrict__ W1d,
                            const float* __restrict__ a1s, const float* __restrict__ a1d,
                            const float* __restrict__ b1,  const float* __restrict__ s1b,
                            const float* __restrict__ W2s, const float* __restrict__ W2d,
                            const float* __restrict__ a2s, const float* __restrict__ a2d,
                            const float* __restrict__ b2,  const float* __restrict__ s2b)
{
    int k = threadIdx.x;
    #pragma unroll
    for (int h = 0; h < 4; h++) {
        float ss = 0.f, sd = 0.f;
        for (int d = 0; d < 64; d++) {
            ss += W1s[k * 256 + h * 64 + d] * a1s[h * 64 + d];
            sd += W1d[k * 256 + h * 64 + d] * a1d[h * 64 + d];
        }
        g_vS1[h * 256 + k] = ss;
        g_vD1[h * 256 + k] = sd;
    }
    float s2 = 0.f, d2 = 0.f;
    for (int d = 0; d < 64; d++) {
        s2 += W2s[k * 64 + d] * a2s[d];
        d2 += W2d[k * 64 + d] * a2d[d];
    }
    g_vS2[k] = s2;
    g_vD2[k] = d2;
    g_comb1[k] = b1[k] + s1b[k];
    if (k < 64) g_comb2[k] = b2[k] + s2b[k];
}

// ---------------- CSR build (merged kernels) ----------------
__global__ void zero_counts()
{
    int i = blockIdx.x * blockDim.x + threadIdx.x;
    if (i < NT1C) g_cnt1[i] = 0;
    if (i < NT2C) g_cnt2[i] = 0;
}

__global__ void count_both(const int* __restrict__ dst1, const int* __restrict__ dst2,
                           int E1, int E2)
{
    int e = blockIdx.x * blockDim.x + threadIdx.x;
    if (e < E1) atomicAdd(&g_cnt1[dst1[e]], 1);
    else if (e - E1 < E2) atomicAdd(&g_cnt2[dst2[e - E1]], 1);
}

// shuffle-based block scan, 1024 threads; blockIdx selects which CSR
__device__ void scan_impl(const int* __restrict__ cnt, int* __restrict__ off,
                          int* __restrict__ cur, int n)
{
    __shared__ int wpre[32];
    __shared__ int carry;
    int t = threadIdx.x, lane = t & 31, w = t >> 5;
    if (t == 0) { carry = 0; off[0] = 0; }
    __syncthreads();
    for (int base = 0; base < n; base += 1024) {
        int i = base + t;
        int v = (i < n) ? cnt[i] : 0;
        int x = v;
        #pragma unroll
        for (int d = 1; d < 32; d <<= 1) {
            int y = __shfl_up_sync(0xffffffffu, x, d);
            if (lane >= d) x += y;
        }
        if (lane == 31) wpre[w] = x;
        __syncthreads();
        if (w == 0) {
            int s = wpre[lane];
            #pragma unroll
            for (int d = 1; d < 32; d <<= 1) {
                int y = __shfl_up_sync(0xffffffffu, s, d);
                if (lane >= d) s += y;
            }
            wpre[lane] = s;
        }
        __syncthreads();
        int incl = x + (w ? wpre[w - 1] : 0) + carry;
        if (i < n) {
            off[i + 1] = incl;
            cur[i] = incl - v;
        }
        __syncthreads();
        if (t == 1023) carry = incl;
        __syncthreads();
    }
}

__global__ void scan_both()
{
    if (blockIdx.x == 0) scan_impl(g_cnt1, g_off1, g_cur1, NT1C);
    else                 scan_impl(g_cnt2, g_off2, g_cur2, NT2C);
}

__global__ void fill_both(const int* __restrict__ dst1, const int* __restrict__ src1,
                          const int* __restrict__ dst2, const int* __restrict__ src2,
                          int E1, int E2)
{
    int e = blockIdx.x * blockDim.x + threadIdx.x;
    if (e < E1) {
        int p = atomicAdd(&g_cur1[dst1[e]], 1);
        g_srcid1[p] = src1[e];
    } else if (e - E1 < E2) {
        int e2 = e - E1;
        int p = atomicAdd(&g_cur2[dst2[e2]], 1);
        g_srcid2[p] = src2[e2];
    }
}

// ---------------- layer 1 aggregation (pairwise online softmax) --------------
__global__ __launch_bounds__(256) void gat_agg1()
{
    int warp = (blockIdx.x * blockDim.x + threadIdx.x) >> 5;
    int lane = threadIdx.x & 31;
    if (warp >= NT1C) return;
    int myh = lane >> 3;
    float ad = g_ad1[warp * 4 + myh];
    int beg = g_off1[warp], end = g_off1[warp + 1];
    float m = -1e30f, s = 0.f;
    float acc[8];
    #pragma unroll
    for (int j = 0; j < 8; j++) acc[j] = 0.f;

    int i = beg;
    for (; i + 1 < end; i += 2) {
        int sa = g_srcid1[i], sb = g_srcid1[i + 1];
        float ea = g_as1[(size_t)sa * 4 + myh] + ad;
        float eb = g_as1[(size_t)sb * 4 + myh] + ad;
        ea = ea > 0.f ? ea : NEG_SLOPE * ea;
        eb = eb > 0.f ? eb : NEG_SLOPE * eb;
        const float4* pa = (const float4*)(g_xs1 + (size_t)sa * 256 + lane * 8);
        const float4* pb = (const float4*)(g_xs1 + (size_t)sb * 256 + lane * 8);
        float4 a0 = pa[0], a1 = pa[1];
        float4 b0 = pb[0], b1 = pb[1];
        float mp = fmaxf(ea, eb);
        float wa = __expf(ea - mp), wb = __expf(eb - mp);
        float nm = fmaxf(m, mp);
        float cm = __expf(m - nm), cp = __expf(mp - nm);
        s = s * cm + (wa + wb) * cp;
        float wap = wa * cp, wbp = wb * cp;
        acc[0] = acc[0] * cm + wap * a0.x + wbp * b0.x;
        acc[1] = acc[1] * cm + wap * a0.y + wbp * b0.y;
        acc[2] = acc[2] * cm + wap * a0.z + wbp * b0.z;
        acc[3] = acc[3] * cm + wap * a0.w + wbp * b0.w;
        acc[4] = acc[4] * cm + wap * a1.x + wbp * b1.x;
        acc[5] = acc[5] * cm + wap * a1.y + wbp * b1.y;
        acc[6] = acc[6] * cm + wap * a1.z + wbp * b1.z;
        acc[7] = acc[7] * cm + wap * a1.w + wbp * b1.w;
        m = nm;
    }
    if (i < end) {
        int sn = g_srcid1[i];
        float ev = g_as1[(size_t)sn * 4 + myh] + ad;
        ev = ev > 0.f ? ev : NEG_SLOPE * ev;
        float nm = fmaxf(m, ev);
        float corr = __expf(m - nm);
        float w = __expf(ev - nm);
        s = s * corr + w;
        const float4* r = (const float4*)(g_xs1 + (size_t)sn * 256 + lane * 8);
        float4 r0 = r[0], r1 = r[1];
        acc[0] = acc[0] * corr + w * r0.x;
        acc[1] = acc[1] * corr + w * r0.y;
        acc[2] = acc[2] * corr + w * r0.z;
        acc[3] = acc[3] * corr + w * r0.w;
        acc[4] = acc[4] * corr + w * r1.x;
        acc[5] = acc[5] * corr + w * r1.y;
        acc[6] = acc[6] * corr + w * r1.z;
        acc[7] = acc[7] * corr + w * r1.w;
        m = nm;
    }
    float inv = 1.f / (s + 1e-16f);
    float* hp = g_h + (size_t)warp * 256 + lane * 8;
    float4 h0 = ((float4*)hp)[0], h1 = ((float4*)hp)[1];
    float v[8];
    v[0] = acc[0] * inv + h0.x;  v[1] = acc[1] * inv + h0.y;
    v[2] = acc[2] * inv + h0.z;  v[3] = acc[3] * inv + h0.w;
    v[4] = acc[4] * inv + h1.x;  v[5] = acc[5] * inv + h1.y;
    v[6] = acc[6] * inv + h1.z;  v[7] = acc[7] * inv + h1.w;
    #pragma unroll
    for (int j = 0; j < 8; j++) v[j] = v[j] > 0.f ? v[j] : (__expf(v[j]) - 1.f);
    ((float4*)hp)[0] = make_float4(v[0], v[1], v[2], v[3]);
    ((float4*)hp)[1] = make_float4(v[4], v[5], v[6], v[7]);
}

// ---------------- layer 2 aggregation (pairwise) ----------------
__global__ __launch_bounds__(256) void gat_agg2()
{
    int warp = (blockIdx.x * blockDim.x + threadIdx.x) >> 5;
    int lane = threadIdx.x & 31;
    if (warp >= NT2C) return;
    float ad = g_ad2[warp];
    int beg = g_off2[warp], end = g_off2[warp + 1];
    float m = -1e30f, s = 0.f, a0 = 0.f, a1 = 0.f;
    int i = beg;
    for (; i + 1 < end; i += 2) {
        int sa = g_srcid2[i], sb = g_srcid2[i + 1];
        float ea = g_as2[sa] + ad;
        float eb = g_as2[sb] + ad;
        ea = ea > 0.f ? ea : NEG_SLOPE * ea;
        eb = eb > 0.f ? eb : NEG_SLOPE * eb;
        float2 ra = *(const float2*)(g_xs2 + (size_t)sa * 64 + lane * 2);
        float2 rb = *(const float2*)(g_xs2 + (size_t)sb * 64 + lane * 2);
        float mp = fmaxf(ea, eb);
        float wa = __expf(ea - mp), wb = __expf(eb - mp);
        float nm = fmaxf(m, mp);
        float cm = __expf(m - nm), cp = __expf(mp - nm);
        s = s * cm + (wa + wb) * cp;
        float wap = wa * cp, wbp = wb * cp;
        a0 = a0 * cm + wap * ra.x + wbp * rb.x;
        a1 = a1 * cm + wap * ra.y + wbp * rb.y;
        m = nm;
    }
    if (i < end) {
        int sn = g_srcid2[i];
        float ev = g_as2[sn] + ad;
        ev = ev > 0.f ? ev : NEG_SLOPE * ev;
        float nm = fmaxf(m, ev);
        float corr = __expf(m - nm);
        float w = __expf(ev - nm);
        s = s * corr + w;
        float2 r = *(const float2*)(g_xs2 + (size_t)sn * 64 + lane * 2);
        a0 = a0 * corr + w * r.x;
        a1 = a1 * corr + w * r.y;
        m = nm;
    }
    float inv = 1.f / (s + 1e-16f);
    float2* op = (float2*)(g_o + (size_t)warp * 64 + lane * 2);
    float2 o = *op;
    o.x += a0 * inv;
    o.y += a1 * inv;
    *op = o;
}

// ---------------- log_softmax ----------------
__global__ void logsoftmax_kernel(float* __restrict__ out)
{
    int warp = (blockIdx.x * blockDim.x + threadIdx.x) >> 5;
    int lane = threadIdx.x & 31;
    if (warp >= NT2C) return;
    float2 v = *(const float2*)(g_o + (size_t)warp * 64 + lane * 2);
    float mx = fmaxf(v.x, v.y);
    #pragma unroll
    for (int o = 16; o; o >>= 1) mx = fmaxf(mx, __shfl_xor_sync(0xffffffffu, mx, o));
    float se = __expf(v.x - mx) + __expf(v.y - mx);
    #pragma unroll
    for (int o = 16; o; o >>= 1) se += __shfl_xor_sync(0xffffffffu, se, o);
    float l = mx + logf(se);
    float2 r;
    r.x = v.x - l;
    r.y = v.y - l;
    *(float2*)(out + (size_t)warp * 64 + lane * 2) = r;
}

// ---------------- host launcher ----------------
extern "C" void kernel_launch(void* const* d_in, const int* in_sizes, int n_in,
                              void* d_out, int out_size)
{
    const float* x    = (const float*)d_in[0];
    const int*   src1 = (const int*)d_in[1];
    const int*   dst1 = (const int*)d_in[2];
    const int*   src2 = (const int*)d_in[3];
    const int*   dst2 = (const int*)d_in[4];
    const float* W1s  = (const float*)d_in[7];
    const float* W1d  = (const float*)d_in[8];
    const float* a1s  = (const float*)d_in[9];
    const float* a1d  = (const float*)d_in[10];
    const float* b1   = (const float*)d_in[11];
    const float* sk1W = (const float*)d_in[12];
    const float* sk1b = (const float*)d_in[13];
    const float* W2s  = (const float*)d_in[14];
    const float* W2d  = (const float*)d_in[15];
    const float* a2s  = (const float*)d_in[16];
    const float* a2d  = (const float*)d_in[17];
    const float* b2   = (const float*)d_in[18];
    const float* sk2W = (const float*)d_in[19];
    const float* sk2b = (const float*)d_in[20];

    int N0 = in_sizes[0] / KDIM;
    int E1 = in_sizes[1];
    int E2 = in_sizes[3];

    float *xs1, *hbuf, *xs2, *obuf, *as1, *ad1, *as2, *ad2;
    float *vS1, *vD1, *vS2, *vD2, *comb1, *comb2;
    unsigned short *xhi, *xlo, *hhi, *hlo;
    unsigned short *B1hi, *B1lo, *Bs1hi, *Bs1lo, *B2hi, *B2lo, *Bs2hi, *Bs2lo;
    cudaGetSymbolAddress((void**)&xs1,  g_xs1);
    cudaGetSymbolAddress((void**)&hbuf, g_h);
    cudaGetSymbolAddress((void**)&xs2,  g_xs2);
    cudaGetSymbolAddress((void**)&obuf, g_o);
    cudaGetSymbolAddress((void**)&as1,  g_as1);
    cudaGetSymbolAddress((void**)&ad1,  g_ad1);
    cudaGetSymbolAddress((void**)&as2,  g_as2);
    cudaGetSymbolAddress((void**)&ad2,  g_ad2);
    cudaGetSymbolAddress((void**)&vS1,  g_vS1);
    cudaGetSymbolAddress((void**)&vD1,  g_vD1);
    cudaGetSymbolAddress((void**)&vS2,  g_vS2);
    cudaGetSymbolAddress((void**)&vD2,  g_vD2);
    cudaGetSymbolAddress((void**)&comb1, g_comb1);
    cudaGetSymbolAddress((void**)&comb2, g_comb2);
    cudaGetSymbolAddress((void**)&xhi,  g_xhi);
    cudaGetSymbolAddress((void**)&xlo,  g_xlo);
    cudaGetSymbolAddress((void**)&hhi,  g_hhi);
    cudaGetSymbolAddress((void**)&hlo,  g_hlo);
    cudaGetSymbolAddress((void**)&B1hi,  g_B1hi);
    cudaGetSymbolAddress((void**)&B1lo,  g_B1lo);
    cudaGetSymbolAddress((void**)&Bs1hi, g_Bs1hi);
    cudaGetSymbolAddress((void**)&Bs1lo, g_Bs1lo);
    cudaGetSymbolAddress((void**)&B2hi,  g_B2hi);
    cudaGetSymbolAddress((void**)&B2lo,  g_B2lo);
    cudaGetSymbolAddress((void**)&Bs2hi, g_Bs2hi);
    cudaGetSymbolAddress((void**)&Bs2lo, g_Bs2lo);

    const int SMEM_BN128 = 4 * 10240 + 4 * 128 * 40 * 2;  // 81920
    const int SMEM_BN64  = 4 * 10240 + 4 * 64 * 40 * 2;   // 61440
    cudaFuncSetAttribute(gemm_mma2<128>, cudaFuncAttributeMaxDynamicSharedMemorySize, SMEM_BN128);
    cudaFuncSetAttribute(gemm_mma2<64>,  cudaFuncAttributeMaxDynamicSharedMemorySize, SMEM_BN64);

    // launch order: big GEMM stays at index 3 (ncu capture slot)
    fold_kernel<<<1, 256>>>(W1s, W1d, a1s, a1d, b1, sk1b,
                            W2s, W2d, a2s, a2d, b2, sk2b);                       // 0
    prep_B<<<256, 256>>>(W1s, sk1W, W2s, sk2W);                                  // 1
    split_dot<4><<<CDIV(N0 * 32, 256), 256>>>(x, xhi, xlo, vS1, vD1,
                                              as1, ad1, N0, NT1C);               // 2
    gemm_mma2<128><<<dim3(2, CDIV(N0, 128)), 256, SMEM_BN128>>>(
        xhi, xlo, B1hi, B1lo, nullptr, xs1, N0, 256);                            // 3 (profiled)

    zero_counts<<<CDIV(NT1C, 256), 256>>>();                                     // 4
    count_both<<<CDIV(E1 + E2, 256), 256>>>(dst1, dst2, E1, E2);                 // 5
    scan_both<<<2, 1024>>>();                                                    // 6
    fill_both<<<CDIV(E1 + E2, 256), 256>>>(dst1, src1, dst2, src2, E1, E2);      // 7

    // --- layer 1 ---
    gemm_mma2<128><<<dim3(2, CDIV(NT1C, 128)), 256, SMEM_BN128>>>(
        xhi, xlo, Bs1hi, Bs1lo, comb1, hbuf, NT1C, 256);                         // 8
    gat_agg1<<<CDIV(NT1C * 32, 256), 256>>>();                                   // 9

    // --- layer 2 ---
    split_dot<1><<<CDIV(NT1C * 32, 256), 256>>>(hbuf, hhi, hlo, vS2, vD2,
                                                as2, ad2, NT1C, NT2C);           // 10
    gemm_mma2<64><<<dim3(1, CDIV(NT1C, 128)), 256, SMEM_BN64>>>(
        hhi, hlo, B2hi, B2lo, nullptr, xs2, NT1C, 64);                           // 11
    gemm_mma2<64><<<dim3(1, CDIV(NT2C, 128)), 256, SMEM_BN64>>>(
        hhi, hlo, Bs2hi, Bs2lo, comb2, obuf, NT2C, 64);                          // 12
    gat_agg2<<<CDIV(NT2C * 32, 256), 256>>>();                                   // 13

    // --- output ---
    logsoftmax_kernel<<<CDIV(NT2C * 32, 256), 256>>>((float*)d_out);             // 14
}

// round 14
// speedup vs baseline: 2.0169x; 1.0906x over previous
#include <cuda_runtime.h>
#include <cuda_fp16.h>
#include <cstdint>

#define CDIV(a,b) (((a)+(b)-1)/(b))

// ---------------- problem constants ----------------
#define KDIM   256
#define NT1C   25000
#define NT2C   5000
#define N0C    100000
#define E1CAP  400000
#define E2CAP  100000
#define NEG_SLOPE 0.2f

// ---------------- static scratch ----------------
__device__ float g_xs1[(size_t)N0C * 256];
__device__ float g_h  [(size_t)NT1C * 256];
__device__ float g_xs2[(size_t)NT1C * 64];
__device__ float g_o  [(size_t)NT2C * 64];
__device__ float g_as1[(size_t)N0C * 4];
__device__ float g_ad1[NT1C * 4];
__device__ float g_as2[NT1C];
__device__ float g_ad2[NT2C];
__device__ float g_vS1[4 * 256];
__device__ float g_vD1[4 * 256];
__device__ float g_vS2[256];
__device__ float g_vD2[256];
__device__ float g_comb1[256];
__device__ float g_comb2[64];
// fp16 hi/lo split planes (A operands); B matrices: hi plane only
__device__ unsigned short g_xhi[(size_t)N0C * 256];
__device__ unsigned short g_xlo[(size_t)N0C * 256];
__device__ unsigned short g_hhi[(size_t)NT1C * 256];
__device__ unsigned short g_hlo[(size_t)NT1C * 256];
__device__ unsigned short g_B1hi[256 * 256];
__device__ unsigned short g_Bs1hi[256 * 256];
__device__ unsigned short g_B2hi[64 * 256];
__device__ unsigned short g_Bs2hi[64 * 256];
__device__ int g_cnt1[NT1C];
__device__ int g_off1[NT1C + 1];
__device__ int g_cur1[NT1C];
__device__ int g_srcid1[E1CAP];
__device__ int g_cnt2[NT2C];
__device__ int g_off2[NT2C + 1];
__device__ int g_cur2[NT2C];
__device__ int g_srcid2[E2CAP];

// ---------------- helpers ----------------
__device__ __forceinline__ uint32_t smem_u32(const void* p) {
    uint32_t a;
    asm("{ .reg .u64 t; cvta.to.shared.u64 t, %1; cvt.u32.u64 %0, t; }" : "=r"(a) : "l"(p));
    return a;
}
// fp16 hi/lo split: hi+lo captures ~22 mantissa bits of the fp32 value
__device__ __forceinline__ void split1(float v, unsigned short& h, unsigned short& l) {
    __half hb = __float2half_rn(v);
    float hf = __half2float(hb);
    h = __half_as_ushort(hb);
    l = __half_as_ushort(__float2half_rn(v - hf));
}
__device__ __forceinline__ void mma_f16(float& c0, float& c1, float& c2, float& c3,
                                        uint32_t a0, uint32_t a1, uint32_t a2, uint32_t a3,
                                        uint32_t b0, uint32_t b1) {
    asm volatile(
        "mma.sync.aligned.m16n8k16.row.col.f32.f16.f16.f32 "
        "{%0,%1,%2,%3}, {%4,%5,%6,%7}, {%8,%9}, {%0,%1,%2,%3};"
        : "+f"(c0), "+f"(c1), "+f"(c2), "+f"(c3)
        : "r"(a0), "r"(a1), "r"(a2), "r"(a3), "r"(b0), "r"(b1));
}
#define LDSM4(r, a) \
    asm volatile("ldmatrix.sync.aligned.m8n8.x4.shared.b16 {%0,%1,%2,%3}, [%4];" \
        : "=r"((r)[0]), "=r"((r)[1]), "=r"((r)[2]), "=r"((r)[3]) : "r"(a))

// ---------------- fused split + attention dots (warp per row) ----------------
template <int H>
__global__ void split_dot(const float* __restrict__ X,
                          unsigned short* __restrict__ hi, unsigned short* __restrict__ lo,
                          const float* __restrict__ Vs, const float* __restrict__ Vd,
                          float* __restrict__ as_, float* __restrict__ ad_,
                          int M, int Mdst)
{
    int warp = (blockIdx.x * blockDim.x + threadIdx.x) >> 5;
    int lane = threadIdx.x & 31;
    if (warp >= M) return;
    const float* xr = X + (size_t)warp * 256 + lane * 8;
    float4 x0 = *(const float4*)xr;
    float4 x1 = *(const float4*)(xr + 4);
    float xv[8] = { x0.x, x0.y, x0.z, x0.w, x1.x, x1.y, x1.z, x1.w };

    unsigned short h8[8], l8[8];
    #pragma unroll
    for (int j = 0; j < 8; j++) split1(xv[j], h8[j], l8[j]);
    uint4 ph, pl;
    ph.x = (uint32_t)h8[0] | ((uint32_t)h8[1] << 16);
    ph.y = (uint32_t)h8[2] | ((uint32_t)h8[3] << 16);
    ph.z = (uint32_t)h8[4] | ((uint32_t)h8[5] << 16);
    ph.w = (uint32_t)h8[6] | ((uint32_t)h8[7] << 16);
    pl.x = (uint32_t)l8[0] | ((uint32_t)l8[1] << 16);
    pl.y = (uint32_t)l8[2] | ((uint32_t)l8[3] << 16);
    pl.z = (uint32_t)l8[4] | ((uint32_t)l8[5] << 16);
    pl.w = (uint32_t)l8[6] | ((uint32_t)l8[7] << 16);
    *(uint4*)(hi + (size_t)warp * 256 + lane * 8) = ph;
    *(uint4*)(lo + (size_t)warp * 256 + lane * 8) = pl;

    #pragma unroll
    for (int hh = 0; hh < H; hh++) {
        const float* vr = Vs + hh * 256 + lane * 8;
        float4 v0 = *(const float4*)vr;
        float4 v1 = *(const float4*)(vr + 4);
        float s = xv[0]*v0.x + xv[1]*v0.y + xv[2]*v0.z + xv[3]*v0.w +
                  xv[4]*v1.x + xv[5]*v1.y + xv[6]*v1.z + xv[7]*v1.w;
        #pragma unroll
        for (int o = 16; o; o >>= 1) s += __shfl_xor_sync(0xffffffffu, s, o);
        if (lane == hh) as_[(size_t)warp * H + hh] = s;
    }
    if (warp < Mdst) {
        #pragma unroll
        for (int hh = 0; hh < H; hh++) {
            const float* vr = Vd + hh * 256 + lane * 8;
            float4 v0 = *(const float4*)vr;
            float4 v1 = *(const float4*)(vr + 4);
            float s = xv[0]*v0.x + xv[1]*v0.y + xv[2]*v0.z + xv[3]*v0.w +
                      xv[4]*v1.x + xv[5]*v1.y + xv[6]*v1.z + xv[7]*v1.w;
            #pragma unroll
            for (int o = 16; o; o >>= 1) s += __shfl_xor_sync(0xffffffffu, s, o);
            if (lane == hh) ad_[(size_t)warp * H + hh] = s;
        }
    }
}

// ---------------- prep: transpose + fp16-round B matrices (hi only) ----------
__global__ void prep_B(const float* __restrict__ W1s, const float* __restrict__ sk1W,
                       const float* __restrict__ W2s, const float* __restrict__ sk2W)
{
    int k = blockIdx.x;    // 0..255
    int n = threadIdx.x;   // 0..255
    g_B1hi[n * 256 + k]  = __half_as_ushort(__float2half_rn(W1s[k * 256 + n]));
    g_Bs1hi[n * 256 + k] = __half_as_ushort(__float2half_rn(sk1W[k * 256 + n]));
    if (n < 64) {
        g_B2hi[n * 256 + k]  = __half_as_ushort(__float2half_rn(W2s[k * 64 + n]));
        g_Bs2hi[n * 256 + k] = __half_as_ushort(__float2half_rn(sk2W[k * 64 + n]));
    }
}

// ---------------- MMA GEMM: C[M,NDIM] = A[M,256] @ B^T (+bias) ---------------
// fp16 2-product split: (Ah + Al) * Bh. A hi/lo planes, B hi only.
// grid = (N-chunks, M-tiles), x-major: both N-halves of an A tile adjacent.
template <int BN>
__global__ __launch_bounds__(256, 2) void gemm_mma2(
    const unsigned short* __restrict__ Ahi, const unsigned short* __restrict__ Alo,
    const unsigned short* __restrict__ Bhi,
    const float* __restrict__ bias, float* __restrict__ C, int M, int NDIM)
{
    constexpr int P = 40;
    constexpr uint32_t APL = 128 * P * 2;          // 10240 B per A plane
    constexpr uint32_t BPL = (uint32_t)BN * P * 2; // B plane
    constexpr uint32_t AREG = 4 * APL;             // 2 bufs x 2 A planes
    constexpr int NT_N = BN / 16;
    constexpr int NPAIR = BN / 32;
    constexpr int BU = BN / 64;

    extern __shared__ char smem[];
    uint32_t sb = smem_u32(smem);
    uint32_t sbB = sb + AREG;

    int tid = threadIdx.x, lane = tid & 31, wid = tid >> 5;
    int wm = wid >> 1, wn = wid & 1;
    int g = lane >> 2, t = lane & 3;
    int bm0 = blockIdx.y * 128, bn0 = blockIdx.x * BN;

    int q8 = lane & 7, mm = lane >> 3;
    uint32_t aoff = (uint32_t)((wm * 32 + (mm & 1) * 8 + q8) * P * 2 + ((mm & 2) * 4) * 2);
    uint32_t boff = (uint32_t)((wn * (BN / 2) + ((mm >> 1) & 1) * 8 + q8) * P * 2 + ((mm & 1) * 8) * 2);

    float acc[2][NT_N][4];
    #pragma unroll
    for (int i = 0; i < 2; i++)
        #pragma unroll
        for (int j = 0; j < NT_N; j++)
            #pragma unroll
            for (int q = 0; q < 4; q++) acc[i][j][q] = 0.f;

    auto ld_stage = [&](int kt, int buf) {
        int k0 = kt * 32;
        #pragma unroll
        for (int pl = 0; pl < 2; pl++) {
            const unsigned short* Ap = pl ? Alo : Ahi;
            #pragma unroll
            for (int u = 0; u < 2; u++) {
                int c = tid + u * 256;
                int r = c >> 2, c4 = c & 3;
                int row = bm0 + r;
                const void* gp = Ap + (size_t)row * KDIM + k0 + c4 * 8;
                uint32_t dst = sb + (buf * 2 + pl) * APL + (uint32_t)(r * P * 2 + c4 * 16);
                int sz = (row < M) ? 16 : 0;
                asm volatile("cp.async.cg.shared.global [%0], [%1], 16, %2;"
                             :: "r"(dst), "l"(gp), "r"(sz));
            }
        }
        #pragma unroll
        for (int u = 0; u < BU; u++) {
            int c = tid + u * 256;
            int r = c >> 2, c4 = c & 3;
            const void* gp = Bhi + (size_t)(bn0 + r) * KDIM + k0 + c4 * 8;
            uint32_t dst = sbB + buf * BPL + (uint32_t)(r * P * 2 + c4 * 16);
            asm volatile("cp.async.cg.shared.global [%0], [%1], 16;"
                         :: "r"(dst), "l"(gp));
        }
        asm volatile("cp.async.commit_group;");
    };

    auto compute = [&](int buf) {
        #pragma unroll
        for (int kk = 0; kk < 32; kk += 16) {
            uint32_t ah[2][4], al[2][4];
            #pragma unroll
            for (int mt = 0; mt < 2; mt++) {
                uint32_t ad = sb + (buf * 2) * APL + aoff + (uint32_t)(mt * 16 * P * 2 + kk * 2);
                LDSM4(ah[mt], ad);
                LDSM4(al[mt], ad + APL);
            }
            uint32_t bh[NT_N][2];
            #pragma unroll
            for (int pr = 0; pr < NPAIR; pr++) {
                uint32_t bd = sbB + buf * BPL + boff + (uint32_t)(pr * 16 * P * 2 + kk * 2);
                uint32_t r4[4];
                LDSM4(r4, bd);
                bh[2 * pr][0] = r4[0]; bh[2 * pr][1] = r4[1];
                bh[2 * pr + 1][0] = r4[2]; bh[2 * pr + 1][1] = r4[3];
            }
            #pragma unroll
            for (int mt = 0; mt < 2; mt++)
                #pragma unroll
                for (int nt = 0; nt < NT_N; nt++) {
                    float* c = acc[mt][nt];
                    mma_f16(c[0], c[1], c[2], c[3],
                            ah[mt][0], ah[mt][1], ah[mt][2], ah[mt][3],
                            bh[nt][0], bh[nt][1]);
                    mma_f16(c[0], c[1], c[2], c[3],
                            al[mt][0], al[mt][1], al[mt][2], al[mt][3],
                            bh[nt][0], bh[nt][1]);
                }
        }
    };

    ld_stage(0, 0);
    asm volatile("cp.async.wait_group 0;");
    __syncthreads();
    int buf = 0;
    for (int kt = 0; kt < 8; kt++) {
        if (kt < 7) ld_stage(kt + 1, buf ^ 1);
        compute(buf);
        if (kt < 7) asm volatile("cp.async.wait_group 0;");
        __syncthreads();
        buf ^= 1;
    }

    #pragma unroll
    for (int nt = 0; nt < NT_N; nt++) {
        int cn = bn0 + wn * (BN / 2) + nt * 8 + t * 2;
        float2 bv = make_float2(0.f, 0.f);
        if (bias) bv = *(const float2*)(bias + cn);
        #pragma unroll
        for (int mt = 0; mt < 2; mt++) {
            int row0 = bm0 + wm * 32 + mt * 16 + g;
            float* c = acc[mt][nt];
            if (row0 < M) {
                float2 o = make_float2(c[0] + bv.x, c[1] + bv.y);
                *(float2*)(C + (size_t)row0 * NDIM + cn) = o;
            }
            if (row0 + 8 < M) {
                float2 o = make_float2(c[2] + bv.x, c[3] + bv.y);
                *(float2*)(C + (size_t)(row0 + 8) * NDIM + cn) = o;
            }
        }
    }
}

// ---------------- fold ----------------
__global__ void fold_kernel(const float* __restrict__ W1s, const float* __restrict__ W1d,
                            const float* __restrict__ a1s, const float* __restrict__ a1d,
                            const float* __restrict__ b1,  const float* __restrict__ s1b,
                            const float* __restrict__ W2s, const float* __restrict__ W2d,
                            const float* __restrict__ a2s, const float* __restrict__ a2d,
                            const float* __restrict__ b2,  const float* __restrict__ s2b)
{
    int k = threadIdx.x;
    #pragma unroll
    for (int h = 0; h < 4; h++) {
        float ss = 0.f, sd = 0.f;
        for (int d = 0; d < 64; d++) {
            ss += W1s[k * 256 + h * 64 + d] * a1s[h * 64 + d];
            sd += W1d[k * 256 + h * 64 + d] * a1d[h * 64 + d];
        }
        g_vS1[h * 256 + k] = ss;
        g_vD1[h * 256 + k] = sd;
    }
    float s2 = 0.f, d2 = 0.f;
    for (int d = 0; d < 64; d++) {
        s2 += W2s[k * 64 + d] * a2s[d];
        d2 += W2d[k * 64 + d] * a2d[d];
    }
    g_vS2[k] = s2;
    g_vD2[k] = d2;
    g_comb1[k] = b1[k] + s1b[k];
    if (k < 64) g_comb2[k] = b2[k] + s2b[k];
}

// ---------------- CSR build (merged kernels) ----------------
__global__ void zero_counts()
{
    int i = blockIdx.x * blockDim.x + threadIdx.x;
    if (i < NT1C) g_cnt1[i] = 0;
    if (i < NT2C) g_cnt2[i] = 0;
}

__global__ void count_both(const int* __restrict__ dst1, const int* __restrict__ dst2,
                           int E1, int E2)
{
    int e = blockIdx.x * blockDim.x + threadIdx.x;
    if (e < E1) atomicAdd(&g_cnt1[dst1[e]], 1);
    else if (e - E1 < E2) atomicAdd(&g_cnt2[dst2[e - E1]], 1);
}

__device__ void scan_impl(const int* __restrict__ cnt, int* __restrict__ off,
                          int* __restrict__ cur, int n)
{
    __shared__ int wpre[32];
    __shared__ int carry;
    int t = threadIdx.x, lane = t & 31, w = t >> 5;
    if (t == 0) { carry = 0; off[0] = 0; }
    __syncthreads();
    for (int base = 0; base < n; base += 1024) {
        int i = base + t;
        int v = (i < n) ? cnt[i] : 0;
        int x = v;
        #pragma unroll
        for (int d = 1; d < 32; d <<= 1) {
            int y = __shfl_up_sync(0xffffffffu, x, d);
            if (lane >= d) x += y;
        }
        if (lane == 31) wpre[w] = x;
        __syncthreads();
        if (w == 0) {
            int s = wpre[lane];
            #pragma unroll
            for (int d = 1; d < 32; d <<= 1) {
                int y = __shfl_up_sync(0xffffffffu, s, d);
                if (lane >= d) s += y;
            }
            wpre[lane] = s;
        }
        __syncthreads();
        int incl = x + (w ? wpre[w - 1] : 0) + carry;
        if (i < n) {
            off[i + 1] = incl;
            cur[i] = incl - v;
        }
        __syncthreads();
        if (t == 1023) carry = incl;
        __syncthreads();
    }
}

__global__ void scan_both()
{
    if (blockIdx.x == 0) scan_impl(g_cnt1, g_off1, g_cur1, NT1C);
    else                 scan_impl(g_cnt2, g_off2, g_cur2, NT2C);
}

__global__ void fill_both(const int* __restrict__ dst1, const int* __restrict__ src1,
                          const int* __restrict__ dst2, const int* __restrict__ src2,
                          int E1, int E2)
{
    int e = blockIdx.x * blockDim.x + threadIdx.x;
    if (e < E1) {
        int p = atomicAdd(&g_cur1[dst1[e]], 1);
        g_srcid1[p] = src1[e];
    } else if (e - E1 < E2) {
        int e2 = e - E1;
        int p = atomicAdd(&g_cur2[dst2[e2]], 1);
        g_srcid2[p] = src2[e2];
    }
}

// ---------------- layer 1 aggregation (pairwise online softmax) --------------
__global__ __launch_bounds__(256) void gat_agg1()
{
    int warp = (blockIdx.x * blockDim.x + threadIdx.x) >> 5;
    int lane = threadIdx.x & 31;
    if (warp >= NT1C) return;
    int myh = lane >> 3;
    float ad = g_ad1[warp * 4 + myh];
    int beg = g_off1[warp], end = g_off1[warp + 1];
    float m = -1e30f, s = 0.f;
    float acc[8];
    #pragma unroll
    for (int j = 0; j < 8; j++) acc[j] = 0.f;

    int i = beg;
    for (; i + 1 < end; i += 2) {
        int sa = g_srcid1[i], sb = g_srcid1[i + 1];
        float ea = g_as1[(size_t)sa * 4 + myh] + ad;
        float eb = g_as1[(size_t)sb * 4 + myh] + ad;
        ea = ea > 0.f ? ea : NEG_SLOPE * ea;
        eb = eb > 0.f ? eb : NEG_SLOPE * eb;
        const float4* pa = (const float4*)(g_xs1 + (size_t)sa * 256 + lane * 8);
        const float4* pb = (const float4*)(g_xs1 + (size_t)sb * 256 + lane * 8);
        float4 a0 = pa[0], a1 = pa[1];
        float4 b0 = pb[0], b1 = pb[1];
        float mp = fmaxf(ea, eb);
        float wa = __expf(ea - mp), wb = __expf(eb - mp);
        float nm = fmaxf(m, mp);
        float cm = __expf(m - nm), cp = __expf(mp - nm);
        s = s * cm + (wa + wb) * cp;
        float wap = wa * cp, wbp = wb * cp;
        acc[0] = acc[0] * cm + wap * a0.x + wbp * b0.x;
        acc[1] = acc[1] * cm + wap * a0.y + wbp * b0.y;
        acc[2] = acc[2] * cm + wap * a0.z + wbp * b0.z;
        acc[3] = acc[3] * cm + wap * a0.w + wbp * b0.w;
        acc[4] = acc[4] * cm + wap * a1.x + wbp * b1.x;
        acc[5] = acc[5] * cm + wap * a1.y + wbp * b1.y;
        acc[6] = acc[6] * cm + wap * a1.z + wbp * b1.z;
        acc[7] = acc[7] * cm + wap * a1.w + wbp * b1.w;
        m = nm;
    }
    if (i < end) {
        int sn = g_srcid1[i];
        float ev = g_as1[(size_t)sn * 4 + myh] + ad;
        ev = ev > 0.f ? ev : NEG_SLOPE * ev;
        float nm = fmaxf(m, ev);
        float corr = __expf(m - nm);
        float w = __expf(ev - nm);
        s = s * corr + w;
        const float4* r = (const float4*)(g_xs1 + (size_t)sn * 256 + lane * 8);
        float4 r0 = r[0], r1 = r[1];
        acc[0] = acc[0] * corr + w * r0.x;
        acc[1] = acc[1] * corr + w * r0.y;
        acc[2] = acc[2] * corr + w * r0.z;
        acc[3] = acc[3] * corr + w * r0.w;
        acc[4] = acc[4] * corr + w * r1.x;
        acc[5] = acc[5] * corr + w * r1.y;
        acc[6] = acc[6] * corr + w * r1.z;
        acc[7] = acc[7] * corr + w * r1.w;
        m = nm;
    }
    float inv = 1.f / (s + 1e-16f);
    float* hp = g_h + (size_t)warp * 256 + lane * 8;
    float4 h0 = ((float4*)hp)[0], h1 = ((float4*)hp)[1];
    float v[8];
    v[0] = acc[0] * inv + h0.x;  v[1] = acc[1] * inv + h0.y;
    v[2] = acc[2] * inv + h0.z;  v[3] = acc[3] * inv + h0.w;
    v[4] = acc[4] * inv + h1.x;  v[5] = acc[5] * inv + h1.y;
    v[6] = acc[6] * inv + h1.z;  v[7] = acc[7] * inv + h1.w;
    #pragma unroll
    for (int j = 0; j < 8; j++) v[j] = v[j] > 0.f ? v[j] : (__expf(v[j]) - 1.f);
    ((float4*)hp)[0] = make_float4(v[0], v[1], v[2], v[3]);
    ((float4*)hp)[1] = make_float4(v[4], v[5], v[6], v[7]);
}

// ---------------- layer 2 aggregation (pairwise) ----------------
__global__ __launch_bounds__(256) void gat_agg2()
{
    int warp = (blockIdx.x * blockDim.x + threadIdx.x) >> 5;
    int lane = threadIdx.x & 31;
    if (warp >= NT2C) return;
    float ad = g_ad2[warp];
    int beg = g_off2[warp], end = g_off2[warp + 1];
    float m = -1e30f, s = 0.f, a0 = 0.f, a1 = 0.f;
    int i = beg;
    for (; i + 1 < end; i += 2) {
        int sa = g_srcid2[i], sb = g_srcid2[i + 1];
        float ea = g_as2[sa] + ad;
        float eb = g_as2[sb] + ad;
        ea = ea > 0.f ? ea : NEG_SLOPE * ea;
        eb = eb > 0.f ? eb : NEG_SLOPE * eb;
        float2 ra = *(const float2*)(g_xs2 + (size_t)sa * 64 + lane * 2);
        float2 rb = *(const float2*)(g_xs2 + (size_t)sb * 64 + lane * 2);
        float mp = fmaxf(ea, eb);
        float wa = __expf(ea - mp), wb = __expf(eb - mp);
        float nm = fmaxf(m, mp);
        float cm = __expf(m - nm), cp = __expf(mp - nm);
        s = s * cm + (wa + wb) * cp;
        float wap = wa * cp, wbp = wb * cp;
        a0 = a0 * cm + wap * ra.x + wbp * rb.x;
        a1 = a1 * cm + wap * ra.y + wbp * rb.y;
        m = nm;
    }
    if (i < end) {
        int sn = g_srcid2[i];
        float ev = g_as2[sn] + ad;
        ev = ev > 0.f ? ev : NEG_SLOPE * ev;
        float nm = fmaxf(m, ev);
        float corr = __expf(m - nm);
        float w = __expf(ev - nm);
        s = s * corr + w;
        float2 r = *(const float2*)(g_xs2 + (size_t)sn * 64 + lane * 2);
        a0 = a0 * corr + w * r.x;
        a1 = a1 * corr + w * r.y;
        m = nm;
    }
    float inv = 1.f / (s + 1e-16f);
    float2* op = (float2*)(g_o + (size_t)warp * 64 + lane * 2);
    float2 o = *op;
    o.x += a0 * inv;
    o.y += a1 * inv;
    *op = o;
}

// ---------------- log_softmax ----------------
__global__ void logsoftmax_kernel(float* __restrict__ out)
{
    int warp = (blockIdx.x * blockDim.x + threadIdx.x) >> 5;
    int lane = threadIdx.x & 31;
    if (warp >= NT2C) return;
    float2 v = *(const float2*)(g_o + (size_t)warp * 64 + lane * 2);
    float mx = fmaxf(v.x, v.y);
    #pragma unroll
    for (int o = 16; o; o >>= 1) mx = fmaxf(mx, __shfl_xor_sync(0xffffffffu, mx, o));
    float se = __expf(v.x - mx) + __expf(v.y - mx);
    #pragma unroll
    for (int o = 16; o; o >>= 1) se += __shfl_xor_sync(0xffffffffu, se, o);
    float l = mx + logf(se);
    float2 r;
    r.x = v.x - l;
    r.y = v.y - l;
    *(float2*)(out + (size_t)warp * 64 + lane * 2) = r;
}

// ---------------- host launcher ----------------
extern "C" void kernel_launch(void* const* d_in, const int* in_sizes, int n_in,
                              void* d_out, int out_size)
{
    const float* x    = (const float*)d_in[0];
    const int*   src1 = (const int*)d_in[1];
    const int*   dst1 = (const int*)d_in[2];
    const int*   src2 = (const int*)d_in[3];
    const int*   dst2 = (const int*)d_in[4];
    const float* W1s  = (const float*)d_in[7];
    const float* W1d  = (const float*)d_in[8];
    const float* a1s  = (const float*)d_in[9];
    const float* a1d  = (const float*)d_in[10];
    const float* b1   = (const float*)d_in[11];
    const float* sk1W = (const float*)d_in[12];
    const float* sk1b = (const float*)d_in[13];
    const float* W2s  = (const float*)d_in[14];
    const float* W2d  = (const float*)d_in[15];
    const float* a2s  = (const float*)d_in[16];
    const float* a2d  = (const float*)d_in[17];
    const float* b2   = (const float*)d_in[18];
    const float* sk2W = (const float*)d_in[19];
    const float* sk2b = (const float*)d_in[20];

    int N0 = in_sizes[0] / KDIM;
    int E1 = in_sizes[1];
    int E2 = in_sizes[3];

    float *xs1, *hbuf, *xs2, *obuf, *as1, *ad1, *as2, *ad2;
    float *vS1, *vD1, *vS2, *vD2, *comb1, *comb2;
    unsigned short *xhi, *xlo, *hhi, *hlo;
    unsigned short *B1hi, *Bs1hi, *B2hi, *Bs2hi;
    cudaGetSymbolAddress((void**)&xs1,  g_xs1);
    cudaGetSymbolAddress((void**)&hbuf, g_h);
    cudaGetSymbolAddress((void**)&xs2,  g_xs2);
    cudaGetSymbolAddress((void**)&obuf, g_o);
    cudaGetSymbolAddress((void**)&as1,  g_as1);
    cudaGetSymbolAddress((void**)&ad1,  g_ad1);
    cudaGetSymbolAddress((void**)&as2,  g_as2);
    cudaGetSymbolAddress((void**)&ad2,  g_ad2);
    cudaGetSymbolAddress((void**)&vS1,  g_vS1);
    cudaGetSymbolAddress((void**)&vD1,  g_vD1);
    cudaGetSymbolAddress((void**)&vS2,  g_vS2);
    cudaGetSymbolAddress((void**)&vD2,  g_vD2);
    cudaGetSymbolAddress((void**)&comb1, g_comb1);
    cudaGetSymbolAddress((void**)&comb2, g_comb2);
    cudaGetSymbolAddress((void**)&xhi,  g_xhi);
    cudaGetSymbolAddress((void**)&xlo,  g_xlo);
    cudaGetSymbolAddress((void**)&hhi,  g_hhi);
    cudaGetSymbolAddress((void**)&hlo,  g_hlo);
    cudaGetSymbolAddress((void**)&B1hi,  g_B1hi);
    cudaGetSymbolAddress((void**)&Bs1hi, g_Bs1hi);
    cudaGetSymbolAddress((void**)&B2hi,  g_B2hi);
    cudaGetSymbolAddress((void**)&Bs2hi, g_Bs2hi);

    const int SMEM_BN128 = 4 * 10240 + 2 * 10240;  // 61440
    const int SMEM_BN64  = 4 * 10240 + 2 * 5120;   // 51200
    cudaFuncSetAttribute(gemm_mma2<128>, cudaFuncAttributeMaxDynamicSharedMemorySize, SMEM_BN128);
    cudaFuncSetAttribute(gemm_mma2<64>,  cudaFuncAttributeMaxDynamicSharedMemorySize, SMEM_BN64);

    // launch order: big GEMM stays at index 3 (ncu capture slot)
    fold_kernel<<<1, 256>>>(W1s, W1d, a1s, a1d, b1, sk1b,
                            W2s, W2d, a2s, a2d, b2, sk2b);                       // 0
    prep_B<<<256, 256>>>(W1s, sk1W, W2s, sk2W);                                  // 1
    split_dot<4><<<CDIV(N0 * 32, 256), 256>>>(x, xhi, xlo, vS1, vD1,
                                              as1, ad1, N0, NT1C);               // 2
    gemm_mma2<128><<<dim3(2, CDIV(N0, 128)), 256, SMEM_BN128>>>(
        xhi, xlo, B1hi, nullptr, xs1, N0, 256);                                  // 3 (profiled)

    zero_counts<<<CDIV(NT1C, 256), 256>>>();                                     // 4
    count_both<<<CDIV(E1 + E2, 256), 256>>>(dst1, dst2, E1, E2);                 // 5
    scan_both<<<2, 1024>>>();                                                    // 6
    fill_both<<<CDIV(E1 + E2, 256), 256>>>(dst1, src1, dst2, src2, E1, E2);      // 7

    // --- layer 1 ---
    gemm_mma2<128><<<dim3(2, CDIV(NT1C, 128)), 256, SMEM_BN128>>>(
        xhi, xlo, Bs1hi, comb1, hbuf, NT1C, 256);                                // 8
    gat_agg1<<<CDIV(NT1C * 32, 256), 256>>>();                                   // 9

    // --- layer 2 ---
    split_dot<1><<<CDIV(NT1C * 32, 256), 256>>>(hbuf, hhi, hlo, vS2, vD2,
                                                as2, ad2, NT1C, NT2C);           // 10
    gemm_mma2<64><<<dim3(1, CDIV(NT1C, 128)), 256, SMEM_BN64>>>(
        hhi, hlo, B2hi, nullptr, xs2, NT1C, 64);                                 // 11
    gemm_mma2<64><<<dim3(1, CDIV(NT2C, 128)), 256, SMEM_BN64>>>(
        hhi, hlo, Bs2hi, comb2, obuf, NT2C, 64);                                 // 12
    gat_agg2<<<CDIV(NT2C * 32, 256), 256>>>();                                   // 13

    // --- output ---
    logsoftmax_kernel<<<CDIV(NT2C * 32, 256), 256>>>((float*)d_out);             // 14
}

// round 15
// speedup vs baseline: 2.0965x; 1.0395x over previous
#include <cuda_runtime.h>
#include <cuda_fp16.h>
#include <cstdint>

#define CDIV(a,b) (((a)+(b)-1)/(b))

// ---------------- problem constants ----------------
#define KDIM   256
#define NT1C   25000
#define NT2C   5000
#define N0C    100000
#define E1CAP  400000
#define E2CAP  100000
#define NEG_SLOPE 0.2f

// ---------------- static scratch ----------------
__device__ float g_xs1[(size_t)N0C * 256];
__device__ float g_h  [(size_t)NT1C * 256];
__device__ float g_xs2[(size_t)NT1C * 64];
__device__ float g_o  [(size_t)NT2C * 64];
__device__ float g_as1[(size_t)N0C * 4];
__device__ float g_ad1[NT1C * 4];
__device__ float g_as2[NT1C];
__device__ float g_ad2[NT2C];
__device__ float g_vS1[4 * 256];
__device__ float g_vD1[4 * 256];
__device__ float g_vS2[256];
__device__ float g_vD2[256];
__device__ float g_comb1[256];
__device__ float g_comb2[64];
// fp16 hi/lo split planes (A operands); B matrices: hi plane only
__device__ unsigned short g_xhi[(size_t)N0C * 256];
__device__ unsigned short g_xlo[(size_t)N0C * 256];
__device__ unsigned short g_hhi[(size_t)NT1C * 256];
__device__ unsigned short g_hlo[(size_t)NT1C * 256];
__device__ unsigned short g_B1hi[256 * 256];
__device__ unsigned short g_Bs1hi[256 * 256];
__device__ unsigned short g_B2hi[64 * 256];
__device__ unsigned short g_Bs2hi[64 * 256];
__device__ int g_cnt1[NT1C];
__device__ int g_off1[NT1C + 1];
__device__ int g_cur1[NT1C];
__device__ int g_srcid1[E1CAP];
__device__ int g_cnt2[NT2C];
__device__ int g_off2[NT2C + 1];
__device__ int g_cur2[NT2C];
__device__ int g_srcid2[E2CAP];

// ---------------- helpers ----------------
__device__ __forceinline__ uint32_t smem_u32(const void* p) {
    uint32_t a;
    asm("{ .reg .u64 t; cvta.to.shared.u64 t, %1; cvt.u32.u64 %0, t; }" : "=r"(a) : "l"(p));
    return a;
}
__device__ __forceinline__ void split1(float v, unsigned short& h, unsigned short& l) {
    __half hb = __float2half_rn(v);
    float hf = __half2float(hb);
    h = __half_as_ushort(hb);
    l = __half_as_ushort(__float2half_rn(v - hf));
}
__device__ __forceinline__ void mma_f16(float& c0, float& c1, float& c2, float& c3,
                                        uint32_t a0, uint32_t a1, uint32_t a2, uint32_t a3,
                                        uint32_t b0, uint32_t b1) {
    asm volatile(
        "mma.sync.aligned.m16n8k16.row.col.f32.f16.f16.f32 "
        "{%0,%1,%2,%3}, {%4,%5,%6,%7}, {%8,%9}, {%0,%1,%2,%3};"
        : "+f"(c0), "+f"(c1), "+f"(c2), "+f"(c3)
        : "r"(a0), "r"(a1), "r"(a2), "r"(a3), "r"(b0), "r"(b1));
}
#define LDSM4(r, a) \
    asm volatile("ldmatrix.sync.aligned.m8n8.x4.shared.b16 {%0,%1,%2,%3}, [%4];" \
        : "=r"((r)[0]), "=r"((r)[1]), "=r"((r)[2]), "=r"((r)[3]) : "r"(a))

// ---------------- fused split + attention dots (warp per row) ----------------
template <int H>
__global__ void split_dot(const float* __restrict__ X,
                          unsigned short* __restrict__ hi, unsigned short* __restrict__ lo,
                          const float* __restrict__ Vs, const float* __restrict__ Vd,
                          float* __restrict__ as_, float* __restrict__ ad_,
                          int M, int Mdst)
{
    int warp = (blockIdx.x * blockDim.x + threadIdx.x) >> 5;
    int lane = threadIdx.x & 31;
    if (warp >= M) return;
    const float* xr = X + (size_t)warp * 256 + lane * 8;
    float4 x0 = *(const float4*)xr;
    float4 x1 = *(const float4*)(xr + 4);
    float xv[8] = { x0.x, x0.y, x0.z, x0.w, x1.x, x1.y, x1.z, x1.w };

    unsigned short h8[8], l8[8];
    #pragma unroll
    for (int j = 0; j < 8; j++) split1(xv[j], h8[j], l8[j]);
    uint4 ph, pl;
    ph.x = (uint32_t)h8[0] | ((uint32_t)h8[1] << 16);
    ph.y = (uint32_t)h8[2] | ((uint32_t)h8[3] << 16);
    ph.z = (uint32_t)h8[4] | ((uint32_t)h8[5] << 16);
    ph.w = (uint32_t)h8[6] | ((uint32_t)h8[7] << 16);
    pl.x = (uint32_t)l8[0] | ((uint32_t)l8[1] << 16);
    pl.y = (uint32_t)l8[2] | ((uint32_t)l8[3] << 16);
    pl.z = (uint32_t)l8[4] | ((uint32_t)l8[5] << 16);
    pl.w = (uint32_t)l8[6] | ((uint32_t)l8[7] << 16);
    *(uint4*)(hi + (size_t)warp * 256 + lane * 8) = ph;
    *(uint4*)(lo + (size_t)warp * 256 + lane * 8) = pl;

    #pragma unroll
    for (int hh = 0; hh < H; hh++) {
        const float* vr = Vs + hh * 256 + lane * 8;
        float4 v0 = *(const float4*)vr;
        float4 v1 = *(const float4*)(vr + 4);
        float s = xv[0]*v0.x + xv[1]*v0.y + xv[2]*v0.z + xv[3]*v0.w +
                  xv[4]*v1.x + xv[5]*v1.y + xv[6]*v1.z + xv[7]*v1.w;
        #pragma unroll
        for (int o = 16; o; o >>= 1) s += __shfl_xor_sync(0xffffffffu, s, o);
        if (lane == hh) as_[(size_t)warp * H + hh] = s;
    }
    if (warp < Mdst) {
        #pragma unroll
        for (int hh = 0; hh < H; hh++) {
            const float* vr = Vd + hh * 256 + lane * 8;
            float4 v0 = *(const float4*)vr;
            float4 v1 = *(const float4*)(vr + 4);
            float s = xv[0]*v0.x + xv[1]*v0.y + xv[2]*v0.z + xv[3]*v0.w +
                      xv[4]*v1.x + xv[5]*v1.y + xv[6]*v1.z + xv[7]*v1.w;
            #pragma unroll
            for (int o = 16; o; o >>= 1) s += __shfl_xor_sync(0xffffffffu, s, o);
            if (lane == hh) ad_[(size_t)warp * H + hh] = s;
        }
    }
}

// ---------------- prep: transpose + fp16-round B matrices (hi only) ----------
__global__ void prep_B(const float* __restrict__ W1s, const float* __restrict__ sk1W,
                       const float* __restrict__ W2s, const float* __restrict__ sk2W)
{
    int k = blockIdx.x;    // 0..255
    int n = threadIdx.x;   // 0..255
    g_B1hi[n * 256 + k]  = __half_as_ushort(__float2half_rn(W1s[k * 256 + n]));
    g_Bs1hi[n * 256 + k] = __half_as_ushort(__float2half_rn(sk1W[k * 256 + n]));
    if (n < 64) {
        g_B2hi[n * 256 + k]  = __half_as_ushort(__float2half_rn(W2s[k * 64 + n]));
        g_Bs2hi[n * 256 + k] = __half_as_ushort(__float2half_rn(sk2W[k * 64 + n]));
    }
}

// ---------------- MMA GEMM: C[M,NDIM] = A[M,256] @ B^T (+bias) ---------------
// fp16 2-product split: (Ah + Al) * Bh. 3-stage cp.async ring (one stage always
// in flight). grid = (N-chunks, M-tiles), x-major for A L2 reuse.
template <int BN>
__global__ __launch_bounds__(256, 2) void gemm_mma2(
    const unsigned short* __restrict__ Ahi, const unsigned short* __restrict__ Alo,
    const unsigned short* __restrict__ Bhi,
    const float* __restrict__ bias, float* __restrict__ C, int M, int NDIM)
{
    constexpr int P = 40;
    constexpr uint32_t APL = 128 * P * 2;          // 10240 B per A plane
    constexpr uint32_t BPL = (uint32_t)BN * P * 2; // B plane
    constexpr uint32_t AREG = 6 * APL;             // 3 bufs x 2 A planes
    constexpr int NT_N = BN / 16;
    constexpr int NPAIR = BN / 32;
    constexpr int BU = BN / 64;

    extern __shared__ char smem[];
    uint32_t sb = smem_u32(smem);
    uint32_t sbB = sb + AREG;

    int tid = threadIdx.x, lane = tid & 31, wid = tid >> 5;
    int wm = wid >> 1, wn = wid & 1;
    int g = lane >> 2, t = lane & 3;
    int bm0 = blockIdx.y * 128, bn0 = blockIdx.x * BN;

    int q8 = lane & 7, mm = lane >> 3;
    uint32_t aoff = (uint32_t)((wm * 32 + (mm & 1) * 8 + q8) * P * 2 + ((mm & 2) * 4) * 2);
    uint32_t boff = (uint32_t)((wn * (BN / 2) + ((mm >> 1) & 1) * 8 + q8) * P * 2 + ((mm & 1) * 8) * 2);

    float acc[2][NT_N][4];
    #pragma unroll
    for (int i = 0; i < 2; i++)
        #pragma unroll
        for (int j = 0; j < NT_N; j++)
            #pragma unroll
            for (int q = 0; q < 4; q++) acc[i][j][q] = 0.f;

    auto ld_stage = [&](int kt, int buf) {
        int k0 = kt * 32;
        #pragma unroll
        for (int pl = 0; pl < 2; pl++) {
            const unsigned short* Ap = pl ? Alo : Ahi;
            #pragma unroll
            for (int u = 0; u < 2; u++) {
                int c = tid + u * 256;
                int r = c >> 2, c4 = c & 3;
                int row = bm0 + r;
                const void* gp = Ap + (size_t)row * KDIM + k0 + c4 * 8;
                uint32_t dst = sb + (uint32_t)(buf * 2 + pl) * APL + (uint32_t)(r * P * 2 + c4 * 16);
                int sz = (row < M) ? 16 : 0;
                asm volatile("cp.async.cg.shared.global [%0], [%1], 16, %2;"
                             :: "r"(dst), "l"(gp), "r"(sz));
            }
        }
        #pragma unroll
        for (int u = 0; u < BU; u++) {
            int c = tid + u * 256;
            int r = c >> 2, c4 = c & 3;
            const void* gp = Bhi + (size_t)(bn0 + r) * KDIM + k0 + c4 * 8;
            uint32_t dst = sbB + (uint32_t)buf * BPL + (uint32_t)(r * P * 2 + c4 * 16);
            asm volatile("cp.async.cg.shared.global [%0], [%1], 16;"
                         :: "r"(dst), "l"(gp));
        }
        asm volatile("cp.async.commit_group;");
    };

    auto compute = [&](int buf) {
        #pragma unroll
        for (int kk = 0; kk < 32; kk += 16) {
            uint32_t ah[2][4], al[2][4];
            #pragma unroll
            for (int mt = 0; mt < 2; mt++) {
                uint32_t ad = sb + (uint32_t)(buf * 2) * APL + aoff + (uint32_t)(mt * 16 * P * 2 + kk * 2);
                LDSM4(ah[mt], ad);
                LDSM4(al[mt], ad + APL);
            }
            uint32_t bh[NT_N][2];
            #pragma unroll
            for (int pr = 0; pr < NPAIR; pr++) {
                uint32_t bd = sbB + (uint32_t)buf * BPL + boff + (uint32_t)(pr * 16 * P * 2 + kk * 2);
                uint32_t r4[4];
                LDSM4(r4, bd);
                bh[2 * pr][0] = r4[0]; bh[2 * pr][1] = r4[1];
                bh[2 * pr + 1][0] = r4[2]; bh[2 * pr + 1][1] = r4[3];
            }
            #pragma unroll
            for (int mt = 0; mt < 2; mt++)
                #pragma unroll
                for (int nt = 0; nt < NT_N; nt++) {
                    float* c = acc[mt][nt];
                    mma_f16(c[0], c[1], c[2], c[3],
                            ah[mt][0], ah[mt][1], ah[mt][2], ah[mt][3],
                            bh[nt][0], bh[nt][1]);
                    mma_f16(c[0], c[1], c[2], c[3],
                            al[mt][0], al[mt][1], al[mt][2], al[mt][3],
                            bh[nt][0], bh[nt][1]);
                }
        }
    };

    // 3-stage ring: one stage always in flight behind the one being computed
    ld_stage(0, 0);
    ld_stage(1, 1);
    #pragma unroll 1
    for (int kt = 0; kt < 8; kt++) {
        if (kt < 7) asm volatile("cp.async.wait_group 1;");
        else        asm volatile("cp.async.wait_group 0;");
        __syncthreads();
        if (kt + 2 < 8) ld_stage(kt + 2, (kt + 2) % 3);
        compute(kt % 3);
    }

    #pragma unroll
    for (int nt = 0; nt < NT_N; nt++) {
        int cn = bn0 + wn * (BN / 2) + nt * 8 + t * 2;
        float2 bv = make_float2(0.f, 0.f);
        if (bias) bv = *(const float2*)(bias + cn);
        #pragma unroll
        for (int mt = 0; mt < 2; mt++) {
            int row0 = bm0 + wm * 32 + mt * 16 + g;
            float* c = acc[mt][nt];
            if (row0 < M) {
                float2 o = make_float2(c[0] + bv.x, c[1] + bv.y);
                *(float2*)(C + (size_t)row0 * NDIM + cn) = o;
            }
            if (row0 + 8 < M) {
                float2 o = make_float2(c[2] + bv.x, c[3] + bv.y);
                *(float2*)(C + (size_t)(row0 + 8) * NDIM + cn) = o;
            }
        }
    }
}

// ---------------- fold ----------------
__global__ void fold_kernel(const float* __restrict__ W1s, const float* __restrict__ W1d,
                            const float* __restrict__ a1s, const float* __restrict__ a1d,
                            const float* __restrict__ b1,  const float* __restrict__ s1b,
                            const float* __restrict__ W2s, const float* __restrict__ W2d,
                            const float* __restrict__ a2s, const float* __restrict__ a2d,
                            const float* __restrict__ b2,  const float* __restrict__ s2b)
{
    int k = threadIdx.x;
    #pragma unroll
    for (int h = 0; h < 4; h++) {
        float ss = 0.f, sd = 0.f;
        for (int d = 0; d < 64; d++) {
            ss += W1s[k * 256 + h * 64 + d] * a1s[h * 64 + d];
            sd += W1d[k * 256 + h * 64 + d] * a1d[h * 64 + d];
        }
        g_vS1[h * 256 + k] = ss;
        g_vD1[h * 256 + k] = sd;
    }
    float s2 = 0.f, d2 = 0.f;
    for (int d = 0; d < 64; d++) {
        s2 += W2s[k * 64 + d] * a2s[d];
        d2 += W2d[k * 64 + d] * a2d[d];
    }
    g_vS2[k] = s2;
    g_vD2[k] = d2;
    g_comb1[k] = b1[k] + s1b[k];
    if (k < 64) g_comb2[k] = b2[k] + s2b[k];
}

// ---------------- CSR build (merged kernels) ----------------
__global__ void zero_counts()
{
    int i = blockIdx.x * blockDim.x + threadIdx.x;
    if (i < NT1C) g_cnt1[i] = 0;
    if (i < NT2C) g_cnt2[i] = 0;
}

__global__ void count_both(const int* __restrict__ dst1, const int* __restrict__ dst2,
                           int E1, int E2)
{
    int e = blockIdx.x * blockDim.x + threadIdx.x;
    if (e < E1) atomicAdd(&g_cnt1[dst1[e]], 1);
    else if (e - E1 < E2) atomicAdd(&g_cnt2[dst2[e - E1]], 1);
}

__device__ void scan_impl(const int* __restrict__ cnt, int* __restrict__ off,
                          int* __restrict__ cur, int n)
{
    __shared__ int wpre[32];
    __shared__ int carry;
    int t = threadIdx.x, lane = t & 31, w = t >> 5;
    if (t == 0) { carry = 0; off[0] = 0; }
    __syncthreads();
    for (int base = 0; base < n; base += 1024) {
        int i = base + t;
        int v = (i < n) ? cnt[i] : 0;
        int x = v;
        #pragma unroll
        for (int d = 1; d < 32; d <<= 1) {
            int y = __shfl_up_sync(0xffffffffu, x, d);
            if (lane >= d) x += y;
        }
        if (lane == 31) wpre[w] = x;
        __syncthreads();
        if (w == 0) {
            int s = wpre[lane];
            #pragma unroll
            for (int d = 1; d < 32; d <<= 1) {
                int y = __shfl_up_sync(0xffffffffu, s, d);
                if (lane >= d) s += y;
            }
            wpre[lane] = s;
        }
        __syncthreads();
        int incl = x + (w ? wpre[w - 1] : 0) + carry;
        if (i < n) {
            off[i + 1] = incl;
            cur[i] = incl - v;
        }
        __syncthreads();
        if (t == 1023) carry = incl;
        __syncthreads();
    }
}

__global__ void scan_both()
{
    if (blockIdx.x == 0) scan_impl(g_cnt1, g_off1, g_cur1, NT1C);
    else                 scan_impl(g_cnt2, g_off2, g_cur2, NT2C);
}

__global__ void fill_both(const int* __restrict__ dst1, const int* __restrict__ src1,
                          const int* __restrict__ dst2, const int* __restrict__ src2,
                          int E1, int E2)
{
    int e = blockIdx.x * blockDim.x + threadIdx.x;
    if (e < E1) {
        int p = atomicAdd(&g_cur1[dst1[e]], 1);
        g_srcid1[p] = src1[e];
    } else if (e - E1 < E2) {
        int e2 = e - E1;
        int p = atomicAdd(&g_cur2[dst2[e2]], 1);
        g_srcid2[p] = src2[e2];
    }
}

// ---------------- layer 1 aggregation (pairwise online softmax) --------------
__global__ __launch_bounds__(256) void gat_agg1()
{
    int warp = (blockIdx.x * blockDim.x + threadIdx.x) >> 5;
    int lane = threadIdx.x & 31;
    if (warp >= NT1C) return;
    int myh = lane >> 3;
    float ad = g_ad1[warp * 4 + myh];
    int beg = g_off1[warp], end = g_off1[warp + 1];
    float m = -1e30f, s = 0.f;
    float acc[8];
    #pragma unroll
    for (int j = 0; j < 8; j++) acc[j] = 0.f;

    int i = beg;
    for (; i + 1 < end; i += 2) {
        int sa = g_srcid1[i], sb = g_srcid1[i + 1];
        float ea = g_as1[(size_t)sa * 4 + myh] + ad;
        float eb = g_as1[(size_t)sb * 4 + myh] + ad;
        ea = ea > 0.f ? ea : NEG_SLOPE * ea;
        eb = eb > 0.f ? eb : NEG_SLOPE * eb;
        const float4* pa = (const float4*)(g_xs1 + (size_t)sa * 256 + lane * 8);
        const float4* pb = (const float4*)(g_xs1 + (size_t)sb * 256 + lane * 8);
        float4 a0 = pa[0], a1 = pa[1];
        float4 b0 = pb[0], b1 = pb[1];
        float mp = fmaxf(ea, eb);
        float wa = __expf(ea - mp), wb = __expf(eb - mp);
        float nm = fmaxf(m, mp);
        float cm = __expf(m - nm), cp = __expf(mp - nm);
        s = s * cm + (wa + wb) * cp;
        float wap = wa * cp, wbp = wb * cp;
        acc[0] = acc[0] * cm + wap * a0.x + wbp * b0.x;
        acc[1] = acc[1] * cm + wap * a0.y + wbp * b0.y;
        acc[2] = acc[2] * cm + wap * a0.z + wbp * b0.z;
        acc[3] = acc[3] * cm + wap * a0.w + wbp * b0.w;
        acc[4] = acc[4] * cm + wap * a1.x + wbp * b1.x;
        acc[5] = acc[5] * cm + wap * a1.y + wbp * b1.y;
        acc[6] = acc[6] * cm + wap * a1.z + wbp * b1.z;
        acc[7] = acc[7] * cm + wap * a1.w + wbp * b1.w;
        m = nm;
    }
    if (i < end) {
        int sn = g_srcid1[i];
        float ev = g_as1[(size_t)sn * 4 + myh] + ad;
        ev = ev > 0.f ? ev : NEG_SLOPE * ev;
        float nm = fmaxf(m, ev);
        float corr = __expf(m - nm);
        float w = __expf(ev - nm);
        s = s * corr + w;
        const float4* r = (const float4*)(g_xs1 + (size_t)sn * 256 + lane * 8);
        float4 r0 = r[0], r1 = r[1];
        acc[0] = acc[0] * corr + w * r0.x;
        acc[1] = acc[1] * corr + w * r0.y;
        acc[2] = acc[2] * corr + w * r0.z;
        acc[3] = acc[3] * corr + w * r0.w;
        acc[4] = acc[4] * corr + w * r1.x;
        acc[5] = acc[5] * corr + w * r1.y;
        acc[6] = acc[6] * corr + w * r1.z;
        acc[7] = acc[7] * corr + w * r1.w;
        m = nm;
    }
    float inv = 1.f / (s + 1e-16f);
    float* hp = g_h + (size_t)warp * 256 + lane * 8;
    float4 h0 = ((float4*)hp)[0], h1 = ((float4*)hp)[1];
    float v[8];
    v[0] = acc[0] * inv + h0.x;  v[1] = acc[1] * inv + h0.y;
    v[2] = acc[2] * inv + h0.z;  v[3] = acc[3] * inv + h0.w;
    v[4] = acc[4] * inv + h1.x;  v[5] = acc[5] * inv + h1.y;
    v[6] = acc[6] * inv + h1.z;  v[7] = acc[7] * inv + h1.w;
    #pragma unroll
    for (int j = 0; j < 8; j++) v[j] = v[j] > 0.f ? v[j] : (__expf(v[j]) - 1.f);
    ((float4*)hp)[0] = make_float4(v[0], v[1], v[2], v[3]);
    ((float4*)hp)[1] = make_float4(v[4], v[5], v[6], v[7]);
}

// ---------- layer 2 aggregation (pairwise) + fused log_softmax ----------
__global__ __launch_bounds__(256) void gat_agg2_lsm(float* __restrict__ out)
{
    int warp = (blockIdx.x * blockDim.x + threadIdx.x) >> 5;
    int lane = threadIdx.x & 31;
    if (warp >= NT2C) return;
    float ad = g_ad2[warp];
    int beg = g_off2[warp], end = g_off2[warp + 1];
    float m = -1e30f, s = 0.f, a0 = 0.f, a1 = 0.f;
    int i = beg;
    for (; i + 1 < end; i += 2) {
        int sa = g_srcid2[i], sb = g_srcid2[i + 1];
        float ea = g_as2[sa] + ad;
        float eb = g_as2[sb] + ad;
        ea = ea > 0.f ? ea : NEG_SLOPE * ea;
        eb = eb > 0.f ? eb : NEG_SLOPE * eb;
        float2 ra = *(const float2*)(g_xs2 + (size_t)sa * 64 + lane * 2);
        float2 rb = *(const float2*)(g_xs2 + (size_t)sb * 64 + lane * 2);
        float mp = fmaxf(ea, eb);
        float wa = __expf(ea - mp), wb = __expf(eb - mp);
        float nm = fmaxf(m, mp);
        float cm = __expf(m - nm), cp = __expf(mp - nm);
        s = s * cm + (wa + wb) * cp;
        float wap = wa * cp, wbp = wb * cp;
        a0 = a0 * cm + wap * ra.x + wbp * rb.x;
        a1 = a1 * cm + wap * ra.y + wbp * rb.y;
        m = nm;
    }
    if (i < end) {
        int sn = g_srcid2[i];
        float ev = g_as2[sn] + ad;
        ev = ev > 0.f ? ev : NEG_SLOPE * ev;
        float nm = fmaxf(m, ev);
        float corr = __expf(m - nm);
        float w = __expf(ev - nm);
        s = s * corr + w;
        float2 r = *(const float2*)(g_xs2 + (size_t)sn * 64 + lane * 2);
        a0 = a0 * corr + w * r.x;
        a1 = a1 * corr + w * r.y;
        m = nm;
    }
    float inv = 1.f / (s + 1e-16f);
    float2 o = *(const float2*)(g_o + (size_t)warp * 64 + lane * 2);  // skip2+bias2
    o.x += a0 * inv;
    o.y += a1 * inv;
    // fused log-softmax over the 64-wide row held by this warp
    float mx = fmaxf(o.x, o.y);
    #pragma unroll
    for (int off = 16; off; off >>= 1) mx = fmaxf(mx, __shfl_xor_sync(0xffffffffu, mx, off));
    float se = __expf(o.x - mx) + __expf(o.y - mx);
    #pragma unroll
    for (int off = 16; off; off >>= 1) se += __shfl_xor_sync(0xffffffffu, se, off);
    float l = mx + logf(se);
    float2 r;
    r.x = o.x - l;
    r.y = o.y - l;
    *(float2*)(out + (size_t)warp * 64 + lane * 2) = r;
}

// ---------------- host launcher ----------------
extern "C" void kernel_launch(void* const* d_in, const int* in_sizes, int n_in,
                              void* d_out, int out_size)
{
    const float* x    = (const float*)d_in[0];
    const int*   src1 = (const int*)d_in[1];
    const int*   dst1 = (const int*)d_in[2];
    const int*   src2 = (const int*)d_in[3];
    const int*   dst2 = (const int*)d_in[4];
    const float* W1s  = (const float*)d_in[7];
    const float* W1d  = (const float*)d_in[8];
    const float* a1s  = (const float*)d_in[9];
    const float* a1d  = (const float*)d_in[10];
    const float* b1   = (const float*)d_in[11];
    const float* sk1W = (const float*)d_in[12];
    const float* sk1b = (const float*)d_in[13];
    const float* W2s  = (const float*)d_in[14];
    const float* W2d  = (const float*)d_in[15];
    const float* a2s  = (const float*)d_in[16];
    const float* a2d  = (const float*)d_in[17];
    const float* b2   = (const float*)d_in[18];
    const float* sk2W = (const float*)d_in[19];
    const float* sk2b = (const float*)d_in[20];

    int N0 = in_sizes[0] / KDIM;
    int E1 = in_sizes[1];
    int E2 = in_sizes[3];

    float *xs1, *hbuf, *xs2, *obuf, *as1, *ad1, *as2, *ad2;
    float *vS1, *vD1, *vS2, *vD2, *comb1, *comb2;
    unsigned short *xhi, *xlo, *hhi, *hlo;
    unsigned short *B1hi, *Bs1hi, *B2hi, *Bs2hi;
    cudaGetSymbolAddress((void**)&xs1,  g_xs1);
    cudaGetSymbolAddress((void**)&hbuf, g_h);
    cudaGetSymbolAddress((void**)&xs2,  g_xs2);
    cudaGetSymbolAddress((void**)&obuf, g_o);
    cudaGetSymbolAddress((void**)&as1,  g_as1);
    cudaGetSymbolAddress((void**)&ad1,  g_ad1);
    cudaGetSymbolAddress((void**)&as2,  g_as2);
    cudaGetSymbolAddress((void**)&ad2,  g_ad2);
    cudaGetSymbolAddress((void**)&vS1,  g_vS1);
    cudaGetSymbolAddress((void**)&vD1,  g_vD1);
    cudaGetSymbolAddress((void**)&vS2,  g_vS2);
    cudaGetSymbolAddress((void**)&vD2,  g_vD2);
    cudaGetSymbolAddress((void**)&comb1, g_comb1);
    cudaGetSymbolAddress((void**)&comb2, g_comb2);
    cudaGetSymbolAddress((void**)&xhi,  g_xhi);
    cudaGetSymbolAddress((void**)&xlo,  g_xlo);
    cudaGetSymbolAddress((void**)&hhi,  g_hhi);
    cudaGetSymbolAddress((void**)&hlo,  g_hlo);
    cudaGetSymbolAddress((void**)&B1hi,  g_B1hi);
    cudaGetSymbolAddress((void**)&Bs1hi, g_Bs1hi);
    cudaGetSymbolAddress((void**)&B2hi,  g_B2hi);
    cudaGetSymbolAddress((void**)&Bs2hi, g_Bs2hi);

    const int SMEM_BN128 = 6 * 10240 + 3 * 10240;  // 92160
    const int SMEM_BN64  = 6 * 10240 + 3 * 5120;   // 76800
    cudaFuncSetAttribute(gemm_mma2<128>, cudaFuncAttributeMaxDynamicSharedMemorySize, SMEM_BN128);
    cudaFuncSetAttribute(gemm_mma2<64>,  cudaFuncAttributeMaxDynamicSharedMemorySize, SMEM_BN64);

    // launch order: big GEMM stays at index 3 (ncu capture slot)
    fold_kernel<<<1, 256>>>(W1s, W1d, a1s, a1d, b1, sk1b,
                            W2s, W2d, a2s, a2d, b2, sk2b);                       // 0
    prep_B<<<256, 256>>>(W1s, sk1W, W2s, sk2W);                                  // 1
    split_dot<4><<<CDIV(N0 * 32, 256), 256>>>(x, xhi, xlo, vS1, vD1,
                                              as1, ad1, N0, NT1C);               // 2
    gemm_mma2<128><<<dim3(2, CDIV(N0, 128)), 256, SMEM_BN128>>>(
        xhi, xlo, B1hi, nullptr, xs1, N0, 256);                                  // 3 (profiled)

    zero_counts<<<CDIV(NT1C, 256), 256>>>();                                     // 4
    count_both<<<CDIV(E1 + E2, 256), 256>>>(dst1, dst2, E1, E2);                 // 5
    scan_both<<<2, 1024>>>();                                                    // 6
    fill_both<<<CDIV(E1 + E2, 256), 256>>>(dst1, src1, dst2, src2, E1, E2);      // 7

    // --- layer 1 ---
    gemm_mma2<128><<<dim3(2, CDIV(NT1C, 128)), 256, SMEM_BN128>>>(
        xhi, xlo, Bs1hi, comb1, hbuf, NT1C, 256);                                // 8
    gat_agg1<<<CDIV(NT1C * 32, 256), 256>>>();                                   // 9

    // --- layer 2 ---
    split_dot<1><<<CDIV(NT1C * 32, 256), 256>>>(hbuf, hhi, hlo, vS2, vD2,
                                                as2, ad2, NT1C, NT2C);           // 10
    gemm_mma2<64><<<dim3(1, CDIV(NT1C, 128)), 256, SMEM_BN64>>>(
        hhi, hlo, B2hi, nullptr, xs2, NT1C, 64);                                 // 11
    gemm_mma2<64><<<dim3(1, CDIV(NT2C, 128)), 256, SMEM_BN64>>>(
        hhi, hlo, Bs2hi, comb2, obuf, NT2C, 64);                                 // 12
    gat_agg2_lsm<<<CDIV(NT2C * 32, 256), 256>>>((float*)d_out);                  // 13
}

// round 16
// speedup vs baseline: 2.4660x; 1.1762x over previous
#include <cuda_runtime.h>
#include <cuda_fp16.h>
#include <cstdint>

#define CDIV(a,b) (((a)+(b)-1)/(b))

// ---------------- problem constants ----------------
#define KDIM   256
#define NT1C   25000
#define NT2C   5000
#define N0C    100000
#define E1CAP  400000
#define E2CAP  100000
#define NEG_SLOPE 0.2f

// ---------------- static scratch ----------------
__device__ unsigned short g_xs1h[(size_t)N0C * 256];   // xs1 as fp16 (51 MB)
__device__ float g_h  [(size_t)NT1C * 256];            // skip1+bias, read by agg1
__device__ float g_xs2[(size_t)NT1C * 64];
__device__ float g_o  [(size_t)NT2C * 64];
__device__ float g_as1[(size_t)N0C * 4];
__device__ float g_ad1[NT1C * 4];
__device__ float g_as2[NT1C];
__device__ float g_ad2[NT2C];
__device__ float g_vS1[4 * 256];
__device__ float g_vD1[4 * 256];
__device__ float g_vS2[256];
__device__ float g_vD2[256];
__device__ float g_comb1[256];
__device__ float g_comb2[64];
__device__ unsigned short g_xhi[(size_t)N0C * 256];    // x as fp16 (hi only)
__device__ unsigned short g_hhi[(size_t)NT1C * 256];   // h fp16 hi
__device__ unsigned short g_hlo[(size_t)NT1C * 256];   // h fp16 lo
__device__ unsigned short g_B1hi[256 * 256];
__device__ unsigned short g_Bs1hi[256 * 256];
__device__ unsigned short g_B2hi[64 * 256];
__device__ unsigned short g_Bs2hi[64 * 256];
__device__ int g_cnt1[NT1C];
__device__ int g_off1[NT1C + 1];
__device__ int g_cur1[NT1C];
__device__ int g_srcid1[E1CAP];
__device__ int g_cnt2[NT2C];
__device__ int g_off2[NT2C + 1];
__device__ int g_cur2[NT2C];
__device__ int g_srcid2[E2CAP];

// ---------------- helpers ----------------
__device__ __forceinline__ uint32_t smem_u32(const void* p) {
    uint32_t a;
    asm("{ .reg .u64 t; cvta.to.shared.u64 t, %1; cvt.u32.u64 %0, t; }" : "=r"(a) : "l"(p));
    return a;
}
__device__ __forceinline__ void split1(float v, unsigned short& h, unsigned short& l) {
    __half hb = __float2half_rn(v);
    float hf = __half2float(hb);
    h = __half_as_ushort(hb);
    l = __half_as_ushort(__float2half_rn(v - hf));
}
__device__ __forceinline__ void mma_f16(float& c0, float& c1, float& c2, float& c3,
                                        uint32_t a0, uint32_t a1, uint32_t a2, uint32_t a3,
                                        uint32_t b0, uint32_t b1) {
    asm volatile(
        "mma.sync.aligned.m16n8k16.row.col.f32.f16.f16.f32 "
        "{%0,%1,%2,%3}, {%4,%5,%6,%7}, {%8,%9}, {%0,%1,%2,%3};"
        : "+f"(c0), "+f"(c1), "+f"(c2), "+f"(c3)
        : "r"(a0), "r"(a1), "r"(a2), "r"(a3), "r"(b0), "r"(b1));
}
#define LDSM4(r, a) \
    asm volatile("ldmatrix.sync.aligned.m8n8.x4.shared.b16 {%0,%1,%2,%3}, [%4];" \
        : "=r"((r)[0]), "=r"((r)[1]), "=r"((r)[2]), "=r"((r)[3]) : "r"(a))

// ------- fused fp16 convert + 8 attention dots via 9-shfl butterfly ----------
__global__ void split_dot4(const float* __restrict__ X,
                           unsigned short* __restrict__ hi_,
                           const float* __restrict__ Vs, const float* __restrict__ Vd,
                           float* __restrict__ as_, float* __restrict__ ad_,
                           int M, int Mdst)
{
    int warp = (blockIdx.x * blockDim.x + threadIdx.x) >> 5;
    int lane = threadIdx.x & 31;
    if (warp >= M) return;
    const float* xr = X + (size_t)warp * 256 + lane * 8;
    float4 x0 = *(const float4*)xr;
    float4 x1 = *(const float4*)(xr + 4);
    float xv[8] = { x0.x, x0.y, x0.z, x0.w, x1.x, x1.y, x1.z, x1.w };

    // fp16 hi plane only (single-product GEMM)
    unsigned short h8[8];
    #pragma unroll
    for (int j = 0; j < 8; j++) h8[j] = __half_as_ushort(__float2half_rn(xv[j]));
    uint4 ph;
    ph.x = (uint32_t)h8[0] | ((uint32_t)h8[1] << 16);
    ph.y = (uint32_t)h8[2] | ((uint32_t)h8[3] << 16);
    ph.z = (uint32_t)h8[4] | ((uint32_t)h8[5] << 16);
    ph.w = (uint32_t)h8[6] | ((uint32_t)h8[7] << 16);
    *(uint4*)(hi_ + (size_t)warp * 256 + lane * 8) = ph;

    // 8 partial dots: v[0..3] = src heads, v[4..7] = dst heads
    float v[8];
    #pragma unroll
    for (int h = 0; h < 4; h++) {
        const float* vr = Vs + h * 256 + lane * 8;
        float4 v0 = *(const float4*)vr;
        float4 v1 = *(const float4*)(vr + 4);
        v[h] = xv[0]*v0.x + xv[1]*v0.y + xv[2]*v0.z + xv[3]*v0.w +
               xv[4]*v1.x + xv[5]*v1.y + xv[6]*v1.z + xv[7]*v1.w;
    }
    #pragma unroll
    for (int h = 0; h < 4; h++) {
        const float* vr = Vd + h * 256 + lane * 8;
        float4 v0 = *(const float4*)vr;
        float4 v1 = *(const float4*)(vr + 4);
        v[4+h] = xv[0]*v0.x + xv[1]*v0.y + xv[2]*v0.z + xv[3]*v0.w +
                 xv[4]*v1.x + xv[5]*v1.y + xv[6]*v1.z + xv[7]*v1.w;
    }

    // 8-value warp reduction in 9 shfls
    bool hb = lane >= 16;
    #pragma unroll
    for (int j = 0; j < 4; j++) {
        float send = hb ? v[j] : v[j + 4];
        float recv = __shfl_xor_sync(0xffffffffu, send, 16);
        if (hb) v[j + 4] += recv; else v[j] += recv;
    }
    float w[4];
    #pragma unroll
    for (int j = 0; j < 4; j++) w[j] = hb ? v[4 + j] : v[j];
    bool qb = (lane & 8) != 0;
    #pragma unroll
    for (int j = 0; j < 2; j++) {
        float send = qb ? w[j] : w[j + 2];
        float recv = __shfl_xor_sync(0xffffffffu, send, 8);
        if (qb) w[j + 2] += recv; else w[j] += recv;
    }
    float u0 = qb ? w[2] : w[0];
    float u1 = qb ? w[3] : w[1];
    bool rb = (lane & 4) != 0;
    float send = rb ? u0 : u1;
    float recv = __shfl_xor_sync(0xffffffffu, send, 4);
    float z = rb ? (u1 + recv) : (u0 + recv);
    z += __shfl_xor_sync(0xffffffffu, z, 2);
    z += __shfl_xor_sync(0xffffffffu, z, 1);

    if ((lane & 3) == 0) {
        int grp = lane >> 2;                 // == value index
        if (grp < 4) as_[(size_t)warp * 4 + grp] = z;
        else if (warp < Mdst) ad_[(size_t)warp * 4 + (grp - 4)] = z;
    }
}

// ---------------- prep: transpose + fp16-round B matrices --------------------
__global__ void prep_B(const float* __restrict__ W1s, const float* __restrict__ sk1W,
                       const float* __restrict__ W2s, const float* __restrict__ sk2W)
{
    int k = blockIdx.x;
    int n = threadIdx.x;
    g_B1hi[n * 256 + k]  = __half_as_ushort(__float2half_rn(W1s[k * 256 + n]));
    g_Bs1hi[n * 256 + k] = __half_as_ushort(__float2half_rn(sk1W[k * 256 + n]));
    if (n < 64) {
        g_B2hi[n * 256 + k]  = __half_as_ushort(__float2half_rn(W2s[k * 64 + n]));
        g_Bs2hi[n * 256 + k] = __half_as_ushort(__float2half_rn(sk2W[k * 64 + n]));
    }
}

// ---------------- MMA GEMM: C[M,NDIM] = A[M,256] @ B^T (+bias) ---------------
// NPROD=1: plain fp16 (A hi only). NPROD=2: (Ah+Al)*Bh exact-split A.
// OUT16: store packed half2. 3-stage cp.async ring, x-major grid for A reuse.
template <int BN, int NPROD, bool OUT16>
__global__ __launch_bounds__(256, 2) void gemm_mma2(
    const unsigned short* __restrict__ Ahi, const unsigned short* __restrict__ Alo,
    const unsigned short* __restrict__ Bhi,
    const float* __restrict__ bias, void* __restrict__ Cv, int M, int NDIM)
{
    constexpr int P = 40;
    constexpr uint32_t APL = 128 * P * 2;
    constexpr uint32_t BPL = (uint32_t)BN * P * 2;
    constexpr uint32_t AREG = 3 * NPROD * APL;
    constexpr int NT_N = BN / 16;
    constexpr int NPAIR = BN / 32;
    constexpr int BU = BN / 64;

    extern __shared__ char smem[];
    uint32_t sb = smem_u32(smem);
    uint32_t sbB = sb + AREG;

    int tid = threadIdx.x, lane = tid & 31, wid = tid >> 5;
    int wm = wid >> 1, wn = wid & 1;
    int g = lane >> 2, t = lane & 3;
    int bm0 = blockIdx.y * 128, bn0 = blockIdx.x * BN;

    int q8 = lane & 7, mm = lane >> 3;
    uint32_t aoff = (uint32_t)((wm * 32 + (mm & 1) * 8 + q8) * P * 2 + ((mm & 2) * 4) * 2);
    uint32_t boff = (uint32_t)((wn * (BN / 2) + ((mm >> 1) & 1) * 8 + q8) * P * 2 + ((mm & 1) * 8) * 2);

    float acc[2][NT_N][4];
    #pragma unroll
    for (int i = 0; i < 2; i++)
        #pragma unroll
        for (int j = 0; j < NT_N; j++)
            #pragma unroll
            for (int q = 0; q < 4; q++) acc[i][j][q] = 0.f;

    auto ld_stage = [&](int kt, int buf) {
        int k0 = kt * 32;
        #pragma unroll
        for (int pl = 0; pl < NPROD; pl++) {
            const unsigned short* Ap = pl ? Alo : Ahi;
            #pragma unroll
            for (int u = 0; u < 2; u++) {
                int c = tid + u * 256;
                int r = c >> 2, c4 = c & 3;
                int row = bm0 + r;
                const void* gp = Ap + (size_t)row * KDIM + k0 + c4 * 8;
                uint32_t dst = sb + (uint32_t)(buf * NPROD + pl) * APL + (uint32_t)(r * P * 2 + c4 * 16);
                int sz = (row < M) ? 16 : 0;
                asm volatile("cp.async.cg.shared.global [%0], [%1], 16, %2;"
                             :: "r"(dst), "l"(gp), "r"(sz));
            }
        }
        #pragma unroll
        for (int u = 0; u < BU; u++) {
            int c = tid + u * 256;
            int r = c >> 2, c4 = c & 3;
            const void* gp = Bhi + (size_t)(bn0 + r) * KDIM + k0 + c4 * 8;
            uint32_t dst = sbB + (uint32_t)buf * BPL + (uint32_t)(r * P * 2 + c4 * 16);
            asm volatile("cp.async.cg.shared.global [%0], [%1], 16;"
                         :: "r"(dst), "l"(gp));
        }
        asm volatile("cp.async.commit_group;");
    };

    auto compute = [&](int buf) {
        #pragma unroll
        for (int kk = 0; kk < 32; kk += 16) {
            uint32_t ah[2][4], al[2][4];
            #pragma unroll
            for (int mt = 0; mt < 2; mt++) {
                uint32_t ad = sb + (uint32_t)(buf * NPROD) * APL + aoff + (uint32_t)(mt * 16 * P * 2 + kk * 2);
                LDSM4(ah[mt], ad);
                if (NPROD == 2) LDSM4(al[mt], ad + APL);
            }
            uint32_t bh[NT_N][2];
            #pragma unroll
            for (int pr = 0; pr < NPAIR; pr++) {
                uint32_t bd = sbB + (uint32_t)buf * BPL + boff + (uint32_t)(pr * 16 * P * 2 + kk * 2);
                uint32_t r4[4];
                LDSM4(r4, bd);
                bh[2 * pr][0] = r4[0]; bh[2 * pr][1] = r4[1];
                bh[2 * pr + 1][0] = r4[2]; bh[2 * pr + 1][1] = r4[3];
            }
            #pragma unroll
            for (int mt = 0; mt < 2; mt++)
                #pragma unroll
                for (int nt = 0; nt < NT_N; nt++) {
                    float* c = acc[mt][nt];
                    mma_f16(c[0], c[1], c[2], c[3],
                            ah[mt][0], ah[mt][1], ah[mt][2], ah[mt][3],
                            bh[nt][0], bh[nt][1]);
                    if (NPROD == 2)
                        mma_f16(c[0], c[1], c[2], c[3],
                                al[mt][0], al[mt][1], al[mt][2], al[mt][3],
                                bh[nt][0], bh[nt][1]);
                }
        }
    };

    ld_stage(0, 0);
    ld_stage(1, 1);
    #pragma unroll 1
    for (int kt = 0; kt < 8; kt++) {
        if (kt < 7) asm volatile("cp.async.wait_group 1;");
        else        asm volatile("cp.async.wait_group 0;");
        __syncthreads();
        if (kt + 2 < 8) ld_stage(kt + 2, (kt + 2) % 3);
        compute(kt % 3);
    }

    #pragma unroll
    for (int nt = 0; nt < NT_N; nt++) {
        int cn = bn0 + wn * (BN / 2) + nt * 8 + t * 2;
        float2 bv = make_float2(0.f, 0.f);
        if (bias) bv = *(const float2*)(bias + cn);
        #pragma unroll
        for (int mt = 0; mt < 2; mt++) {
            int row0 = bm0 + wm * 32 + mt * 16 + g;
            float* c = acc[mt][nt];
            if constexpr (OUT16) {
                __half2* C16 = (__half2*)Cv;
                if (row0 < M)
                    C16[(size_t)row0 * (NDIM / 2) + (cn >> 1)] =
                        __floats2half2_rn(c[0] + bv.x, c[1] + bv.y);
                if (row0 + 8 < M)
                    C16[(size_t)(row0 + 8) * (NDIM / 2) + (cn >> 1)] =
                        __floats2half2_rn(c[2] + bv.x, c[3] + bv.y);
            } else {
                float* C = (float*)Cv;
                if (row0 < M) {
                    float2 o = make_float2(c[0] + bv.x, c[1] + bv.y);
                    *(float2*)(C + (size_t)row0 * NDIM + cn) = o;
                }
                if (row0 + 8 < M) {
                    float2 o = make_float2(c[2] + bv.x, c[3] + bv.y);
                    *(float2*)(C + (size_t)(row0 + 8) * NDIM + cn) = o;
                }
            }
        }
    }
}

// ---------------- fold ----------------
__global__ void fold_kernel(const float* __restrict__ W1s, const float* __restrict__ W1d,
                            const float* __restrict__ a1s, const float* __restrict__ a1d,
                            const float* __restrict__ b1,  const float* __restrict__ s1b,
                            const float* __restrict__ W2s, const float* __restrict__ W2d,
                            const float* __restrict__ a2s, const float* __restrict__ a2d,
                            const float* __restrict__ b2,  const float* __restrict__ s2b)
{
    int k = threadIdx.x;
    #pragma unroll
    for (int h = 0; h < 4; h++) {
        float ss = 0.f, sd = 0.f;
        for (int d = 0; d < 64; d++) {
            ss += W1s[k * 256 + h * 64 + d] * a1s[h * 64 + d];
            sd += W1d[k * 256 + h * 64 + d] * a1d[h * 64 + d];
        }
        g_vS1[h * 256 + k] = ss;
        g_vD1[h * 256 + k] = sd;
    }
    float s2 = 0.f, d2 = 0.f;
    for (int d = 0; d < 64; d++) {
        s2 += W2s[k * 64 + d] * a2s[d];
        d2 += W2d[k * 64 + d] * a2d[d];
    }
    g_vS2[k] = s2;
    g_vD2[k] = d2;
    g_comb1[k] = b1[k] + s1b[k];
    if (k < 64) g_comb2[k] = b2[k] + s2b[k];
}

// ---------------- CSR build ----------------
__global__ void zero_counts()
{
    int i = blockIdx.x * blockDim.x + threadIdx.x;
    if (i < NT1C) g_cnt1[i] = 0;
    if (i < NT2C) g_cnt2[i] = 0;
}

__global__ void count_both(const int* __restrict__ dst1, const int* __restrict__ dst2,
                           int E1, int E2)
{
    int e = blockIdx.x * blockDim.x + threadIdx.x;
    if (e < E1) atomicAdd(&g_cnt1[dst1[e]], 1);
    else if (e - E1 < E2) atomicAdd(&g_cnt2[dst2[e - E1]], 1);
}

__device__ void scan_impl(const int* __restrict__ cnt, int* __restrict__ off,
                          int* __restrict__ cur, int n)
{
    __shared__ int wpre[32];
    __shared__ int carry;
    int t = threadIdx.x, lane = t & 31, w = t >> 5;
    if (t == 0) { carry = 0; off[0] = 0; }
    __syncthreads();
    for (int base = 0; base < n; base += 1024) {
        int i = base + t;
        int v = (i < n) ? cnt[i] : 0;
        int x = v;
        #pragma unroll
        for (int d = 1; d < 32; d <<= 1) {
            int y = __shfl_up_sync(0xffffffffu, x, d);
            if (lane >= d) x += y;
        }
        if (lane == 31) wpre[w] = x;
        __syncthreads();
        if (w == 0) {
            int s = wpre[lane];
            #pragma unroll
            for (int d = 1; d < 32; d <<= 1) {
                int y = __shfl_up_sync(0xffffffffu, s, d);
                if (lane >= d) s += y;
            }
            wpre[lane] = s;
        }
        __syncthreads();
        int incl = x + (w ? wpre[w - 1] : 0) + carry;
        if (i < n) {
            off[i + 1] = incl;
            cur[i] = incl - v;
        }
        __syncthreads();
        if (t == 1023) carry = incl;
        __syncthreads();
    }
}

__global__ void scan_both()
{
    if (blockIdx.x == 0) scan_impl(g_cnt1, g_off1, g_cur1, NT1C);
    else                 scan_impl(g_cnt2, g_off2, g_cur2, NT2C);
}

__global__ void fill_both(const int* __restrict__ dst1, const int* __restrict__ src1,
                          const int* __restrict__ dst2, const int* __restrict__ src2,
                          int E1, int E2)
{
    int e = blockIdx.x * blockDim.x + threadIdx.x;
    if (e < E1) {
        int p = atomicAdd(&g_cur1[dst1[e]], 1);
        g_srcid1[p] = src1[e];
    } else if (e - E1 < E2) {
        int e2 = e - E1;
        int p = atomicAdd(&g_cur2[dst2[e2]], 1);
        g_srcid2[p] = src2[e2];
    }
}

// -------- layer 1 aggregation (fp16 gather) + h split + layer-2 dots ---------
__global__ __launch_bounds__(256) void gat_agg1()
{
    int warp = (blockIdx.x * blockDim.x + threadIdx.x) >> 5;
    int lane = threadIdx.x & 31;
    if (warp >= NT1C) return;
    int myh = lane >> 3;
    float ad = g_ad1[warp * 4 + myh];
    int beg = g_off1[warp], end = g_off1[warp + 1];
    float m = -1e30f, s = 0.f;
    float acc[8];
    #pragma unroll
    for (int j = 0; j < 8; j++) acc[j] = 0.f;

    int i = beg;
    for (; i + 1 < end; i += 2) {
        int sa = g_srcid1[i], sb = g_srcid1[i + 1];
        float ea = g_as1[(size_t)sa * 4 + myh] + ad;
        float eb = g_as1[(size_t)sb * 4 + myh] + ad;
        ea = ea > 0.f ? ea : NEG_SLOPE * ea;
        eb = eb > 0.f ? eb : NEG_SLOPE * eb;
        uint4 qa = *(const uint4*)(g_xs1h + (size_t)sa * 256 + lane * 8);
        uint4 qb = *(const uint4*)(g_xs1h + (size_t)sb * 256 + lane * 8);
        float2 a01 = __half22float2(*(__half2*)&qa.x);
        float2 a23 = __half22float2(*(__half2*)&qa.y);
        float2 a45 = __half22float2(*(__half2*)&qa.z);
        float2 a67 = __half22float2(*(__half2*)&qa.w);
        float2 b01 = __half22float2(*(__half2*)&qb.x);
        float2 b23 = __half22float2(*(__half2*)&qb.y);
        float2 b45 = __half22float2(*(__half2*)&qb.z);
        float2 b67 = __half22float2(*(__half2*)&qb.w);
        float mp = fmaxf(ea, eb);
        float wa = __expf(ea - mp), wb = __expf(eb - mp);
        float nm = fmaxf(m, mp);
        float cm = __expf(m - nm), cp = __expf(mp - nm);
        s = s * cm + (wa + wb) * cp;
        float wap = wa * cp, wbp = wb * cp;
        acc[0] = acc[0] * cm + wap * a01.x + wbp * b01.x;
        acc[1] = acc[1] * cm + wap * a01.y + wbp * b01.y;
        acc[2] = acc[2] * cm + wap * a23.x + wbp * b23.x;
        acc[3] = acc[3] * cm + wap * a23.y + wbp * b23.y;
        acc[4] = acc[4] * cm + wap * a45.x + wbp * b45.x;
        acc[5] = acc[5] * cm + wap * a45.y + wbp * b45.y;
        acc[6] = acc[6] * cm + wap * a67.x + wbp * b67.x;
        acc[7] = acc[7] * cm + wap * a67.y + wbp * b67.y;
        m = nm;
    }
    if (i < end) {
        int sn = g_srcid1[i];
        float ev = g_as1[(size_t)sn * 4 + myh] + ad;
        ev = ev > 0.f ? ev : NEG_SLOPE * ev;
        float nm = fmaxf(m, ev);
        float corr = __expf(m - nm);
        float w = __expf(ev - nm);
        s = s * corr + w;
        uint4 qa = *(const uint4*)(g_xs1h + (size_t)sn * 256 + lane * 8);
        float2 a01 = __half22float2(*(__half2*)&qa.x);
        float2 a23 = __half22float2(*(__half2*)&qa.y);
        float2 a45 = __half22float2(*(__half2*)&qa.z);
        float2 a67 = __half22float2(*(__half2*)&qa.w);
        acc[0] = acc[0] * corr + w * a01.x;
        acc[1] = acc[1] * corr + w * a01.y;
        acc[2] = acc[2] * corr + w * a23.x;
        acc[3] = acc[3] * corr + w * a23.y;
        acc[4] = acc[4] * corr + w * a45.x;
        acc[5] = acc[5] * corr + w * a45.y;
        acc[6] = acc[6] * corr + w * a67.x;
        acc[7] = acc[7] * corr + w * a67.y;
        m = nm;
    }
    float inv = 1.f / (s + 1e-16f);
    const float* hp = g_h + (size_t)warp * 256 + lane * 8;
    float4 h0 = ((const float4*)hp)[0], h1 = ((const float4*)hp)[1];
    float v[8];
    v[0] = acc[0] * inv + h0.x;  v[1] = acc[1] * inv + h0.y;
    v[2] = acc[2] * inv + h0.z;  v[3] = acc[3] * inv + h0.w;
    v[4] = acc[4] * inv + h1.x;  v[5] = acc[5] * inv + h1.y;
    v[6] = acc[6] * inv + h1.z;  v[7] = acc[7] * inv + h1.w;
    #pragma unroll
    for (int j = 0; j < 8; j++) v[j] = v[j] > 0.f ? v[j] : (__expf(v[j]) - 1.f);

    // write fp16 hi/lo planes of h
    unsigned short hh[8], hl[8];
    #pragma unroll
    for (int j = 0; j < 8; j++) split1(v[j], hh[j], hl[j]);
    uint4 phh, pll;
    phh.x = (uint32_t)hh[0] | ((uint32_t)hh[1] << 16);
    phh.y = (uint32_t)hh[2] | ((uint32_t)hh[3] << 16);
    phh.z = (uint32_t)hh[4] | ((uint32_t)hh[5] << 16);
    phh.w = (uint32_t)hh[6] | ((uint32_t)hh[7] << 16);
    pll.x = (uint32_t)hl[0] | ((uint32_t)hl[1] << 16);
    pll.y = (uint32_t)hl[2] | ((uint32_t)hl[3] << 16);
    pll.z = (uint32_t)hl[4] | ((uint32_t)hl[5] << 16);
    pll.w = (uint32_t)hl[6] | ((uint32_t)hl[7] << 16);
    *(uint4*)(g_hhi + (size_t)warp * 256 + lane * 8) = phh;
    *(uint4*)(g_hlo + (size_t)warp * 256 + lane * 8) = pll;

    // layer-2 attention dots from in-register h row (2-value 5-shfl reduce)
    const float* vs = g_vS2 + lane * 8;
    const float* vd = g_vD2 + lane * 8;
    float4 s0 = *(const float4*)vs, s1 = *(const float4*)(vs + 4);
    float4 d0 = *(const float4*)vd, d1 = *(const float4*)(vd + 4);
    float a = v[0]*s0.x + v[1]*s0.y + v[2]*s0.z + v[3]*s0.w +
              v[4]*s1.x + v[5]*s1.y + v[6]*s1.z + v[7]*s1.w;
    float b = v[0]*d0.x + v[1]*d0.y + v[2]*d0.z + v[3]*d0.w +
              v[4]*d1.x + v[5]*d1.y + v[6]*d1.z + v[7]*d1.w;
    bool hb = lane >= 16;
    float send = hb ? a : b;
    float recv = __shfl_xor_sync(0xffffffffu, send, 16);
    if (hb) b += recv; else a += recv;
    float z = hb ? b : a;
    z += __shfl_xor_sync(0xffffffffu, z, 8);
    z += __shfl_xor_sync(0xffffffffu, z, 4);
    z += __shfl_xor_sync(0xffffffffu, z, 2);
    z += __shfl_xor_sync(0xffffffffu, z, 1);
    if (lane == 0) g_as2[warp] = z;
    if (lane == 16 && warp < NT2C) g_ad2[warp] = z;
}

// ---------- layer 2 aggregation (pairwise) + fused log_softmax ----------
__global__ __launch_bounds__(256) void gat_agg2_lsm(float* __restrict__ out)
{
    int warp = (blockIdx.x * blockDim.x + threadIdx.x) >> 5;
    int lane = threadIdx.x & 31;
    if (warp >= NT2C) return;
    float ad = g_ad2[warp];
    int beg = g_off2[warp], end = g_off2[warp + 1];
    float m = -1e30f, s = 0.f, a0 = 0.f, a1 = 0.f;
    int i = beg;
    for (; i + 1 < end; i += 2) {
        int sa = g_srcid2[i], sb = g_srcid2[i + 1];
        float ea = g_as2[sa] + ad;
        float eb = g_as2[sb] + ad;
        ea = ea > 0.f ? ea : NEG_SLOPE * ea;
        eb = eb > 0.f ? eb : NEG_SLOPE * eb;
        float2 ra = *(const float2*)(g_xs2 + (size_t)sa * 64 + lane * 2);
        float2 rb = *(const float2*)(g_xs2 + (size_t)sb * 64 + lane * 2);
        float mp = fmaxf(ea, eb);
        float wa = __expf(ea - mp), wb = __expf(eb - mp);
        float nm = fmaxf(m, mp);
        float cm = __expf(m - nm), cp = __expf(mp - nm);
        s = s * cm + (wa + wb) * cp;
        float wap = wa * cp, wbp = wb * cp;
        a0 = a0 * cm + wap * ra.x + wbp * rb.x;
        a1 = a1 * cm + wap * ra.y + wbp * rb.y;
        m = nm;
    }
    if (i < end) {
        int sn = g_srcid2[i];
        float ev = g_as2[sn] + ad;
        ev = ev > 0.f ? ev : NEG_SLOPE * ev;
        float nm = fmaxf(m, ev);
        float corr = __expf(m - nm);
        float w = __expf(ev - nm);
        s = s * corr + w;
        float2 r = *(const float2*)(g_xs2 + (size_t)sn * 64 + lane * 2);
        a0 = a0 * corr + w * r.x;
        a1 = a1 * corr + w * r.y;
        m = nm;
    }
    float inv = 1.f / (s + 1e-16f);
    float2 o = *(const float2*)(g_o + (size_t)warp * 64 + lane * 2);
    o.x += a0 * inv;
    o.y += a1 * inv;
    float mx = fmaxf(o.x, o.y);
    #pragma unroll
    for (int off = 16; off; off >>= 1) mx = fmaxf(mx, __shfl_xor_sync(0xffffffffu, mx, off));
    float se = __expf(o.x - mx) + __expf(o.y - mx);
    #pragma unroll
    for (int off = 16; off; off >>= 1) se += __shfl_xor_sync(0xffffffffu, se, off);
    float l = mx + logf(se);
    float2 r;
    r.x = o.x - l;
    r.y = o.y - l;
    *(float2*)(out + (size_t)warp * 64 + lane * 2) = r;
}

// ---------------- host launcher ----------------
extern "C" void kernel_launch(void* const* d_in, const int* in_sizes, int n_in,
                              void* d_out, int out_size)
{
    const float* x    = (const float*)d_in[0];
    const int*   src1 = (const int*)d_in[1];
    const int*   dst1 = (const int*)d_in[2];
    const int*   src2 = (const int*)d_in[3];
    const int*   dst2 = (const int*)d_in[4];
    const float* W1s  = (const float*)d_in[7];
    const float* W1d  = (const float*)d_in[8];
    const float* a1s  = (const float*)d_in[9];
    const float* a1d  = (const float*)d_in[10];
    const float* b1   = (const float*)d_in[11];
    const float* sk1W = (const float*)d_in[12];
    const float* sk1b = (const float*)d_in[13];
    const float* W2s  = (const float*)d_in[14];
    const float* W2d  = (const float*)d_in[15];
    const float* a2s  = (const float*)d_in[16];
    const float* a2d  = (const float*)d_in[17];
    const float* b2   = (const float*)d_in[18];
    const float* sk2W = (const float*)d_in[19];
    const float* sk2b = (const float*)d_in[20];

    int N0 = in_sizes[0] / KDIM;
    int E1 = in_sizes[1];
    int E2 = in_sizes[3];

    unsigned short *xs1h, *xhi, *hhi, *hlo;
    float *hbuf, *xs2, *obuf, *as1, *ad1, *as2, *ad2;
    float *vS1, *vD1, *vS2, *vD2, *comb1, *comb2;
    unsigned short *B1hi, *Bs1hi, *B2hi, *Bs2hi;
    cudaGetSymbolAddress((void**)&xs1h, g_xs1h);
    cudaGetSymbolAddress((void**)&hbuf, g_h);
    cudaGetSymbolAddress((void**)&xs2,  g_xs2);
    cudaGetSymbolAddress((void**)&obuf, g_o);
    cudaGetSymbolAddress((void**)&as1,  g_as1);
    cudaGetSymbolAddress((void**)&ad1,  g_ad1);
    cudaGetSymbolAddress((void**)&as2,  g_as2);
    cudaGetSymbolAddress((void**)&ad2,  g_ad2);
    cudaGetSymbolAddress((void**)&vS1,  g_vS1);
    cudaGetSymbolAddress((void**)&vD1,  g_vD1);
    cudaGetSymbolAddress((void**)&vS2,  g_vS2);
    cudaGetSymbolAddress((void**)&vD2,  g_vD2);
    cudaGetSymbolAddress((void**)&comb1, g_comb1);
    cudaGetSymbolAddress((void**)&comb2, g_comb2);
    cudaGetSymbolAddress((void**)&xhi,  g_xhi);
    cudaGetSymbolAddress((void**)&hhi,  g_hhi);
    cudaGetSymbolAddress((void**)&hlo,  g_hlo);
    cudaGetSymbolAddress((void**)&B1hi,  g_B1hi);
    cudaGetSymbolAddress((void**)&Bs1hi, g_Bs1hi);
    cudaGetSymbolAddress((void**)&B2hi,  g_B2hi);
    cudaGetSymbolAddress((void**)&Bs2hi, g_Bs2hi);

    const int SMEM_L1 = 3 * 10240 + 3 * 10240;   // BN=128, NPROD=1: 61440
    const int SMEM_L2 = 6 * 10240 + 3 * 5120;    // BN=64,  NPROD=2: 76800
    cudaFuncSetAttribute((const void*)gemm_mma2<128, 1, true>,
                         cudaFuncAttributeMaxDynamicSharedMemorySize, SMEM_L1);
    cudaFuncSetAttribute((const void*)gemm_mma2<128, 1, false>,
                         cudaFuncAttributeMaxDynamicSharedMemorySize, SMEM_L1);
    cudaFuncSetAttribute((const void*)gemm_mma2<64, 2, false>,
                         cudaFuncAttributeMaxDynamicSharedMemorySize, SMEM_L2);

    // launch order: big GEMM at index 3 (ncu capture slot)
    fold_kernel<<<1, 256>>>(W1s, W1d, a1s, a1d, b1, sk1b,
                            W2s, W2d, a2s, a2d, b2, sk2b);                       // 0
    prep_B<<<256, 256>>>(W1s, sk1W, W2s, sk2W);                                  // 1
    split_dot4<<<CDIV(N0 * 32, 256), 256>>>(x, xhi, vS1, vD1,
                                            as1, ad1, N0, NT1C);                 // 2
    gemm_mma2<128, 1, true><<<dim3(2, CDIV(N0, 128)), 256, SMEM_L1>>>(
        xhi, nullptr, B1hi, nullptr, xs1h, N0, 256);                             // 3 (profiled)

    zero_counts<<<CDIV(NT1C, 256), 256>>>();                                     // 4
    count_both<<<CDIV(E1 + E2, 256), 256>>>(dst1, dst2, E1, E2);                 // 5
    scan_both<<<2, 1024>>>();                                                    // 6
    fill_both<<<CDIV(E1 + E2, 256), 256>>>(dst1, src1, dst2, src2, E1, E2);      // 7

    // --- layer 1 ---
    gemm_mma2<128, 1, false><<<dim3(2, CDIV(NT1C, 128)), 256, SMEM_L1>>>(
        xhi, nullptr, Bs1hi, comb1, hbuf, NT1C, 256);                            // 8
    gat_agg1<<<CDIV(NT1C * 32, 256), 256>>>();                                   // 9

    // --- layer 2 ---
    gemm_mma2<64, 2, false><<<dim3(1, CDIV(NT1C, 128)), 256, SMEM_L2>>>(
        hhi, hlo, B2hi, nullptr, xs2, NT1C, 64);                                 // 10
    gemm_mma2<64, 2, false><<<dim3(1, CDIV(NT2C, 128)), 256, SMEM_L2>>>(
        hhi, hlo, Bs2hi, comb2, obuf, NT2C, 64);                                 // 11
    gat_agg2_lsm<<<CDIV(NT2C * 32, 256), 256>>>((float*)d_out);                  // 12
}

// round 17
// speedup vs baseline: 3.1358x; 1.2716x over previous
#include <cuda_runtime.h>
#include <cuda_fp16.h>
#include <cstdint>

#define CDIV(a,b) (((a)+(b)-1)/(b))

// ---------------- problem constants ----------------
#define KDIM   256
#define NT1C   25000
#define NT2C   5000
#define N0C    100000
#define E1CAP  400000
#define E2CAP  100000
#define NEG_SLOPE 0.2f

// ---------------- static scratch ----------------
__device__ unsigned short g_xs1h[(size_t)N0C * 256];   // xs1 as fp16
__device__ float g_h  [(size_t)NT1C * 256];            // skip1+bias -> h
__device__ float g_xs2[(size_t)NT1C * 64];
__device__ float g_o  [(size_t)NT2C * 64];
__device__ float g_as1[(size_t)N0C * 4];
__device__ float g_ad1[NT1C * 4];
__device__ float g_as2[NT1C];
__device__ float g_ad2[NT2C];
__device__ float g_vS1[4 * 256];
__device__ float g_vD1[4 * 256];
__device__ float g_vS2[256];
__device__ float g_vD2[256];
__device__ float g_comb1[256];
__device__ float g_comb2[64];
__device__ unsigned short g_xhi[(size_t)N0C * 256];    // x as fp16
__device__ unsigned short g_hhi[(size_t)NT1C * 256];   // h fp16 hi
__device__ unsigned short g_hlo[(size_t)NT1C * 256];   // h fp16 lo
__device__ unsigned short g_B1hi[256 * 256];
__device__ unsigned short g_Bs1hi[256 * 256];
__device__ unsigned short g_B2hi[64 * 256];
__device__ unsigned short g_Bs2hi[64 * 256];
__device__ int g_cnt1[NT1C];
__device__ int g_off1[NT1C + 1];
__device__ int g_cur1[NT1C];
__device__ int g_srcid1[E1CAP];
__device__ int g_cnt2[NT2C];
__device__ int g_off2[NT2C + 1];
__device__ int g_cur2[NT2C];
__device__ int g_srcid2[E2CAP];

// ---------------- helpers ----------------
__device__ __forceinline__ uint32_t smem_u32(const void* p) {
    uint32_t a;
    asm("{ .reg .u64 t; cvta.to.shared.u64 t, %1; cvt.u32.u64 %0, t; }" : "=r"(a) : "l"(p));
    return a;
}
__device__ __forceinline__ void split1(float v, unsigned short& h, unsigned short& l) {
    __half hb = __float2half_rn(v);
    float hf = __half2float(hb);
    h = __half_as_ushort(hb);
    l = __half_as_ushort(__float2half_rn(v - hf));
}
__device__ __forceinline__ void mma_f16(float& c0, float& c1, float& c2, float& c3,
                                        uint32_t a0, uint32_t a1, uint32_t a2, uint32_t a3,
                                        uint32_t b0, uint32_t b1) {
    asm volatile(
        "mma.sync.aligned.m16n8k16.row.col.f32.f16.f16.f32 "
        "{%0,%1,%2,%3}, {%4,%5,%6,%7}, {%8,%9}, {%0,%1,%2,%3};"
        : "+f"(c0), "+f"(c1), "+f"(c2), "+f"(c3)
        : "r"(a0), "r"(a1), "r"(a2), "r"(a3), "r"(b0), "r"(b1));
}
#define LDSM4(r, a) \
    asm volatile("ldmatrix.sync.aligned.m8n8.x4.shared.b16 {%0,%1,%2,%3}, [%4];" \
        : "=r"((r)[0]), "=r"((r)[1]), "=r"((r)[2]), "=r"((r)[3]) : "r"(a))

// ------- fused fp16 convert + 8 attention dots + edge counting --------------
__global__ void split_dot4_count(const float* __restrict__ X,
                                 unsigned short* __restrict__ hi_,
                                 const float* __restrict__ Vs, const float* __restrict__ Vd,
                                 float* __restrict__ as_, float* __restrict__ ad_,
                                 int M, int Mdst, int nbrow,
                                 const int* __restrict__ dst1, const int* __restrict__ dst2,
                                 int E1, int E2)
{
    if ((int)blockIdx.x >= nbrow) {
        int e = (blockIdx.x - nbrow) * 256 + threadIdx.x;
        if (e < E1) atomicAdd(&g_cnt1[dst1[e]], 1);
        else if (e - E1 < E2) atomicAdd(&g_cnt2[dst2[e - E1]], 1);
        return;
    }
    int warp = (blockIdx.x * blockDim.x + threadIdx.x) >> 5;
    int lane = threadIdx.x & 31;
    if (warp >= M) return;
    const float* xr = X + (size_t)warp * 256 + lane * 8;
    float4 x0 = *(const float4*)xr;
    float4 x1 = *(const float4*)(xr + 4);
    float xv[8] = { x0.x, x0.y, x0.z, x0.w, x1.x, x1.y, x1.z, x1.w };

    unsigned short h8[8];
    #pragma unroll
    for (int j = 0; j < 8; j++) h8[j] = __half_as_ushort(__float2half_rn(xv[j]));
    uint4 ph;
    ph.x = (uint32_t)h8[0] | ((uint32_t)h8[1] << 16);
    ph.y = (uint32_t)h8[2] | ((uint32_t)h8[3] << 16);
    ph.z = (uint32_t)h8[4] | ((uint32_t)h8[5] << 16);
    ph.w = (uint32_t)h8[6] | ((uint32_t)h8[7] << 16);
    *(uint4*)(hi_ + (size_t)warp * 256 + lane * 8) = ph;

    float v[8];
    #pragma unroll
    for (int h = 0; h < 4; h++) {
        const float* vr = Vs + h * 256 + lane * 8;
        float4 v0 = *(const float4*)vr;
        float4 v1 = *(const float4*)(vr + 4);
        v[h] = xv[0]*v0.x + xv[1]*v0.y + xv[2]*v0.z + xv[3]*v0.w +
               xv[4]*v1.x + xv[5]*v1.y + xv[6]*v1.z + xv[7]*v1.w;
    }
    #pragma unroll
    for (int h = 0; h < 4; h++) {
        const float* vr = Vd + h * 256 + lane * 8;
        float4 v0 = *(const float4*)vr;
        float4 v1 = *(const float4*)(vr + 4);
        v[4+h] = xv[0]*v0.x + xv[1]*v0.y + xv[2]*v0.z + xv[3]*v0.w +
                 xv[4]*v1.x + xv[5]*v1.y + xv[6]*v1.z + xv[7]*v1.w;
    }

    bool hb = lane >= 16;
    #pragma unroll
    for (int j = 0; j < 4; j++) {
        float send = hb ? v[j] : v[j + 4];
        float recv = __shfl_xor_sync(0xffffffffu, send, 16);
        if (hb) v[j + 4] += recv; else v[j] += recv;
    }
    float w[4];
    #pragma unroll
    for (int j = 0; j < 4; j++) w[j] = hb ? v[4 + j] : v[j];
    bool qb = (lane & 8) != 0;
    #pragma unroll
    for (int j = 0; j < 2; j++) {
        float send = qb ? w[j] : w[j + 2];
        float recv = __shfl_xor_sync(0xffffffffu, send, 8);
        if (qb) w[j + 2] += recv; else w[j] += recv;
    }
    float u0 = qb ? w[2] : w[0];
    float u1 = qb ? w[3] : w[1];
    bool rb = (lane & 4) != 0;
    float send = rb ? u0 : u1;
    float recv = __shfl_xor_sync(0xffffffffu, send, 4);
    float z = rb ? (u1 + recv) : (u0 + recv);
    z += __shfl_xor_sync(0xffffffffu, z, 2);
    z += __shfl_xor_sync(0xffffffffu, z, 1);

    if ((lane & 3) == 0) {
        int grp = lane >> 2;
        if (grp < 4) as_[(size_t)warp * 4 + grp] = z;
        else if (warp < Mdst) ad_[(size_t)warp * 4 + (grp - 4)] = z;
    }
}

// ---- prep: coalesced smem-tile transpose + fp16 round, all 4 B matrices -----
__global__ void prep_Bt(const float* __restrict__ W1s, const float* __restrict__ sk1W,
                        const float* __restrict__ W2s, const float* __restrict__ sk2W)
{
    const float* src;
    unsigned short* dst;
    int N;
    switch (blockIdx.z) {
        case 0:  src = W1s;  dst = g_B1hi;  N = 256; break;
        case 1:  src = sk1W; dst = g_Bs1hi; N = 256; break;
        case 2:  src = W2s;  dst = g_B2hi;  N = 64;  break;
        default: src = sk2W; dst = g_Bs2hi; N = 64;  break;
    }
    int n0 = blockIdx.y * 32;
    if (n0 >= N) return;
    int k0 = blockIdx.x * 32;
    __shared__ unsigned short tile[32][33];
    int tx = threadIdx.x, ty = threadIdx.y;   // 32 x 8
    #pragma unroll
    for (int i = ty; i < 32; i += 8)
        tile[i][tx] = __half_as_ushort(__float2half_rn(src[(size_t)(k0 + i) * N + n0 + tx]));
    __syncthreads();
    #pragma unroll
    for (int i = ty; i < 32; i += 8)
        dst[(size_t)(n0 + i) * 256 + k0 + tx] = tile[tx][i];
}

// ---------------- fold (parallelized over 16 blocks) ----------------
__global__ void fold_kernel(const float* __restrict__ W1s, const float* __restrict__ W1d,
                            const float* __restrict__ a1s, const float* __restrict__ a1d,
                            const float* __restrict__ b1,  const float* __restrict__ s1b,
                            const float* __restrict__ W2s, const float* __restrict__ W2d,
                            const float* __restrict__ a2s, const float* __restrict__ a2d,
                            const float* __restrict__ b2,  const float* __restrict__ s2b)
{
    int k = blockIdx.x * 16 + threadIdx.x;
    #pragma unroll
    for (int h = 0; h < 4; h++) {
        float ss = 0.f, sd = 0.f;
        for (int d = 0; d < 64; d++) {
            ss += W1s[k * 256 + h * 64 + d] * a1s[h * 64 + d];
            sd += W1d[k * 256 + h * 64 + d] * a1d[h * 64 + d];
        }
        g_vS1[h * 256 + k] = ss;
        g_vD1[h * 256 + k] = sd;
    }
    float s2 = 0.f, d2 = 0.f;
    for (int d = 0; d < 64; d++) {
        s2 += W2s[k * 64 + d] * a2s[d];
        d2 += W2d[k * 64 + d] * a2d[d];
    }
    g_vS2[k] = s2;
    g_vD2[k] = d2;
    g_comb1[k] = b1[k] + s1b[k];
    if (k < 64) g_comb2[k] = b2[k] + s2b[k];
}

// ------- fused layer-1 GEMM: xs1 (fp16 out) + skip1 (f32 out, bias) ----------
// grid (4, M-tiles): bx in {0,1} -> xs1 chunks, {2,3} -> skip chunks (rows<Mskip).
__global__ __launch_bounds__(256, 2) void gemm_l1(
    const unsigned short* __restrict__ Ahi,
    const unsigned short* __restrict__ B1,  const unsigned short* __restrict__ Bs1,
    const float* __restrict__ comb1,
    unsigned short* __restrict__ C16, float* __restrict__ Cskip,
    int M, int Mskip)
{
    constexpr int BN = 128;
    constexpr int P = 40;
    constexpr uint32_t APL = 128 * P * 2;
    constexpr uint32_t BPL = (uint32_t)BN * P * 2;
    constexpr uint32_t AREG = 3 * APL;
    constexpr int NT_N = BN / 16;
    constexpr int NPAIR = BN / 32;

    bool skipH = blockIdx.x >= 2;
    int bm0 = blockIdx.y * 128;
    int Me = skipH ? Mskip : M;
    if (bm0 >= Me) return;
    int bn0 = (blockIdx.x & 1) * BN;
    const unsigned short* Bhi = skipH ? Bs1 : B1;

    extern __shared__ char smem[];
    uint32_t sb = smem_u32(smem);
    uint32_t sbB = sb + AREG;

    int tid = threadIdx.x, lane = tid & 31, wid = tid >> 5;
    int wm = wid >> 1, wn = wid & 1;
    int g = lane >> 2, t = lane & 3;
    int q8 = lane & 7, mm = lane >> 3;
    uint32_t aoff = (uint32_t)((wm * 32 + (mm & 1) * 8 + q8) * P * 2 + ((mm & 2) * 4) * 2);
    uint32_t boff = (uint32_t)((wn * (BN / 2) + ((mm >> 1) & 1) * 8 + q8) * P * 2 + ((mm & 1) * 8) * 2);

    float acc[2][NT_N][4];
    #pragma unroll
    for (int i = 0; i < 2; i++)
        #pragma unroll
        for (int j = 0; j < NT_N; j++)
            #pragma unroll
            for (int q = 0; q < 4; q++) acc[i][j][q] = 0.f;

    auto ld_stage = [&](int kt, int buf) {
        int k0 = kt * 32;
        #pragma unroll
        for (int u = 0; u < 2; u++) {
            int c = tid + u * 256;
            int r = c >> 2, c4 = c & 3;
            int row = bm0 + r;
            const void* gp = Ahi + (size_t)row * KDIM + k0 + c4 * 8;
            uint32_t dstp = sb + (uint32_t)buf * APL + (uint32_t)(r * P * 2 + c4 * 16);
            int sz = (row < Me) ? 16 : 0;
            asm volatile("cp.async.cg.shared.global [%0], [%1], 16, %2;"
                         :: "r"(dstp), "l"(gp), "r"(sz));
        }
        #pragma unroll
        for (int u = 0; u < 2; u++) {
            int c = tid + u * 256;
            int r = c >> 2, c4 = c & 3;
            const void* gp = Bhi + (size_t)(bn0 + r) * KDIM + k0 + c4 * 8;
            uint32_t dstp = sbB + (uint32_t)buf * BPL + (uint32_t)(r * P * 2 + c4 * 16);
            asm volatile("cp.async.cg.shared.global [%0], [%1], 16;"
                         :: "r"(dstp), "l"(gp));
        }
        asm volatile("cp.async.commit_group;");
    };

    auto compute = [&](int buf) {
        #pragma unroll
        for (int kk = 0; kk < 32; kk += 16) {
            uint32_t ah[2][4];
            #pragma unroll
            for (int mt = 0; mt < 2; mt++) {
                uint32_t ad = sb + (uint32_t)buf * APL + aoff + (uint32_t)(mt * 16 * P * 2 + kk * 2);
                LDSM4(ah[mt], ad);
            }
            uint32_t bh[NT_N][2];
            #pragma unroll
            for (int pr = 0; pr < NPAIR; pr++) {
                uint32_t bd = sbB + (uint32_t)buf * BPL + boff + (uint32_t)(pr * 16 * P * 2 + kk * 2);
                uint32_t r4[4];
                LDSM4(r4, bd);
                bh[2 * pr][0] = r4[0]; bh[2 * pr][1] = r4[1];
                bh[2 * pr + 1][0] = r4[2]; bh[2 * pr + 1][1] = r4[3];
            }
            #pragma unroll
            for (int mt = 0; mt < 2; mt++)
                #pragma unroll
                for (int nt = 0; nt < NT_N; nt++)
                    mma_f16(acc[mt][nt][0], acc[mt][nt][1], acc[mt][nt][2], acc[mt][nt][3],
                            ah[mt][0], ah[mt][1], ah[mt][2], ah[mt][3],
                            bh[nt][0], bh[nt][1]);
        }
    };

    ld_stage(0, 0);
    ld_stage(1, 1);
    #pragma unroll 1
    for (int kt = 0; kt < 8; kt++) {
        if (kt < 7) asm volatile("cp.async.wait_group 1;");
        else        asm volatile("cp.async.wait_group 0;");
        __syncthreads();
        if (kt + 2 < 8) ld_stage(kt + 2, (kt + 2) % 3);
        compute(kt % 3);
    }

    #pragma unroll
    for (int nt = 0; nt < NT_N; nt++) {
        int cn = bn0 + wn * (BN / 2) + nt * 8 + t * 2;
        float2 bv = make_float2(0.f, 0.f);
        if (skipH) bv = *(const float2*)(comb1 + cn);
        #pragma unroll
        for (int mt = 0; mt < 2; mt++) {
            int row0 = bm0 + wm * 32 + mt * 16 + g;
            float* c = acc[mt][nt];
            if (skipH) {
                if (row0 < Me) {
                    float2 o = make_float2(c[0] + bv.x, c[1] + bv.y);
                    *(float2*)(Cskip + (size_t)row0 * 256 + cn) = o;
                }
                if (row0 + 8 < Me) {
                    float2 o = make_float2(c[2] + bv.x, c[3] + bv.y);
                    *(float2*)(Cskip + (size_t)(row0 + 8) * 256 + cn) = o;
                }
            } else {
                __half2* Ch = (__half2*)C16;
                if (row0 < Me)
                    Ch[(size_t)row0 * 128 + (cn >> 1)] = __floats2half2_rn(c[0], c[1]);
                if (row0 + 8 < Me)
                    Ch[(size_t)(row0 + 8) * 128 + (cn >> 1)] = __floats2half2_rn(c[2], c[3]);
            }
        }
    }
}

// ------- fused layer-2 GEMMs: xs2 (M=NT1C) + o (M=NT2C, bias) ---------------
// grid (1, YA+YB). NPROD=2 exact hi+lo split of A.
__global__ __launch_bounds__(256, 2) void gemm_l2(
    const unsigned short* __restrict__ Ahi, const unsigned short* __restrict__ Alo,
    const unsigned short* __restrict__ B2,  const unsigned short* __restrict__ Bs2,
    const float* __restrict__ comb2,
    float* __restrict__ Cxs2, float* __restrict__ Co, int YA)
{
    constexpr int BN = 64;
    constexpr int P = 40;
    constexpr uint32_t APL = 128 * P * 2;
    constexpr uint32_t BPL = (uint32_t)BN * P * 2;
    constexpr uint32_t AREG = 6 * APL;
    constexpr int NT_N = BN / 16;
    constexpr int NPAIR = BN / 32;

    bool second = (int)blockIdx.y >= YA;
    int bm0 = (second ? (blockIdx.y - YA) : blockIdx.y) * 128;
    int Me = second ? NT2C : NT1C;
    if (bm0 >= Me) return;
    const unsigned short* Bhi = second ? Bs2 : B2;
    float* C = second ? Co : Cxs2;
    const float* bias = second ? comb2 : nullptr;

    extern __shared__ char smem[];
    uint32_t sb = smem_u32(smem);
    uint32_t sbB = sb + AREG;

    int tid = threadIdx.x, lane = tid & 31, wid = tid >> 5;
    int wm = wid >> 1, wn = wid & 1;
    int g = lane >> 2, t = lane & 3;
    int q8 = lane & 7, mm = lane >> 3;
    uint32_t aoff = (uint32_t)((wm * 32 + (mm & 1) * 8 + q8) * P * 2 + ((mm & 2) * 4) * 2);
    uint32_t boff = (uint32_t)((wn * (BN / 2) + ((mm >> 1) & 1) * 8 + q8) * P * 2 + ((mm & 1) * 8) * 2);

    float acc[2][NT_N][4];
    #pragma unroll
    for (int i = 0; i < 2; i++)
        #pragma unroll
        for (int j = 0; j < NT_N; j++)
            #pragma unroll
            for (int q = 0; q < 4; q++) acc[i][j][q] = 0.f;

    auto ld_stage = [&](int kt, int buf) {
        int k0 = kt * 32;
        #pragma unroll
        for (int pl = 0; pl < 2; pl++) {
            const unsigned short* Ap = pl ? Alo : Ahi;
            #pragma unroll
            for (int u = 0; u < 2; u++) {
                int c = tid + u * 256;
                int r = c >> 2, c4 = c & 3;
                int row = bm0 + r;
                const void* gp = Ap + (size_t)row * KDIM + k0 + c4 * 8;
                uint32_t dstp = sb + (uint32_t)(buf * 2 + pl) * APL + (uint32_t)(r * P * 2 + c4 * 16);
                int sz = (row < Me) ? 16 : 0;
                asm volatile("cp.async.cg.shared.global [%0], [%1], 16, %2;"
                             :: "r"(dstp), "l"(gp), "r"(sz));
            }
        }
        {
            int r = tid >> 2, c4 = tid & 3;
            const void* gp = Bhi + (size_t)r * KDIM + k0 + c4 * 8;
            uint32_t dstp = sbB + (uint32_t)buf * BPL + (uint32_t)(r * P * 2 + c4 * 16);
            asm volatile("cp.async.cg.shared.global [%0], [%1], 16;"
                         :: "r"(dstp), "l"(gp));
        }
        asm volatile("cp.async.commit_group;");
    };

    auto compute = [&](int buf) {
        #pragma unroll
        for (int kk = 0; kk < 32; kk += 16) {
            uint32_t ah[2][4], al[2][4];
            #pragma unroll
            for (int mt = 0; mt < 2; mt++) {
                uint32_t ad = sb + (uint32_t)(buf * 2) * APL + aoff + (uint32_t)(mt * 16 * P * 2 + kk * 2);
                LDSM4(ah[mt], ad);
                LDSM4(al[mt], ad + APL);
            }
            uint32_t bh[NT_N][2];
            #pragma unroll
            for (int pr = 0; pr < NPAIR; pr++) {
                uint32_t bd = sbB + (uint32_t)buf * BPL + boff + (uint32_t)(pr * 16 * P * 2 + kk * 2);
                uint32_t r4[4];
                LDSM4(r4, bd);
                bh[2 * pr][0] = r4[0]; bh[2 * pr][1] = r4[1];
                bh[2 * pr + 1][0] = r4[2]; bh[2 * pr + 1][1] = r4[3];
            }
            #pragma unroll
            for (int mt = 0; mt < 2; mt++)
                #pragma unroll
                for (int nt = 0; nt < NT_N; nt++) {
                    float* c = acc[mt][nt];
                    mma_f16(c[0], c[1], c[2], c[3],
                            ah[mt][0], ah[mt][1], ah[mt][2], ah[mt][3],
                            bh[nt][0], bh[nt][1]);
                    mma_f16(c[0], c[1], c[2], c[3],
                            al[mt][0], al[mt][1], al[mt][2], al[mt][3],
                            bh[nt][0], bh[nt][1]);
                }
        }
    };

    ld_stage(0, 0);
    ld_stage(1, 1);
    #pragma unroll 1
    for (int kt = 0; kt < 8; kt++) {
        if (kt < 7) asm volatile("cp.async.wait_group 1;");
        else        asm volatile("cp.async.wait_group 0;");
        __syncthreads();
        if (kt + 2 < 8) ld_stage(kt + 2, (kt + 2) % 3);
        compute(kt % 3);
    }

    #pragma unroll
    for (int nt = 0; nt < NT_N; nt++) {
        int cn = wn * (BN / 2) + nt * 8 + t * 2;
        float2 bv = make_float2(0.f, 0.f);
        if (bias) bv = *(const float2*)(bias + cn);
        #pragma unroll
        for (int mt = 0; mt < 2; mt++) {
            int row0 = bm0 + wm * 32 + mt * 16 + g;
            float* c = acc[mt][nt];
            if (row0 < Me) {
                float2 o = make_float2(c[0] + bv.x, c[1] + bv.y);
                *(float2*)(C + (size_t)row0 * 64 + cn) = o;
            }
            if (row0 + 8 < Me) {
                float2 o = make_float2(c[2] + bv.x, c[3] + bv.y);
                *(float2*)(C + (size_t)(row0 + 8) * 64 + cn) = o;
            }
        }
    }
}

// ---------------- CSR scan + fill ----------------
__device__ void scan_impl(const int* __restrict__ cnt, int* __restrict__ off,
                          int* __restrict__ cur, int n)
{
    __shared__ int wpre[32];
    __shared__ int carry;
    int t = threadIdx.x, lane = t & 31, w = t >> 5;
    if (t == 0) { carry = 0; off[0] = 0; }
    __syncthreads();
    for (int base = 0; base < n; base += 1024) {
        int i = base + t;
        int v = (i < n) ? cnt[i] : 0;
        int x = v;
        #pragma unroll
        for (int d = 1; d < 32; d <<= 1) {
            int y = __shfl_up_sync(0xffffffffu, x, d);
            if (lane >= d) x += y;
        }
        if (lane == 31) wpre[w] = x;
        __syncthreads();
        if (w == 0) {
            int s = wpre[lane];
            #pragma unroll
            for (int d = 1; d < 32; d <<= 1) {
                int y = __shfl_up_sync(0xffffffffu, s, d);
                if (lane >= d) s += y;
            }
            wpre[lane] = s;
        }
        __syncthreads();
        int incl = x + (w ? wpre[w - 1] : 0) + carry;
        if (i < n) {
            off[i + 1] = incl;
            cur[i] = incl - v;
        }
        __syncthreads();
        if (t == 1023) carry = incl;
        __syncthreads();
    }
}

__global__ void scan_both()
{
    if (blockIdx.x == 0) scan_impl(g_cnt1, g_off1, g_cur1, NT1C);
    else                 scan_impl(g_cnt2, g_off2, g_cur2, NT2C);
}

__global__ void fill_both(const int* __restrict__ dst1, const int* __restrict__ src1,
                          const int* __restrict__ dst2, const int* __restrict__ src2,
                          int E1, int E2)
{
    int e = blockIdx.x * blockDim.x + threadIdx.x;
    if (e < E1) {
        int p = atomicAdd(&g_cur1[dst1[e]], 1);
        g_srcid1[p] = src1[e];
    } else if (e - E1 < E2) {
        int e2 = e - E1;
        int p = atomicAdd(&g_cur2[dst2[e2]], 1);
        g_srcid2[p] = src2[e2];
    }
}

// -------- layer 1 aggregation (fp16 gather) + h split + layer-2 dots ---------
__global__ __launch_bounds__(256) void gat_agg1()
{
    int warp = (blockIdx.x * blockDim.x + threadIdx.x) >> 5;
    int lane = threadIdx.x & 31;
    if (warp >= NT1C) return;
    int myh = lane >> 3;
    float ad = g_ad1[warp * 4 + myh];
    int beg = g_off1[warp], end = g_off1[warp + 1];
    float m = -1e30f, s = 0.f;
    float acc[8];
    #pragma unroll
    for (int j = 0; j < 8; j++) acc[j] = 0.f;

    int i = beg;
    for (; i + 1 < end; i += 2) {
        int sa = g_srcid1[i], sb = g_srcid1[i + 1];
        float ea = g_as1[(size_t)sa * 4 + myh] + ad;
        float eb = g_as1[(size_t)sb * 4 + myh] + ad;
        ea = ea > 0.f ? ea : NEG_SLOPE * ea;
        eb = eb > 0.f ? eb : NEG_SLOPE * eb;
        uint4 qa = *(const uint4*)(g_xs1h + (size_t)sa * 256 + lane * 8);
        uint4 qb = *(const uint4*)(g_xs1h + (size_t)sb * 256 + lane * 8);
        float2 a01 = __half22float2(*(__half2*)&qa.x);
        float2 a23 = __half22float2(*(__half2*)&qa.y);
        float2 a45 = __half22float2(*(__half2*)&qa.z);
        float2 a67 = __half22float2(*(__half2*)&qa.w);
        float2 b01 = __half22float2(*(__half2*)&qb.x);
        float2 b23 = __half22float2(*(__half2*)&qb.y);
        float2 b45 = __half22float2(*(__half2*)&qb.z);
        float2 b67 = __half22float2(*(__half2*)&qb.w);
        float mp = fmaxf(ea, eb);
        float wa = __expf(ea - mp), wb = __expf(eb - mp);
        float nm = fmaxf(m, mp);
        float cm = __expf(m - nm), cp = __expf(mp - nm);
        s = s * cm + (wa + wb) * cp;
        float wap = wa * cp, wbp = wb * cp;
        acc[0] = acc[0] * cm + wap * a01.x + wbp * b01.x;
        acc[1] = acc[1] * cm + wap * a01.y + wbp * b01.y;
        acc[2] = acc[2] * cm + wap * a23.x + wbp * b23.x;
        acc[3] = acc[3] * cm + wap * a23.y + wbp * b23.y;
        acc[4] = acc[4] * cm + wap * a45.x + wbp * b45.x;
        acc[5] = acc[5] * cm + wap * a45.y + wbp * b45.y;
        acc[6] = acc[6] * cm + wap * a67.x + wbp * b67.x;
        acc[7] = acc[7] * cm + wap * a67.y + wbp * b67.y;
        m = nm;
    }
    if (i < end) {
        int sn = g_srcid1[i];
        float ev = g_as1[(size_t)sn * 4 + myh] + ad;
        ev = ev > 0.f ? ev : NEG_SLOPE * ev;
        float nm = fmaxf(m, ev);
        float corr = __expf(m - nm);
        float w = __expf(ev - nm);
        s = s * corr + w;
        uint4 qa = *(const uint4*)(g_xs1h + (size_t)sn * 256 + lane * 8);
        float2 a01 = __half22float2(*(__half2*)&qa.x);
        float2 a23 = __half22float2(*(__half2*)&qa.y);
        float2 a45 = __half22float2(*(__half2*)&qa.z);
        float2 a67 = __half22float2(*(__half2*)&qa.w);
        acc[0] = acc[0] * corr + w * a01.x;
        acc[1] = acc[1] * corr + w * a01.y;
        acc[2] = acc[2] * corr + w * a23.x;
        acc[3] = acc[3] * corr + w * a23.y;
        acc[4] = acc[4] * corr + w * a45.x;
        acc[5] = acc[5] * corr + w * a45.y;
        acc[6] = acc[6] * corr + w * a67.x;
        acc[7] = acc[7] * corr + w * a67.y;
        m = nm;
    }
    float inv = 1.f / (s + 1e-16f);
    const float* hp = g_h + (size_t)warp * 256 + lane * 8;
    float4 h0 = ((const float4*)hp)[0], h1 = ((const float4*)hp)[1];
    float v[8];
    v[0] = acc[0] * inv + h0.x;  v[1] = acc[1] * inv + h0.y;
    v[2] = acc[2] * inv + h0.z;  v[3] = acc[3] * inv + h0.w;
    v[4] = acc[4] * inv + h1.x;  v[5] = acc[5] * inv + h1.y;
    v[6] = acc[6] * inv + h1.z;  v[7] = acc[7] * inv + h1.w;
    #pragma unroll
    for (int j = 0; j < 8; j++) v[j] = v[j] > 0.f ? v[j] : (__expf(v[j]) - 1.f);

    unsigned short hh[8], hl[8];
    #pragma unroll
    for (int j = 0; j < 8; j++) split1(v[j], hh[j], hl[j]);
    uint4 phh, pll;
    phh.x = (uint32_t)hh[0] | ((uint32_t)hh[1] << 16);
    phh.y = (uint32_t)hh[2] | ((uint32_t)hh[3] << 16);
    phh.z = (uint32_t)hh[4] | ((uint32_t)hh[5] << 16);
    phh.w = (uint32_t)hh[6] | ((uint32_t)hh[7] << 16);
    pll.x = (uint32_t)hl[0] | ((uint32_t)hl[1] << 16);
    pll.y = (uint32_t)hl[2] | ((uint32_t)hl[3] << 16);
    pll.z = (uint32_t)hl[4] | ((uint32_t)hl[5] << 16);
    pll.w = (uint32_t)hl[6] | ((uint32_t)hl[7] << 16);
    *(uint4*)(g_hhi + (size_t)warp * 256 + lane * 8) = phh;
    *(uint4*)(g_hlo + (size_t)warp * 256 + lane * 8) = pll;

    const float* vs = g_vS2 + lane * 8;
    const float* vd = g_vD2 + lane * 8;
    float4 s0 = *(const float4*)vs, s1 = *(const float4*)(vs + 4);
    float4 d0 = *(const float4*)vd, d1 = *(const float4*)(vd + 4);
    float a = v[0]*s0.x + v[1]*s0.y + v[2]*s0.z + v[3]*s0.w +
              v[4]*s1.x + v[5]*s1.y + v[6]*s1.z + v[7]*s1.w;
    float b = v[0]*d0.x + v[1]*d0.y + v[2]*d0.z + v[3]*d0.w +
              v[4]*d1.x + v[5]*d1.y + v[6]*d1.z + v[7]*d1.w;
    bool hb = lane >= 16;
    float send = hb ? a : b;
    float recv = __shfl_xor_sync(0xffffffffu, send, 16);
    if (hb) b += recv; else a += recv;
    float z = hb ? b : a;
    z += __shfl_xor_sync(0xffffffffu, z, 8);
    z += __shfl_xor_sync(0xffffffffu, z, 4);
    z += __shfl_xor_sync(0xffffffffu, z, 2);
    z += __shfl_xor_sync(0xffffffffu, z, 1);
    if (lane == 0) g_as2[warp] = z;
    if (lane == 16 && warp < NT2C) g_ad2[warp] = z;
}

// ---------- layer 2 aggregation (pairwise) + fused log_softmax ----------
__global__ __launch_bounds__(256) void gat_agg2_lsm(float* __restrict__ out)
{
    int warp = (blockIdx.x * blockDim.x + threadIdx.x) >> 5;
    int lane = threadIdx.x & 31;
    if (warp >= NT2C) return;
    float ad = g_ad2[warp];
    int beg = g_off2[warp], end = g_off2[warp + 1];
    float m = -1e30f, s = 0.f, a0 = 0.f, a1 = 0.f;
    int i = beg;
    for (; i + 1 < end; i += 2) {
        int sa = g_srcid2[i], sb = g_srcid2[i + 1];
        float ea = g_as2[sa] + ad;
        float eb = g_as2[sb] + ad;
        ea = ea > 0.f ? ea : NEG_SLOPE * ea;
        eb = eb > 0.f ? eb : NEG_SLOPE * eb;
        float2 ra = *(const float2*)(g_xs2 + (size_t)sa * 64 + lane * 2);
        float2 rb = *(const float2*)(g_xs2 + (size_t)sb * 64 + lane * 2);
        float mp = fmaxf(ea, eb);
        float wa = __expf(ea - mp), wb = __expf(eb - mp);
        float nm = fmaxf(m, mp);
        float cm = __expf(m - nm), cp = __expf(mp - nm);
        s = s * cm + (wa + wb) * cp;
        float wap = wa * cp, wbp = wb * cp;
        a0 = a0 * cm + wap * ra.x + wbp * rb.x;
        a1 = a1 * cm + wap * ra.y + wbp * rb.y;
        m = nm;
    }
    if (i < end) {
        int sn = g_srcid2[i];
        float ev = g_as2[sn] + ad;
        ev = ev > 0.f ? ev : NEG_SLOPE * ev;
        float nm = fmaxf(m, ev);
        float corr = __expf(m - nm);
        float w = __expf(ev - nm);
        s = s * corr + w;
        float2 r = *(const float2*)(g_xs2 + (size_t)sn * 64 + lane * 2);
        a0 = a0 * corr + w * r.x;
        a1 = a1 * corr + w * r.y;
        m = nm;
    }
    float inv = 1.f / (s + 1e-16f);
    float2 o = *(const float2*)(g_o + (size_t)warp * 64 + lane * 2);
    o.x += a0 * inv;
    o.y += a1 * inv;
    float mx = fmaxf(o.x, o.y);
    #pragma unroll
    for (int off = 16; off; off >>= 1) mx = fmaxf(mx, __shfl_xor_sync(0xffffffffu, mx, off));
    float se = __expf(o.x - mx) + __expf(o.y - mx);
    #pragma unroll
    for (int off = 16; off; off >>= 1) se += __shfl_xor_sync(0xffffffffu, se, off);
    float l = mx + logf(se);
    float2 r;
    r.x = o.x - l;
    r.y = o.y - l;
    *(float2*)(out + (size_t)warp * 64 + lane * 2) = r;
}

// ---------------- host launcher ----------------
extern "C" void kernel_launch(void* const* d_in, const int* in_sizes, int n_in,
                              void* d_out, int out_size)
{
    const float* x    = (const float*)d_in[0];
    const int*   src1 = (const int*)d_in[1];
    const int*   dst1 = (const int*)d_in[2];
    const int*   src2 = (const int*)d_in[3];
    const int*   dst2 = (const int*)d_in[4];
    const float* W1s  = (const float*)d_in[7];
    const float* W1d  = (const float*)d_in[8];
    const float* a1s  = (const float*)d_in[9];
    const float* a1d  = (const float*)d_in[10];
    const float* b1   = (const float*)d_in[11];
    const float* sk1W = (const float*)d_in[12];
    const float* sk1b = (const float*)d_in[13];
    const float* W2s  = (const float*)d_in[14];
    const float* W2d  = (const float*)d_in[15];
    const float* a2s  = (const float*)d_in[16];
    const float* a2d  = (const float*)d_in[17];
    const float* b2   = (const float*)d_in[18];
    const float* sk2W = (const float*)d_in[19];
    const float* sk2b = (const float*)d_in[20];

    int N0 = in_sizes[0] / KDIM;
    int E1 = in_sizes[1];
    int E2 = in_sizes[3];

    unsigned short *xs1h, *xhi, *hhi, *hlo;
    float *hbuf, *xs2, *obuf, *as1, *ad1;
    float *vS1, *vD1, *comb1, *comb2;
    unsigned short *B1hi, *Bs1hi, *B2hi, *Bs2hi;
    int *cnt1, *cnt2;
    cudaGetSymbolAddress((void**)&xs1h, g_xs1h);
    cudaGetSymbolAddress((void**)&hbuf, g_h);
    cudaGetSymbolAddress((void**)&xs2,  g_xs2);
    cudaGetSymbolAddress((void**)&obuf, g_o);
    cudaGetSymbolAddress((void**)&as1,  g_as1);
    cudaGetSymbolAddress((void**)&ad1,  g_ad1);
    cudaGetSymbolAddress((void**)&vS1,  g_vS1);
    cudaGetSymbolAddress((void**)&vD1,  g_vD1);
    cudaGetSymbolAddress((void**)&comb1, g_comb1);
    cudaGetSymbolAddress((void**)&comb2, g_comb2);
    cudaGetSymbolAddress((void**)&xhi,  g_xhi);
    cudaGetSymbolAddress((void**)&hhi,  g_hhi);
    cudaGetSymbolAddress((void**)&hlo,  g_hlo);
    cudaGetSymbolAddress((void**)&B1hi,  g_B1hi);
    cudaGetSymbolAddress((void**)&Bs1hi, g_Bs1hi);
    cudaGetSymbolAddress((void**)&B2hi,  g_B2hi);
    cudaGetSymbolAddress((void**)&Bs2hi, g_Bs2hi);
    cudaGetSymbolAddress((void**)&cnt1, g_cnt1);
    cudaGetSymbolAddress((void**)&cnt2, g_cnt2);

    const int SMEM_L1 = 3 * 10240 + 3 * 10240;   // 61440
    const int SMEM_L2 = 6 * 10240 + 3 * 5120;    // 76800
    cudaFuncSetAttribute(gemm_l1, cudaFuncAttributeMaxDynamicSharedMemorySize, SMEM_L1);
    cudaFuncSetAttribute(gemm_l2, cudaFuncAttributeMaxDynamicSharedMemorySize, SMEM_L2);

    int nbrow = CDIV(N0 * 32, 256);
    int nbcnt = CDIV(E1 + E2, 256);
    int YA = CDIV(NT1C, 128), YB = CDIV(NT2C, 128);

    // zero edge counters (graph-capturable async memsets)
    cudaMemsetAsync(cnt1, 0, NT1C * sizeof(int));
    cudaMemsetAsync(cnt2, 0, NT2C * sizeof(int));

    fold_kernel<<<16, 16>>>(W1s, W1d, a1s, a1d, b1, sk1b,
                            W2s, W2d, a2s, a2d, b2, sk2b);                       // k0
    prep_Bt<<<dim3(8, 8, 4), dim3(32, 8)>>>(W1s, sk1W, W2s, sk2W);               // k1
    split_dot4_count<<<nbrow + nbcnt, 256>>>(x, xhi, vS1, vD1, as1, ad1,
                                             N0, NT1C, nbrow,
                                             dst1, dst2, E1, E2);                // k2
    gemm_l1<<<dim3(4, CDIV(N0, 128)), 256, SMEM_L1>>>(
        xhi, B1hi, Bs1hi, comb1, xs1h, hbuf, N0, NT1C);                          // k3 (profiled)
    scan_both<<<2, 1024>>>();                                                    // k4
    fill_both<<<nbcnt, 256>>>(dst1, src1, dst2, src2, E1, E2);                   // k5
    gat_agg1<<<CDIV(NT1C * 32, 256), 256>>>();                                   // k6
    gemm_l2<<<dim3(1, YA + YB), 256, SMEM_L2>>>(
        hhi, hlo, B2hi, Bs2hi, comb2, xs2, obuf, YA);                            // k7
    gat_agg2_lsm<<<CDIV(NT2C * 32, 256), 256>>>((float*)d_out);                  // k8
}